// round 5
// baseline (speedup 1.0000x reference)
#include <cuda_runtime.h>

#define TOK   32768
#define DIN   1024
#define RDIM  128
#define NSLOT 4096
#define MAXK  32

typedef unsigned long long u64;

// ---------------- scratch ----------------
__device__ float  g_hidden[TOK * RDIM];
__device__ float4 g_scores_v[TOK * NSLOT / 4];     // 512 MB
__device__ int    g_budget[TOK];
__device__ float4 g_counts_v[NSLOT / 4];
__device__ float  g_aux;

#define g_scores ((float*)g_scores_v)
#define g_counts ((float*)g_counts_v)

// ---------------- reductions ----------------
__device__ __forceinline__ float warpReduceMaxF(float v) {
#pragma unroll
    for (int o = 16; o > 0; o >>= 1) v = fmaxf(v, __shfl_xor_sync(0xffffffffu, v, o));
    return v;
}
__device__ __forceinline__ float warpReduceSumF(float v) {
#pragma unroll
    for (int o = 16; o > 0; o >>= 1) v += __shfl_xor_sync(0xffffffffu, v, o);
    return v;
}
__device__ __forceinline__ u64 warpReduceMaxU64(u64 v) {
#pragma unroll
    for (int o = 16; o > 0; o >>= 1) {
        u64 t = __shfl_xor_sync(0xffffffffu, v, o);
        v = (t > v) ? t : v;
    }
    return v;
}

// ---------------- K0 ----------------
__global__ void k_init() {
    int i = blockIdx.x * blockDim.x + threadIdx.x;
    if (i < NSLOT) g_counts[i] = 0.f;
    if (i == 0)    g_aux = 0.f;
}

// ---------------- K1: hidden GEMM + budget ----------------
__global__ __launch_bounds__(256) void k_hidden(
    const float* __restrict__ x,  const float* __restrict__ Wc, const float* __restrict__ bc,
    const float* __restrict__ Wh, const float* __restrict__ bh, float* __restrict__ out_b)
{
    __shared__ float Xs[32][132];
    __shared__ float Wsm[32][128];
    __shared__ float Wcs[32];

    const int tid = threadIdx.x;
    const int tx = tid & 15, ty = tid >> 4;
    const int t0 = blockIdx.x * 128;

    float acc[8][8];
#pragma unroll
    for (int j = 0; j < 8; j++) {
        int c = (j < 4) ? tx * 4 + j : 64 + tx * 4 + (j - 4);
        float b = bh[c];
#pragma unroll
        for (int i = 0; i < 8; i++) acc[i][j] = b;
    }
    float cacc = 0.f;

    for (int kt = 0; kt < 32; kt++) {
#pragma unroll
        for (int i = 0; i < 4; i++) {
            int id = tid + i * 256;
            int token = id >> 3, kg = id & 7;
            float4 f = *(const float4*)(x + (size_t)(t0 + token) * DIN + kt * 32 + kg * 4);
            Xs[kg * 4 + 0][token] = f.x; Xs[kg * 4 + 1][token] = f.y;
            Xs[kg * 4 + 2][token] = f.z; Xs[kg * 4 + 3][token] = f.w;
        }
#pragma unroll
        for (int i = 0; i < 4; i++) {
            int id = tid + i * 256;
            int rowk = id >> 5, ng = id & 31;
            *(float4*)&Wsm[rowk][ng * 4] =
                *(const float4*)(Wh + (size_t)(kt * 32 + rowk) * RDIM + ng * 4);
        }
        if (tid < 32) Wcs[tid] = Wc[kt * 32 + tid];
        __syncthreads();

#pragma unroll
        for (int k = 0; k < 32; k++) {
            float4 a0 = *(float4*)&Xs[k][ty * 4];
            float4 a1 = *(float4*)&Xs[k][64 + ty * 4];
            float4 b0 = *(float4*)&Wsm[k][tx * 4];
            float4 b1 = *(float4*)&Wsm[k][64 + tx * 4];
            float xf[8] = {a0.x, a0.y, a0.z, a0.w, a1.x, a1.y, a1.z, a1.w};
            float wf[8] = {b0.x, b0.y, b0.z, b0.w, b1.x, b1.y, b1.z, b1.w};
#pragma unroll
            for (int i = 0; i < 8; i++)
#pragma unroll
                for (int j = 0; j < 8; j++)
                    acc[i][j] += xf[i] * wf[j];
        }
        if (tid < 128) {
            float s = 0.f;
#pragma unroll
            for (int k = 0; k < 32; k++) s += Xs[k][tid] * Wcs[k];
            cacc += s;
        }
        __syncthreads();
    }

#pragma unroll
    for (int i = 0; i < 8; i++) {
        int r = (i < 4) ? ty * 4 + i : 64 + ty * 4 + (i - 4);
        float4 o0 = make_float4(fmaxf(acc[i][0], 0.f), fmaxf(acc[i][1], 0.f),
                                fmaxf(acc[i][2], 0.f), fmaxf(acc[i][3], 0.f));
        float4 o1 = make_float4(fmaxf(acc[i][4], 0.f), fmaxf(acc[i][5], 0.f),
                                fmaxf(acc[i][6], 0.f), fmaxf(acc[i][7], 0.f));
        *(float4*)(g_hidden + (size_t)(t0 + r) * RDIM + tx * 4) = o0;
        *(float4*)(g_hidden + (size_t)(t0 + r) * RDIM + 64 + tx * 4) = o1;
    }
    if (tid < 128) {
        float zc = cacc + bc[0];
        float c = 1.f / (1.f + expf(-zc));
        float bf = 4.f + 28.f * c * c;
        int b = (int)floorf(bf);
        g_budget[t0 + tid] = b;
        out_b[t0 + tid] = (float)b;
    }
}

// ---------------- K2: scores GEMM ----------------
__global__ __launch_bounds__(256) void k_scores(const float* __restrict__ Wsg,
                                                const float* __restrict__ bs)
{
    extern __shared__ float sm[];
    float* Hs = sm;
    float* Wt = sm + 128 * 132;

    const int tid = threadIdx.x;
    const int tx = tid & 15, ty = tid >> 4;
    const int t0 = blockIdx.x * 128;

#pragma unroll
    for (int i = 0; i < 16; i++) {
        int id = tid + i * 256;
        int token = id >> 5, kg = id & 31;
        float4 f = *(const float4*)(g_hidden + (size_t)(t0 + token) * RDIM + kg * 4);
        Hs[(kg * 4 + 0) * 132 + token] = f.x;
        Hs[(kg * 4 + 1) * 132 + token] = f.y;
        Hs[(kg * 4 + 2) * 132 + token] = f.z;
        Hs[(kg * 4 + 3) * 132 + token] = f.w;
    }

    for (int nt = 0; nt < 32; nt++) {
        __syncthreads();
#pragma unroll
        for (int i = 0; i < 16; i++) {
            int id = tid + i * 256;
            int rowk = id >> 5, ng = id & 31;
            *(float4*)&Wt[rowk * 132 + ng * 4] =
                *(const float4*)(Wsg + (size_t)rowk * NSLOT + nt * 128 + ng * 4);
        }
        __syncthreads();

        float acc[8][8];
#pragma unroll
        for (int j = 0; j < 8; j++) {
            int c = (j < 4) ? tx * 4 + j : 64 + tx * 4 + (j - 4);
            float b = bs[nt * 128 + c];
#pragma unroll
            for (int i = 0; i < 8; i++) acc[i][j] = b;
        }
#pragma unroll 8
        for (int k = 0; k < 128; k++) {
            float4 a0 = *(float4*)&Hs[k * 132 + ty * 4];
            float4 a1 = *(float4*)&Hs[k * 132 + 64 + ty * 4];
            float4 b0 = *(float4*)&Wt[k * 132 + tx * 4];
            float4 b1 = *(float4*)&Wt[k * 132 + 64 + tx * 4];
            float xf[8] = {a0.x, a0.y, a0.z, a0.w, a1.x, a1.y, a1.z, a1.w};
            float wf[8] = {b0.x, b0.y, b0.z, b0.w, b1.x, b1.y, b1.z, b1.w};
#pragma unroll
            for (int i = 0; i < 8; i++)
#pragma unroll
                for (int j = 0; j < 8; j++)
                    acc[i][j] += xf[i] * wf[j];
        }
#pragma unroll
        for (int i = 0; i < 8; i++) {
            int r = (i < 4) ? ty * 4 + i : 64 + ty * 4 + (i - 4);
            float* base = g_scores + (size_t)(t0 + r) * NSLOT + nt * 128;
            *(float4*)(base + tx * 4)      = make_float4(acc[i][0], acc[i][1], acc[i][2], acc[i][3]);
            *(float4*)(base + 64 + tx * 4) = make_float4(acc[i][4], acc[i][5], acc[i][6], acc[i][7]);
        }
    }
}

// ---------------- K3: block-per-token exact top-32 ----------------
// 16 keys/thread in registers; stat threshold -> compact candidates ->
// warp0 exact extraction. Block-wide exact fallback for safety.
__global__ __launch_bounds__(256) void k_topk(float* __restrict__ out_idx,
                                              float* __restrict__ out_w)
{
    __shared__ u64      cand[256];
    __shared__ u64      sel[MAXK];
    __shared__ float    fred[8];
    __shared__ float    f2red[8];
    __shared__ u64      ured[8];
    __shared__ unsigned s_cnt;
    __shared__ u64      s_win;
    __shared__ float    s_mean, s_sig;

    const int t = blockIdx.x;
    const int tid = threadIdx.x, lane = tid & 31, wid = tid >> 5;
    const float* row = g_scores + (size_t)t * NSLOT;

    // load 16 values/thread; idx of key[i*4+j] = (tid + i*256)*4 + j
    unsigned key[16];
    float s = 0.f, s2 = 0.f;
#pragma unroll
    for (int i = 0; i < 4; i++) {
        float4 f = *(const float4*)(row + (size_t)(tid + i * 256) * 4);
        float vv[4] = {f.x, f.y, f.z, f.w};
#pragma unroll
        for (int j = 0; j < 4; j++) {
            s += vv[j]; s2 += vv[j] * vv[j];
            unsigned b = __float_as_uint(vv[j]);
            key[i * 4 + j] = b ^ ((unsigned)((int)b >> 31) | 0x80000000u);
        }
    }
    s = warpReduceSumF(s);
    s2 = warpReduceSumF(s2);
    if (lane == 0) { fred[wid] = s; f2red[wid] = s2; }
    __syncthreads();
    if (tid == 0) {
        float ss = 0.f, ss2 = 0.f;
#pragma unroll
        for (int i = 0; i < 8; i++) { ss += fred[i]; ss2 += f2red[i]; }
        float mean = ss * (1.f / NSLOT);
        float var = fmaxf(ss2 * (1.f / NSLOT) - mean * mean, 0.f);
        s_mean = mean; s_sig = sqrtf(var) + 1e-20f;
    }
    __syncthreads();
    const float mean = s_mean, sigma = s_sig;

    // threshold attempts (uniform control flow across block)
    float zf = 2.35f;
    int cnt = 0;
    bool ok = false;
    for (int attempt = 0; attempt < 8; attempt++) {
        if (tid == 0) s_cnt = 0;
        __syncthreads();
        float thr = mean + zf * sigma;
        unsigned tb = __float_as_uint(thr);
        unsigned thrKey = tb ^ ((unsigned)((int)tb >> 31) | 0x80000000u);

        // local count
        unsigned my = 0;
#pragma unroll
        for (int i = 0; i < 16; i++) my += (key[i] > thrKey) ? 1u : 0u;
        // warp inclusive prefix
        unsigned pre = my;
#pragma unroll
        for (int o = 1; o < 32; o <<= 1) {
            unsigned tt = __shfl_up_sync(0xffffffffu, pre, o);
            if (lane >= o) pre += tt;
        }
        unsigned wtot = __shfl_sync(0xffffffffu, pre, 31);
        unsigned wbase = 0;
        if (lane == 31 && wtot > 0) wbase = atomicAdd(&s_cnt, wtot);
        wbase = __shfl_sync(0xffffffffu, wbase, 31);
        unsigned pos = wbase + pre - my;
        if (my > 0) {
#pragma unroll
            for (int i = 0; i < 16; i++) {
                if (key[i] > thrKey) {
                    if (pos < 256) {
                        unsigned idx = (unsigned)((tid + (i >> 2) * 256) * 4 + (i & 3));
                        cand[pos] = ((u64)key[i] << 12) | (u64)(4095u - idx);
                    }
                    pos++;
                }
            }
        }
        __syncthreads();
        cnt = (int)s_cnt;
        if (cnt >= MAXK && cnt <= 256) { ok = true; break; }
        if (cnt < MAXK) zf -= 0.6f; else zf += 0.45f;
    }

    if (!ok) {
        // exact block-wide extraction fallback (rare)
        for (int r2 = 0; r2 < MAXK; r2++) {
            u64 lb = 0;
#pragma unroll
            for (int i = 0; i < 16; i++) {
                unsigned idx = (unsigned)((tid + (i >> 2) * 256) * 4 + (i & 3));
                u64 p = ((u64)key[i] << 12) | (u64)(4095u - idx);
                if (p > lb) lb = p;
            }
            lb = warpReduceMaxU64(lb);
            if (lane == 0) ured[wid] = lb;
            __syncthreads();
            if (tid == 0) {
                u64 w = ured[0];
#pragma unroll
                for (int i = 1; i < 8; i++) w = (ured[i] > w) ? ured[i] : w;
                s_win = w; sel[r2] = w;
            }
            __syncthreads();
            u64 wb = s_win;
#pragma unroll
            for (int i = 0; i < 16; i++) {
                unsigned idx = (unsigned)((tid + (i >> 2) * 256) * 4 + (i & 3));
                u64 p = ((u64)key[i] << 12) | (u64)(4095u - idx);
                if (p == wb) key[i] = 0u;
            }
            __syncthreads();
        }
    }
    // ensure cand[] writes visible to warp 0
    __syncthreads();

    // warp 0: exact extraction from candidates (ok path) + outputs
    if (wid == 0) {
        u64 mysel;
        if (ok) {
            u64 cl[8];
#pragma unroll
            for (int q = 0; q < 8; q++) {
                int p = lane + 32 * q;
                cl[q] = (p < cnt) ? cand[p] : 0ull;
            }
            // presort 8 desc
#pragma unroll
            for (int a = 1; a < 8; a++)
#pragma unroll
                for (int b2 = a; b2 > 0; b2--) {
                    u64 lo = cl[b2 - 1] < cl[b2] ? cl[b2 - 1] : cl[b2];
                    u64 hi = cl[b2 - 1] < cl[b2] ? cl[b2] : cl[b2 - 1];
                    cl[b2 - 1] = hi; cl[b2] = lo;
                }
            mysel = 0;
#pragma unroll
            for (int r2 = 0; r2 < MAXK; r2++) {
                u64 wb = warpReduceMaxU64(cl[0]);
                if (cl[0] == wb) {     // unique winner (idx unique)
#pragma unroll
                    for (int q = 0; q < 7; q++) cl[q] = cl[q + 1];
                    cl[7] = 0ull;
                }
                if (lane == r2) mysel = wb;
            }
        } else {
            mysel = sel[lane];
        }

        unsigned keyv = (unsigned)(mysel >> 12);
        unsigned idxv = 4095u - (unsigned)(mysel & 0xFFFull);
        unsigned fb = (keyv & 0x80000000u) ? (keyv ^ 0x80000000u) : ~keyv;
        float val = __uint_as_float(fb);

        int b = g_budget[t];
        float v0 = __shfl_sync(0xffffffffu, val, 0);
        bool msk = lane < b;
        float ev = msk ? __expf(val - v0) : 0.f;
        float zz = warpReduceSumF(ev);
        float w = msk ? ev / zz : 0.f;

        out_idx[(size_t)t * MAXK + lane] = (float)idxv;
        out_w[(size_t)t * MAXK + lane] = w;
        if (msk) atomicAdd(&g_counts[idxv], 1.0f);
    }
}

// ---------------- K4: aux ----------------
__global__ __launch_bounds__(256) void k_aux()
{
    __shared__ float sredZ[8], sredD[8], s_m;
    const int t = blockIdx.x;
    const int tid = threadIdx.x, lane = tid & 31, wid = tid >> 5;
    const float* row = g_scores + (size_t)t * NSLOT;

    float4 r[4];
#pragma unroll
    for (int i = 0; i < 4; i++) r[i] = *(const float4*)(row + (size_t)(tid + i * 256) * 4);

    float m = r[0].x;
#pragma unroll
    for (int i = 0; i < 4; i++) {
        m = fmaxf(m, r[i].x); m = fmaxf(m, r[i].y);
        m = fmaxf(m, r[i].z); m = fmaxf(m, r[i].w);
    }
    m = warpReduceMaxF(m);
    if (lane == 0) sredZ[wid] = m;
    __syncthreads();
    if (tid == 0) {
        float mm = sredZ[0];
#pragma unroll
        for (int i = 1; i < 8; i++) mm = fmaxf(mm, sredZ[i]);
        s_m = mm;
    }
    __syncthreads();
    m = s_m;

    float z = 0.f, d = 0.f;
#pragma unroll
    for (int i = 0; i < 4; i++) {
        float4 c = g_counts_v[tid + i * 256];
        float e0 = __expf(r[i].x - m), e1 = __expf(r[i].y - m);
        float e2 = __expf(r[i].z - m), e3 = __expf(r[i].w - m);
        z += e0 + e1 + e2 + e3;
        d += e0 * c.x + e1 * c.y + e2 * c.z + e3 * c.w;
    }
    z = warpReduceSumF(z);
    d = warpReduceSumF(d);
    if (lane == 0) { sredZ[wid] = z; sredD[wid] = d; }
    __syncthreads();
    if (tid == 0) {
        float zz = 0.f, dd = 0.f;
#pragma unroll
        for (int i = 0; i < 8; i++) { zz += sredZ[i]; dd += sredD[i]; }
        float contrib = (dd / zz) * ((float)NSLOT / ((float)TOK * (float)TOK));
        atomicAdd(&g_aux, contrib);
    }
}

// ---------------- K5 ----------------
__global__ void k_finish(float* __restrict__ out_aux)
{
    if (threadIdx.x == 0) out_aux[0] = g_aux;
}

// ---------------- launch ----------------
extern "C" void kernel_launch(void* const* d_in, const int* in_sizes, int n_in,
                              void* d_out, int out_size)
{
    const float* x  = (const float*)d_in[0];
    const float* Wc = (const float*)d_in[1];
    const float* bc = (const float*)d_in[2];
    const float* Wh = (const float*)d_in[3];
    const float* bh = (const float*)d_in[4];
    const float* Ws = (const float*)d_in[5];
    const float* bs = (const float*)d_in[6];

    float* out     = (float*)d_out;
    float* out_idx = out;
    float* out_w   = out + TOK * MAXK;
    float* out_b   = out + 2 * TOK * MAXK;
    float* out_aux = out + 2 * TOK * MAXK + TOK;

    const int smem2 = 2 * 128 * 132 * (int)sizeof(float);
    cudaFuncSetAttribute(k_scores, cudaFuncAttributeMaxDynamicSharedMemorySize, smem2);

    k_init<<<(NSLOT + 255) / 256, 256>>>();
    k_hidden<<<TOK / 128, 256>>>(x, Wc, bc, Wh, bh, out_b);
    k_scores<<<TOK / 128, 256, smem2>>>(Ws, bs);
    k_topk<<<TOK, 256>>>(out_idx, out_w);
    k_aux<<<TOK, 256>>>();
    k_finish<<<1, 32>>>(out_aux);
}

// round 6
// speedup vs baseline: 1.2713x; 1.2713x over previous
#include <cuda_runtime.h>

#define TOK   32768
#define DIN   1024
#define RDIM  128
#define NSLOT 4096
#define MAXK  32

typedef unsigned long long u64;

// ---------------- scratch ----------------
__device__ float  g_hidden[TOK * RDIM];
__device__ float4 g_scores_v[TOK * NSLOT / 4];     // 512 MB
__device__ int    g_budget[TOK];
__device__ float4 g_counts_v[NSLOT / 4];
__device__ float  g_aux;

#define g_scores ((float*)g_scores_v)
#define g_counts ((float*)g_counts_v)

// ---------------- reductions ----------------
__device__ __forceinline__ float warpReduceMaxF(float v) {
#pragma unroll
    for (int o = 16; o > 0; o >>= 1) v = fmaxf(v, __shfl_xor_sync(0xffffffffu, v, o));
    return v;
}
__device__ __forceinline__ float warpReduceSumF(float v) {
#pragma unroll
    for (int o = 16; o > 0; o >>= 1) v += __shfl_xor_sync(0xffffffffu, v, o);
    return v;
}
__device__ __forceinline__ int warpReduceSumI(int v) {
#pragma unroll
    for (int o = 16; o > 0; o >>= 1) v += __shfl_xor_sync(0xffffffffu, v, o);
    return v;
}
__device__ __forceinline__ int warpReduceMinI(int v) {
#pragma unroll
    for (int o = 16; o > 0; o >>= 1) {
        int t = __shfl_xor_sync(0xffffffffu, v, o);
        v = (t < v) ? t : v;
    }
    return v;
}
__device__ __forceinline__ u64 warpReduceMaxU64(u64 v) {
#pragma unroll
    for (int o = 16; o > 0; o >>= 1) {
        u64 t = __shfl_xor_sync(0xffffffffu, v, o);
        v = (t > v) ? t : v;
    }
    return v;
}

// ---------------- K0 ----------------
__global__ void k_init() {
    int i = blockIdx.x * blockDim.x + threadIdx.x;
    if (i < NSLOT) g_counts[i] = 0.f;
    if (i == 0)    g_aux = 0.f;
}

// ---------------- K1: hidden GEMM + budget ----------------
__global__ __launch_bounds__(256) void k_hidden(
    const float* __restrict__ x,  const float* __restrict__ Wc, const float* __restrict__ bc,
    const float* __restrict__ Wh, const float* __restrict__ bh, float* __restrict__ out_b)
{
    __shared__ float Xs[32][132];
    __shared__ float Wsm[32][128];
    __shared__ float Wcs[32];

    const int tid = threadIdx.x;
    const int tx = tid & 15, ty = tid >> 4;
    const int t0 = blockIdx.x * 128;

    float acc[8][8];
#pragma unroll
    for (int j = 0; j < 8; j++) {
        int c = (j < 4) ? tx * 4 + j : 64 + tx * 4 + (j - 4);
        float b = bh[c];
#pragma unroll
        for (int i = 0; i < 8; i++) acc[i][j] = b;
    }
    float cacc = 0.f;

    for (int kt = 0; kt < 32; kt++) {
#pragma unroll
        for (int i = 0; i < 4; i++) {
            int id = tid + i * 256;
            int token = id >> 3, kg = id & 7;
            float4 f = *(const float4*)(x + (size_t)(t0 + token) * DIN + kt * 32 + kg * 4);
            Xs[kg * 4 + 0][token] = f.x; Xs[kg * 4 + 1][token] = f.y;
            Xs[kg * 4 + 2][token] = f.z; Xs[kg * 4 + 3][token] = f.w;
        }
#pragma unroll
        for (int i = 0; i < 4; i++) {
            int id = tid + i * 256;
            int rowk = id >> 5, ng = id & 31;
            *(float4*)&Wsm[rowk][ng * 4] =
                *(const float4*)(Wh + (size_t)(kt * 32 + rowk) * RDIM + ng * 4);
        }
        if (tid < 32) Wcs[tid] = Wc[kt * 32 + tid];
        __syncthreads();

#pragma unroll
        for (int k = 0; k < 32; k++) {
            float4 a0 = *(float4*)&Xs[k][ty * 4];
            float4 a1 = *(float4*)&Xs[k][64 + ty * 4];
            float4 b0 = *(float4*)&Wsm[k][tx * 4];
            float4 b1 = *(float4*)&Wsm[k][64 + tx * 4];
            float xf[8] = {a0.x, a0.y, a0.z, a0.w, a1.x, a1.y, a1.z, a1.w};
            float wf[8] = {b0.x, b0.y, b0.z, b0.w, b1.x, b1.y, b1.z, b1.w};
#pragma unroll
            for (int i = 0; i < 8; i++)
#pragma unroll
                for (int j = 0; j < 8; j++)
                    acc[i][j] += xf[i] * wf[j];
        }
        if (tid < 128) {
            float s = 0.f;
#pragma unroll
            for (int k = 0; k < 32; k++) s += Xs[k][tid] * Wcs[k];
            cacc += s;
        }
        __syncthreads();
    }

#pragma unroll
    for (int i = 0; i < 8; i++) {
        int r = (i < 4) ? ty * 4 + i : 64 + ty * 4 + (i - 4);
        float4 o0 = make_float4(fmaxf(acc[i][0], 0.f), fmaxf(acc[i][1], 0.f),
                                fmaxf(acc[i][2], 0.f), fmaxf(acc[i][3], 0.f));
        float4 o1 = make_float4(fmaxf(acc[i][4], 0.f), fmaxf(acc[i][5], 0.f),
                                fmaxf(acc[i][6], 0.f), fmaxf(acc[i][7], 0.f));
        *(float4*)(g_hidden + (size_t)(t0 + r) * RDIM + tx * 4) = o0;
        *(float4*)(g_hidden + (size_t)(t0 + r) * RDIM + 64 + tx * 4) = o1;
    }
    if (tid < 128) {
        float zc = cacc + bc[0];
        float c = 1.f / (1.f + expf(-zc));
        float bf = 4.f + 28.f * c * c;
        int b = (int)floorf(bf);
        g_budget[t0 + tid] = b;
        out_b[t0 + tid] = (float)b;
    }
}

// ---------------- K2: scores GEMM ----------------
__global__ __launch_bounds__(256) void k_scores(const float* __restrict__ Wsg,
                                                const float* __restrict__ bs)
{
    extern __shared__ float sm[];
    float* Hs = sm;
    float* Wt = sm + 128 * 132;

    const int tid = threadIdx.x;
    const int tx = tid & 15, ty = tid >> 4;
    const int t0 = blockIdx.x * 128;

#pragma unroll
    for (int i = 0; i < 16; i++) {
        int id = tid + i * 256;
        int token = id >> 5, kg = id & 31;
        float4 f = *(const float4*)(g_hidden + (size_t)(t0 + token) * RDIM + kg * 4);
        Hs[(kg * 4 + 0) * 132 + token] = f.x;
        Hs[(kg * 4 + 1) * 132 + token] = f.y;
        Hs[(kg * 4 + 2) * 132 + token] = f.z;
        Hs[(kg * 4 + 3) * 132 + token] = f.w;
    }

    for (int nt = 0; nt < 32; nt++) {
        __syncthreads();
#pragma unroll
        for (int i = 0; i < 16; i++) {
            int id = tid + i * 256;
            int rowk = id >> 5, ng = id & 31;
            *(float4*)&Wt[rowk * 132 + ng * 4] =
                *(const float4*)(Wsg + (size_t)rowk * NSLOT + nt * 128 + ng * 4);
        }
        __syncthreads();

        float acc[8][8];
#pragma unroll
        for (int j = 0; j < 8; j++) {
            int c = (j < 4) ? tx * 4 + j : 64 + tx * 4 + (j - 4);
            float b = bs[nt * 128 + c];
#pragma unroll
            for (int i = 0; i < 8; i++) acc[i][j] = b;
        }
#pragma unroll 8
        for (int k = 0; k < 128; k++) {
            float4 a0 = *(float4*)&Hs[k * 132 + ty * 4];
            float4 a1 = *(float4*)&Hs[k * 132 + 64 + ty * 4];
            float4 b0 = *(float4*)&Wt[k * 132 + tx * 4];
            float4 b1 = *(float4*)&Wt[k * 132 + 64 + tx * 4];
            float xf[8] = {a0.x, a0.y, a0.z, a0.w, a1.x, a1.y, a1.z, a1.w};
            float wf[8] = {b0.x, b0.y, b0.z, b0.w, b1.x, b1.y, b1.z, b1.w};
#pragma unroll
            for (int i = 0; i < 8; i++)
#pragma unroll
                for (int j = 0; j < 8; j++)
                    acc[i][j] += xf[i] * wf[j];
        }
#pragma unroll
        for (int i = 0; i < 8; i++) {
            int r = (i < 4) ? ty * 4 + i : 64 + ty * 4 + (i - 4);
            float* base = g_scores + (size_t)(t0 + r) * NSLOT + nt * 128;
            *(float4*)(base + tx * 4)      = make_float4(acc[i][0], acc[i][1], acc[i][2], acc[i][3]);
            *(float4*)(base + 64 + tx * 4) = make_float4(acc[i][4], acc[i][5], acc[i][6], acc[i][7]);
        }
    }
}

// ---------------- K3: block-per-token exact top-32, smem-staged keys ----------------
__global__ __launch_bounds__(256) void k_topk(float* __restrict__ out_idx,
                                              float* __restrict__ out_w)
{
    __shared__ unsigned skey[4096];      // 16 KB sortable keys
    __shared__ u64      cand[256];
    __shared__ float    fred[8], f2red[8];
    __shared__ int      ired[8];
    __shared__ unsigned s_cnt;
    __shared__ int      s_best;

    const int t = blockIdx.x;
    const int tid = threadIdx.x, lane = tid & 31, wid = tid >> 5;
    const float4* rowv = (const float4*)(g_scores + (size_t)t * NSLOT);

    // pass 0: DRAM -> keys in smem, accumulate stats
    float s = 0.f, s2 = 0.f;
#pragma unroll
    for (int i = 0; i < 4; i++) {
        int e4 = tid + i * 256;
        float4 f = rowv[e4];
        float vv[4] = {f.x, f.y, f.z, f.w};
        unsigned kk[4];
#pragma unroll
        for (int j = 0; j < 4; j++) {
            s += vv[j]; s2 += vv[j] * vv[j];
            unsigned b = __float_as_uint(vv[j]);
            kk[j] = b ^ ((unsigned)((int)b >> 31) | 0x80000000u);
        }
        *(uint4*)&skey[e4 * 4] = make_uint4(kk[0], kk[1], kk[2], kk[3]);
    }
    s = warpReduceSumF(s);
    s2 = warpReduceSumF(s2);
    if (lane == 0) { fred[wid] = s; f2red[wid] = s2; }
    __syncthreads();
    float ss = 0.f, ss2 = 0.f;
#pragma unroll
    for (int i = 0; i < 8; i++) { ss += fred[i]; ss2 += f2red[i]; }
    const float mean = ss * (1.f / NSLOT);
    const float sigma = sqrtf(fmaxf(ss2 * (1.f / NSLOT) - mean * mean, 0.f)) + 1e-20f;

    // counting pass over smem keys (block-uniform thrKey); 2 barriers
    auto countGreater = [&](unsigned thrKey) -> int {
        int c = 0;
#pragma unroll
        for (int i = 0; i < 4; i++) {
            uint4 k4 = *(uint4*)&skey[(tid + i * 256) * 4];
            c += (k4.x > thrKey) + (k4.y > thrKey) + (k4.z > thrKey) + (k4.w > thrKey);
        }
        c = warpReduceSumI(c);
        __syncthreads();               // protect ired from previous use
        if (lane == 0) ired[wid] = c;
        __syncthreads();
        int tot = 0;
#pragma unroll
        for (int i = 0; i < 8; i++) tot += ired[i];
        return tot;                    // uniform across block
    };

    // phase 1: statistical threshold, few attempts
    unsigned thrKey = 0;
    int cnt = 0;
    bool ok = false;
    float zf = 2.3f;
    for (int a = 0; a < 4; a++) {
        float thr = mean + zf * sigma;
        unsigned tb = __float_as_uint(thr);
        unsigned tk = tb ^ ((unsigned)((int)tb >> 31) | 0x80000000u);
        int c = countGreater(tk);
        if (c >= MAXK && c <= 256) { thrKey = tk; cnt = c; ok = true; break; }
        zf += (c < MAXK) ? -0.7f : 0.5f;
    }

    bool tiePath = false;
    unsigned Tkey = 0;
    if (!ok) {
        // exact: binary search max K with count(>K) >= 32  (distribution-independent)
        unsigned K = 0;
        for (int bit = 31; bit >= 0; bit--) {
            unsigned trial = K | (1u << bit);
            if (countGreater(trial) >= MAXK) K = trial;
        }
        int c = countGreater(K);       // includes all keys >= T (T = K+1)
        if (c <= 256) {
            thrKey = K; cnt = c; ok = true;
        } else {
            tiePath = true;            // massive ties at T
            Tkey = K + 1u;
            thrKey = Tkey;             // compact strictly greater than T (< 32 of them)
            cnt = countGreater(Tkey);
        }
    }

    // compaction pass: all keys > thrKey -> cand[] (warp prefix + shared atomic)
    if (tid == 0) s_cnt = 0;
    __syncthreads();
    {
        unsigned kk[16];
        unsigned my = 0;
#pragma unroll
        for (int i = 0; i < 4; i++) {
            uint4 k4 = *(uint4*)&skey[(tid + i * 256) * 4];
            kk[i * 4 + 0] = k4.x; kk[i * 4 + 1] = k4.y;
            kk[i * 4 + 2] = k4.z; kk[i * 4 + 3] = k4.w;
        }
#pragma unroll
        for (int i = 0; i < 16; i++) my += (kk[i] > thrKey) ? 1u : 0u;
        unsigned pre = my;
#pragma unroll
        for (int o = 1; o < 32; o <<= 1) {
            unsigned tt = __shfl_up_sync(0xffffffffu, pre, o);
            if (lane >= o) pre += tt;
        }
        unsigned wtot = __shfl_sync(0xffffffffu, pre, 31);
        unsigned wbase = 0;
        if (lane == 31 && wtot > 0) wbase = atomicAdd(&s_cnt, wtot);
        wbase = __shfl_sync(0xffffffffu, wbase, 31);
        unsigned pos = wbase + pre - my;
        if (my > 0) {
#pragma unroll
            for (int i = 0; i < 16; i++) {
                if (kk[i] > thrKey) {
                    if (pos < 256) {
                        unsigned idx = (unsigned)((tid + (i >> 2) * 256) * 4 + (i & 3));
                        cand[pos] = ((u64)kk[i] << 12) | (u64)(4095u - idx);
                    }
                    pos++;
                }
            }
        }
    }
    __syncthreads();

    if (tiePath) {
        // fill remaining slots with equal-to-T keys, smallest index first (jax tie-break)
        int lastIdx = -1;
        for (int e = cnt; e < MAXK; e++) {
            int best = 0x7FFFFFFF;
#pragma unroll
            for (int i = 0; i < 4; i++) {
                uint4 k4 = *(uint4*)&skey[(tid + i * 256) * 4];
                unsigned ka[4] = {k4.x, k4.y, k4.z, k4.w};
#pragma unroll
                for (int j = 0; j < 4; j++) {
                    int idx = (tid + i * 256) * 4 + j;
                    if (ka[j] == Tkey && idx > lastIdx && idx < best) best = idx;
                }
            }
            best = warpReduceMinI(best);
            __syncthreads();
            if (lane == 0) ired[wid] = best;
            __syncthreads();
            if (tid == 0) {
                int bb = ired[0];
#pragma unroll
                for (int i = 1; i < 8; i++) bb = (ired[i] < bb) ? ired[i] : bb;
                s_best = bb;
                cand[e] = ((u64)Tkey << 12) | (u64)(4095u - (unsigned)bb);
            }
            __syncthreads();
            lastIdx = s_best;
        }
        cnt = MAXK;
        __syncthreads();
    }

    // warp 0: exact extraction of top-32 from cand[0..cnt) + outputs
    if (wid == 0) {
        u64 cl[8];
#pragma unroll
        for (int q = 0; q < 8; q++) {
            int p = lane + 32 * q;
            cl[q] = (p < cnt) ? cand[p] : 0ull;
        }
        // presort 8 desc per lane
#pragma unroll
        for (int a = 1; a < 8; a++)
#pragma unroll
            for (int b2 = a; b2 > 0; b2--) {
                u64 lo = cl[b2 - 1] < cl[b2] ? cl[b2 - 1] : cl[b2];
                u64 hi = cl[b2 - 1] < cl[b2] ? cl[b2] : cl[b2 - 1];
                cl[b2 - 1] = hi; cl[b2] = lo;
            }
        u64 mysel = 0;
#pragma unroll
        for (int r2 = 0; r2 < MAXK; r2++) {
            u64 wb = warpReduceMaxU64(cl[0]);
            if (cl[0] == wb) {      // unique winner (packed idx unique)
#pragma unroll
                for (int q = 0; q < 7; q++) cl[q] = cl[q + 1];
                cl[7] = 0ull;
            }
            if (lane == r2) mysel = wb;
        }

        unsigned keyv = (unsigned)(mysel >> 12);
        unsigned idxv = 4095u - (unsigned)(mysel & 0xFFFull);
        unsigned fb = (keyv & 0x80000000u) ? (keyv ^ 0x80000000u) : ~keyv;
        float val = __uint_as_float(fb);

        int b = g_budget[t];
        float v0 = __shfl_sync(0xffffffffu, val, 0);
        bool msk = lane < b;
        float ev = msk ? __expf(val - v0) : 0.f;
        float zz = warpReduceSumF(ev);
        float w = msk ? ev / zz : 0.f;

        out_idx[(size_t)t * MAXK + lane] = (float)idxv;
        out_w[(size_t)t * MAXK + lane] = w;
        if (msk) atomicAdd(&g_counts[idxv], 1.0f);
    }
}

// ---------------- K4: aux ----------------
__global__ __launch_bounds__(256) void k_aux()
{
    __shared__ float sredZ[8], sredD[8], s_m;
    const int t = blockIdx.x;
    const int tid = threadIdx.x, lane = tid & 31, wid = tid >> 5;
    const float* row = g_scores + (size_t)t * NSLOT;

    float4 r[4];
#pragma unroll
    for (int i = 0; i < 4; i++) r[i] = *(const float4*)(row + (size_t)(tid + i * 256) * 4);

    float m = r[0].x;
#pragma unroll
    for (int i = 0; i < 4; i++) {
        m = fmaxf(m, r[i].x); m = fmaxf(m, r[i].y);
        m = fmaxf(m, r[i].z); m = fmaxf(m, r[i].w);
    }
    m = warpReduceMaxF(m);
    if (lane == 0) sredZ[wid] = m;
    __syncthreads();
    if (tid == 0) {
        float mm = sredZ[0];
#pragma unroll
        for (int i = 1; i < 8; i++) mm = fmaxf(mm, sredZ[i]);
        s_m = mm;
    }
    __syncthreads();
    m = s_m;

    float z = 0.f, d = 0.f;
#pragma unroll
    for (int i = 0; i < 4; i++) {
        float4 c = g_counts_v[tid + i * 256];
        float e0 = __expf(r[i].x - m), e1 = __expf(r[i].y - m);
        float e2 = __expf(r[i].z - m), e3 = __expf(r[i].w - m);
        z += e0 + e1 + e2 + e3;
        d += e0 * c.x + e1 * c.y + e2 * c.z + e3 * c.w;
    }
    z = warpReduceSumF(z);
    d = warpReduceSumF(d);
    if (lane == 0) { sredZ[wid] = z; sredD[wid] = d; }
    __syncthreads();
    if (tid == 0) {
        float zz = 0.f, dd = 0.f;
#pragma unroll
        for (int i = 0; i < 8; i++) { zz += sredZ[i]; dd += sredD[i]; }
        float contrib = (dd / zz) * ((float)NSLOT / ((float)TOK * (float)TOK));
        atomicAdd(&g_aux, contrib);
    }
}

// ---------------- K5 ----------------
__global__ void k_finish(float* __restrict__ out_aux)
{
    if (threadIdx.x == 0) out_aux[0] = g_aux;
}

// ---------------- launch ----------------
extern "C" void kernel_launch(void* const* d_in, const int* in_sizes, int n_in,
                              void* d_out, int out_size)
{
    const float* x  = (const float*)d_in[0];
    const float* Wc = (const float*)d_in[1];
    const float* bc = (const float*)d_in[2];
    const float* Wh = (const float*)d_in[3];
    const float* bh = (const float*)d_in[4];
    const float* Ws = (const float*)d_in[5];
    const float* bs = (const float*)d_in[6];

    float* out     = (float*)d_out;
    float* out_idx = out;
    float* out_w   = out + TOK * MAXK;
    float* out_b   = out + 2 * TOK * MAXK;
    float* out_aux = out + 2 * TOK * MAXK + TOK;

    const int smem2 = 2 * 128 * 132 * (int)sizeof(float);
    cudaFuncSetAttribute(k_scores, cudaFuncAttributeMaxDynamicSharedMemorySize, smem2);

    k_init<<<(NSLOT + 255) / 256, 256>>>();
    k_hidden<<<TOK / 128, 256>>>(x, Wc, bc, Wh, bh, out_b);
    k_scores<<<TOK / 128, 256, smem2>>>(Ws, bs);
    k_topk<<<TOK, 256>>>(out_idx, out_w);
    k_aux<<<TOK, 256>>>();
    k_finish<<<1, 32>>>(out_aux);
}

// round 10
// speedup vs baseline: 1.3702x; 1.0778x over previous
#include <cuda_runtime.h>
#include <cstdint>

#define TOK   32768
#define DIN   1024
#define RDIM  128
#define NSLOT 4096
#define MAXK  32
#define KSEL  48

typedef unsigned long long u64;

// ---------------- scratch ----------------
__device__ float  g_hidden[TOK * RDIM];
__device__ float4 g_scores_v[TOK * NSLOT / 4];     // 512 MB (approx scores)
__device__ float  g_wsT[NSLOT * RDIM];             // 2 MB W_s transposed
__device__ int    g_budget[TOK];
__device__ float4 g_counts_v[NSLOT / 4];
__device__ float  g_aux;

#define g_scores ((float*)g_scores_v)
#define g_counts ((float*)g_counts_v)

// ---------------- tf32 ----------------
__device__ __forceinline__ float to_tf32(float v) {
    unsigned h;
    asm("cvt.rna.tf32.f32 %0, %1;" : "=r"(h) : "f"(v));
    return __uint_as_float(h);
}

#define MMA_TF32(c, a, b) \
    asm volatile("mma.sync.aligned.m16n8k8.row.col.f32.tf32.tf32.f32 " \
        "{%0,%1,%2,%3}, {%4,%5,%6,%7}, {%8,%9}, {%0,%1,%2,%3};" \
        : "+f"((c)[0]), "+f"((c)[1]), "+f"((c)[2]), "+f"((c)[3]) \
        : "r"(__float_as_uint((a).x)), "r"(__float_as_uint((a).y)), \
          "r"(__float_as_uint((a).z)), "r"(__float_as_uint((a).w)), \
          "r"(__float_as_uint((b).x)), "r"(__float_as_uint((b).y)))

// smem layout for k_scores_mma (bytes)
#define SM2_A     0          // 128x128 fp32 frag-order (65536)
#define SM2_B     65536      // 128x64 frag-order (32768)
#define SM2_BIAS  98304      // 4096 floats (16384)
#define SM2_TOTAL 114688

// ---------------- reductions ----------------
__device__ __forceinline__ float warpReduceMaxF(float v) {
#pragma unroll
    for (int o = 16; o > 0; o >>= 1) v = fmaxf(v, __shfl_xor_sync(0xffffffffu, v, o));
    return v;
}
__device__ __forceinline__ float warpReduceSumF(float v) {
#pragma unroll
    for (int o = 16; o > 0; o >>= 1) v += __shfl_xor_sync(0xffffffffu, v, o);
    return v;
}
__device__ __forceinline__ int warpReduceSumI(int v) {
#pragma unroll
    for (int o = 16; o > 0; o >>= 1) v += __shfl_xor_sync(0xffffffffu, v, o);
    return v;
}
__device__ __forceinline__ int warpReduceMinI(int v) {
#pragma unroll
    for (int o = 16; o > 0; o >>= 1) {
        int t = __shfl_xor_sync(0xffffffffu, v, o);
        v = (t < v) ? t : v;
    }
    return v;
}
__device__ __forceinline__ u64 warpReduceMaxU64(u64 v) {
#pragma unroll
    for (int o = 16; o > 0; o >>= 1) {
        u64 t = __shfl_xor_sync(0xffffffffu, v, o);
        v = (t > v) ? t : v;
    }
    return v;
}

// ---------------- K0 ----------------
__global__ void k_init() {
    int i = blockIdx.x * blockDim.x + threadIdx.x;
    if (i < NSLOT) g_counts[i] = 0.f;
    if (i == 0)    g_aux = 0.f;
}

// ---------------- K0b: transpose W_s -> g_wsT[N][R] ----------------
__global__ __launch_bounds__(256) void k_transpose(const float* __restrict__ Wsg) {
    __shared__ float tile[32][33];
    const int bx = blockIdx.x;          // n tile 0..127
    const int by = blockIdx.y;          // r tile 0..3
    const int tx = threadIdx.x & 31, ty = threadIdx.x >> 5;   // 32 x 8
#pragma unroll
    for (int i = 0; i < 4; i++) {
        int r = by * 32 + ty + i * 8;
        tile[ty + i * 8][tx] = Wsg[(size_t)r * NSLOT + bx * 32 + tx];
    }
    __syncthreads();
#pragma unroll
    for (int i = 0; i < 4; i++) {
        int n = bx * 32 + ty + i * 8;
        g_wsT[(size_t)n * RDIM + by * 32 + tx] = tile[tx][ty + i * 8];
    }
}

// ---------------- K1: hidden GEMM + budget (unchanged) ----------------
__global__ __launch_bounds__(256) void k_hidden(
    const float* __restrict__ x,  const float* __restrict__ Wc, const float* __restrict__ bc,
    const float* __restrict__ Wh, const float* __restrict__ bh, float* __restrict__ out_b)
{
    __shared__ float Xs[32][132];
    __shared__ float Wsm[32][128];
    __shared__ float Wcs[32];

    const int tid = threadIdx.x;
    const int tx = tid & 15, ty = tid >> 4;
    const int t0 = blockIdx.x * 128;

    float acc[8][8];
#pragma unroll
    for (int j = 0; j < 8; j++) {
        int c = (j < 4) ? tx * 4 + j : 64 + tx * 4 + (j - 4);
        float b = bh[c];
#pragma unroll
        for (int i = 0; i < 8; i++) acc[i][j] = b;
    }
    float cacc = 0.f;

    for (int kt = 0; kt < 32; kt++) {
#pragma unroll
        for (int i = 0; i < 4; i++) {
            int id = tid + i * 256;
            int token = id >> 3, kg = id & 7;
            float4 f = *(const float4*)(x + (size_t)(t0 + token) * DIN + kt * 32 + kg * 4);
            Xs[kg * 4 + 0][token] = f.x; Xs[kg * 4 + 1][token] = f.y;
            Xs[kg * 4 + 2][token] = f.z; Xs[kg * 4 + 3][token] = f.w;
        }
#pragma unroll
        for (int i = 0; i < 4; i++) {
            int id = tid + i * 256;
            int rowk = id >> 5, ng = id & 31;
            *(float4*)&Wsm[rowk][ng * 4] =
                *(const float4*)(Wh + (size_t)(kt * 32 + rowk) * RDIM + ng * 4);
        }
        if (tid < 32) Wcs[tid] = Wc[kt * 32 + tid];
        __syncthreads();

#pragma unroll
        for (int k = 0; k < 32; k++) {
            float4 a0 = *(float4*)&Xs[k][ty * 4];
            float4 a1 = *(float4*)&Xs[k][64 + ty * 4];
            float4 b0 = *(float4*)&Wsm[k][tx * 4];
            float4 b1 = *(float4*)&Wsm[k][64 + tx * 4];
            float xf[8] = {a0.x, a0.y, a0.z, a0.w, a1.x, a1.y, a1.z, a1.w};
            float wf[8] = {b0.x, b0.y, b0.z, b0.w, b1.x, b1.y, b1.z, b1.w};
#pragma unroll
            for (int i = 0; i < 8; i++)
#pragma unroll
                for (int j = 0; j < 8; j++)
                    acc[i][j] += xf[i] * wf[j];
        }
        if (tid < 128) {
            float s = 0.f;
#pragma unroll
            for (int k = 0; k < 32; k++) s += Xs[k][tid] * Wcs[k];
            cacc += s;
        }
        __syncthreads();
    }

#pragma unroll
    for (int i = 0; i < 8; i++) {
        int r = (i < 4) ? ty * 4 + i : 64 + ty * 4 + (i - 4);
        float4 o0 = make_float4(fmaxf(acc[i][0], 0.f), fmaxf(acc[i][1], 0.f),
                                fmaxf(acc[i][2], 0.f), fmaxf(acc[i][3], 0.f));
        float4 o1 = make_float4(fmaxf(acc[i][4], 0.f), fmaxf(acc[i][5], 0.f),
                                fmaxf(acc[i][6], 0.f), fmaxf(acc[i][7], 0.f));
        *(float4*)(g_hidden + (size_t)(t0 + r) * RDIM + tx * 4) = o0;
        *(float4*)(g_hidden + (size_t)(t0 + r) * RDIM + 64 + tx * 4) = o1;
    }
    if (tid < 128) {
        float zc = cacc + bc[0];
        float c = 1.f / (1.f + expf(-zc));
        float bf = 4.f + 28.f * c * c;
        int b = (int)floorf(bf);
        g_budget[t0 + tid] = b;
        out_b[t0 + tid] = (float)b;
    }
}

// ---------------- K2: approx scores via single-term tf32 mma.sync ----------------
__global__ __launch_bounds__(256) void k_scores_mma(const float* __restrict__ Wsg,
                                                    const float* __restrict__ bs)
{
    extern __shared__ char smem[];
    float*  sA    = (float*)(smem + SM2_A);
    float*  sB    = (float*)(smem + SM2_B);
    float*  sBias = (float*)(smem + SM2_BIAS);
    const float4* sA4 = (const float4*)sA;
    const float2* sB2 = (const float2*)sB;

    const int tid = threadIdx.x;
    const int lane = tid & 31, wid = tid >> 5;
    const int warpM = wid & 3, warpN = wid >> 2;
    const int gid = lane >> 2, tig = lane & 3;
    const int t0 = blockIdx.x * 128;

#pragma unroll
    for (int i = 0; i < 4; i++) {
        int id = tid + i * 256;
        ((float4*)sBias)[id] = ((const float4*)bs)[id];
    }

    // stage A: hidden[128][128] tf32 in fragment order
#pragma unroll
    for (int i = 0; i < 16; i++) {
        int id = tid + i * 256;
        int m = id >> 5, fg = id & 31;
        float4 v = *(const float4*)(g_hidden + (size_t)(t0 + m) * RDIM + fg * 4);
        float hv[4] = {to_tf32(v.x), to_tf32(v.y), to_tf32(v.z), to_tf32(v.w)};
        int mt = m >> 4, rr = m & 15;
#pragma unroll
        for (int j = 0; j < 4; j++) {
            int k = fg * 4 + j;
            int kc = k >> 3, c4 = k & 7;
            int reg = ((rr >> 3) & 1) | (((c4 >> 2) & 1) << 1);
            int ln = (rr & 7) * 4 + (c4 & 3);
            sA[((mt * 16 + kc) * 32 + ln) * 4 + reg] = hv[j];
        }
    }

    for (int nt = 0; nt < 64; nt++) {
        const int nbase = nt * 64;
        __syncthreads();

        // stage B tile tf32 frag order
#pragma unroll
        for (int i = 0; i < 8; i++) {
            int id = tid + i * 256;
            int k = id >> 4, ng = id & 15;
            float4 v = *(const float4*)(Wsg + (size_t)k * NSLOT + nbase + ng * 4);
            float hv[4] = {to_tf32(v.x), to_tf32(v.y), to_tf32(v.z), to_tf32(v.w)};
            int kc = k >> 3, k8 = k & 7;
            int r = (k8 >> 2) & 1, tg = k8 & 3;
#pragma unroll
            for (int j = 0; j < 4; j++) {
                int n = ng * 4 + j;
                sB[(((kc * 8 + (n >> 3)) * 32 + ((n & 7) * 4 + tg)) * 2) + r] = hv[j];
            }
        }
        __syncthreads();

        float c[2][4][4];
#pragma unroll
        for (int mi = 0; mi < 2; mi++)
#pragma unroll
            for (int ni = 0; ni < 4; ni++)
#pragma unroll
                for (int q = 0; q < 4; q++) c[mi][ni][q] = 0.f;

#pragma unroll 4
        for (int kc = 0; kc < 16; kc++) {
            float4 ah[2];
            float2 bh[4];
#pragma unroll
            for (int mi = 0; mi < 2; mi++) {
                int mt = warpM * 2 + mi;
                ah[mi] = sA4[(mt * 16 + kc) * 32 + lane];
            }
#pragma unroll
            for (int ni = 0; ni < 4; ni++) {
                int nt8 = warpN * 4 + ni;
                bh[ni] = sB2[(kc * 8 + nt8) * 32 + lane];
            }
#pragma unroll
            for (int mi = 0; mi < 2; mi++)
#pragma unroll
                for (int ni = 0; ni < 4; ni++)
                    MMA_TF32(c[mi][ni], ah[mi], bh[ni]);
        }

#pragma unroll
        for (int mi = 0; mi < 2; mi++) {
            int row = t0 + warpM * 32 + mi * 16 + gid;
#pragma unroll
            for (int ni = 0; ni < 4; ni++) {
                int col = nbase + warpN * 32 + ni * 8 + tig * 2;
                float b0 = sBias[col], b1 = sBias[col + 1];
                *(float2*)(g_scores + (size_t)row * NSLOT + col) =
                    make_float2(c[mi][ni][0] + b0, c[mi][ni][1] + b1);
                *(float2*)(g_scores + (size_t)(row + 8) * NSLOT + col) =
                    make_float2(c[mi][ni][2] + b0, c[mi][ni][3] + b1);
            }
        }
    }
}

// ---------------- K3: candidates from approx scores + R1-arithmetic exact refine ----------------
__global__ __launch_bounds__(256) void k_topk(float* __restrict__ out_idx,
                                              float* __restrict__ out_w,
                                              const float* __restrict__ bsg)
{
    __shared__ unsigned skey[4096];
    __shared__ u64      cand[256];
    __shared__ float    hrow[128];
    __shared__ float    fred[8], f2red[8];
    __shared__ int      ired[8];
    __shared__ unsigned s_cnt;
    __shared__ int      s_best;

    const int t = blockIdx.x;
    const int tid = threadIdx.x, lane = tid & 31, wid = tid >> 5;
    const float4* rowv = (const float4*)(g_scores + (size_t)t * NSLOT);

    if (tid < 32)
        *(float4*)&hrow[tid * 4] = *(const float4*)(g_hidden + (size_t)t * RDIM + tid * 4);

    float s = 0.f, s2 = 0.f;
#pragma unroll
    for (int i = 0; i < 4; i++) {
        int e4 = tid + i * 256;
        float4 f = rowv[e4];
        float vv[4] = {f.x, f.y, f.z, f.w};
        unsigned kk[4];
#pragma unroll
        for (int j = 0; j < 4; j++) {
            s += vv[j]; s2 += vv[j] * vv[j];
            unsigned b = __float_as_uint(vv[j]);
            kk[j] = b ^ ((unsigned)((int)b >> 31) | 0x80000000u);
        }
        *(uint4*)&skey[e4 * 4] = make_uint4(kk[0], kk[1], kk[2], kk[3]);
    }
    s = warpReduceSumF(s);
    s2 = warpReduceSumF(s2);
    if (lane == 0) { fred[wid] = s; f2red[wid] = s2; }
    __syncthreads();
    float ss = 0.f, ss2 = 0.f;
#pragma unroll
    for (int i = 0; i < 8; i++) { ss += fred[i]; ss2 += f2red[i]; }
    const float mean = ss * (1.f / NSLOT);
    const float sigma = sqrtf(fmaxf(ss2 * (1.f / NSLOT) - mean * mean, 0.f)) + 1e-20f;

    auto countGreater = [&](unsigned thrKey) -> int {
        int c = 0;
#pragma unroll
        for (int i = 0; i < 4; i++) {
            uint4 k4 = *(uint4*)&skey[(tid + i * 256) * 4];
            c += (k4.x > thrKey) + (k4.y > thrKey) + (k4.z > thrKey) + (k4.w > thrKey);
        }
        c = warpReduceSumI(c);
        __syncthreads();
        if (lane == 0) ired[wid] = c;
        __syncthreads();
        int tot = 0;
#pragma unroll
        for (int i = 0; i < 8; i++) tot += ired[i];
        return tot;
    };

    unsigned thrKey = 0;
    int cnt = 0;
    bool ok = false;
    float zf = 2.2f;
    for (int a = 0; a < 4; a++) {
        float thr = mean + zf * sigma;
        unsigned tb = __float_as_uint(thr);
        unsigned tk = tb ^ ((unsigned)((int)tb >> 31) | 0x80000000u);
        int c = countGreater(tk);
        if (c >= KSEL && c <= 256) { thrKey = tk; cnt = c; ok = true; break; }
        zf += (c < KSEL) ? -0.6f : 0.45f;
    }

    bool tiePath = false;
    unsigned Tkey = 0;
    if (!ok) {
        unsigned K = 0;
        for (int bit = 31; bit >= 0; bit--) {
            unsigned trial = K | (1u << bit);
            if (countGreater(trial) >= KSEL) K = trial;
        }
        int c = countGreater(K);
        if (c <= 256) {
            thrKey = K; cnt = c; ok = true;
        } else {
            tiePath = true;
            Tkey = K + 1u;
            thrKey = Tkey;
            cnt = countGreater(Tkey);
        }
    }

    if (tid == 0) s_cnt = 0;
    __syncthreads();
    {
        unsigned kk[16];
        unsigned my = 0;
#pragma unroll
        for (int i = 0; i < 4; i++) {
            uint4 k4 = *(uint4*)&skey[(tid + i * 256) * 4];
            kk[i * 4 + 0] = k4.x; kk[i * 4 + 1] = k4.y;
            kk[i * 4 + 2] = k4.z; kk[i * 4 + 3] = k4.w;
        }
#pragma unroll
        for (int i = 0; i < 16; i++) my += (kk[i] > thrKey) ? 1u : 0u;
        unsigned pre = my;
#pragma unroll
        for (int o = 1; o < 32; o <<= 1) {
            unsigned tt = __shfl_up_sync(0xffffffffu, pre, o);
            if (lane >= o) pre += tt;
        }
        unsigned wtot = __shfl_sync(0xffffffffu, pre, 31);
        unsigned wbase = 0;
        if (lane == 31 && wtot > 0) wbase = atomicAdd(&s_cnt, wtot);
        wbase = __shfl_sync(0xffffffffu, wbase, 31);
        unsigned pos = wbase + pre - my;
        if (my > 0) {
#pragma unroll
            for (int i = 0; i < 16; i++) {
                if (kk[i] > thrKey) {
                    if (pos < 256) {
                        unsigned idx = (unsigned)((tid + (i >> 2) * 256) * 4 + (i & 3));
                        cand[pos] = ((u64)kk[i] << 12) | (u64)(4095u - idx);
                    }
                    pos++;
                }
            }
        }
    }
    __syncthreads();

    if (tiePath) {
        int lastIdx = -1;
        for (int e = cnt; e < KSEL; e++) {
            int best = 0x7FFFFFFF;
#pragma unroll
            for (int i = 0; i < 4; i++) {
                uint4 k4 = *(uint4*)&skey[(tid + i * 256) * 4];
                unsigned ka[4] = {k4.x, k4.y, k4.z, k4.w};
#pragma unroll
                for (int j = 0; j < 4; j++) {
                    int idx = (tid + i * 256) * 4 + j;
                    if (ka[j] == Tkey && idx > lastIdx && idx < best) best = idx;
                }
            }
            best = warpReduceMinI(best);
            __syncthreads();
            if (lane == 0) ired[wid] = best;
            __syncthreads();
            if (tid == 0) {
                int bb = ired[0];
#pragma unroll
                for (int i = 1; i < 8; i++) bb = (ired[i] < bb) ? ired[i] : bb;
                s_best = bb;
                cand[e] = ((u64)Tkey << 12) | (u64)(4095u - (unsigned)bb);
            }
            __syncthreads();
            lastIdx = s_best;
        }
        cnt = KSEL;
        __syncthreads();
    }

    // ---- exact refine: one THREAD per candidate, bias-first, k-serial fmaf
    //      (bit-matches the R1 arithmetic that passed at rel_err 4e-6) ----
    const int ncand = (cnt < 256) ? cnt : 256;
    if (tid < ncand) {
        unsigned idxv = 4095u - (unsigned)(cand[tid] & 0xFFFull);
        const float4* wv = (const float4*)(g_wsT + (size_t)idxv * RDIM);
        float acc = __ldg(bsg + idxv);
#pragma unroll
        for (int q = 0; q < 32; q++) {
            float4 w4 = __ldg(wv + q);
            float4 h4 = *(const float4*)&hrow[q * 4];
            acc = fmaf(h4.x, w4.x, acc);
            acc = fmaf(h4.y, w4.y, acc);
            acc = fmaf(h4.z, w4.z, acc);
            acc = fmaf(h4.w, w4.w, acc);
        }
        unsigned b = __float_as_uint(acc);
        unsigned k = b ^ ((unsigned)((int)b >> 31) | 0x80000000u);
        cand[tid] = ((u64)k << 12) | (u64)(4095u - idxv);
    }
    __syncthreads();

    // warp 0: exact top-32 extraction + outputs
    if (wid == 0) {
        u64 cl[8];
#pragma unroll
        for (int q = 0; q < 8; q++) {
            int p = lane + 32 * q;
            cl[q] = (p < ncand) ? cand[p] : 0ull;
        }
#pragma unroll
        for (int a = 1; a < 8; a++)
#pragma unroll
            for (int b2 = a; b2 > 0; b2--) {
                u64 lo = cl[b2 - 1] < cl[b2] ? cl[b2 - 1] : cl[b2];
                u64 hi = cl[b2 - 1] < cl[b2] ? cl[b2] : cl[b2 - 1];
                cl[b2 - 1] = hi; cl[b2] = lo;
            }
        u64 mysel = 0;
#pragma unroll
        for (int r2 = 0; r2 < MAXK; r2++) {
            u64 wb = warpReduceMaxU64(cl[0]);
            if (cl[0] == wb) {
#pragma unroll
                for (int q = 0; q < 7; q++) cl[q] = cl[q + 1];
                cl[7] = 0ull;
            }
            if (lane == r2) mysel = wb;
        }

        unsigned keyv = (unsigned)(mysel >> 12);
        unsigned idxv = 4095u - (unsigned)(mysel & 0xFFFull);
        unsigned fb = (keyv & 0x80000000u) ? (keyv ^ 0x80000000u) : ~keyv;
        float val = __uint_as_float(fb);

        int b = g_budget[t];
        float v0 = __shfl_sync(0xffffffffu, val, 0);
        bool msk = lane < b;
        float ev = msk ? __expf(val - v0) : 0.f;
        float zz = warpReduceSumF(ev);
        float w = msk ? ev / zz : 0.f;

        out_idx[(size_t)t * MAXK + lane] = (float)idxv;
        out_w[(size_t)t * MAXK + lane] = w;
        if (msk) atomicAdd(&g_counts[idxv], 1.0f);
    }
}

// ---------------- K4: aux (approx scores) ----------------
__global__ __launch_bounds__(256) void k_aux()
{
    __shared__ float sredZ[8], sredD[8], s_m;
    const int t = blockIdx.x;
    const int tid = threadIdx.x, lane = tid & 31, wid = tid >> 5;
    const float* row = g_scores + (size_t)t * NSLOT;

    float4 r[4];
#pragma unroll
    for (int i = 0; i < 4; i++) r[i] = *(const float4*)(row + (size_t)(tid + i * 256) * 4);

    float m = r[0].x;
#pragma unroll
    for (int i = 0; i < 4; i++) {
        m = fmaxf(m, r[i].x); m = fmaxf(m, r[i].y);
        m = fmaxf(m, r[i].z); m = fmaxf(m, r[i].w);
    }
    m = warpReduceMaxF(m);
    if (lane == 0) sredZ[wid] = m;
    __syncthreads();
    if (tid == 0) {
        float mm = sredZ[0];
#pragma unroll
        for (int i = 1; i < 8; i++) mm = fmaxf(mm, sredZ[i]);
        s_m = mm;
    }
    __syncthreads();
    m = s_m;

    float z = 0.f, d = 0.f;
#pragma unroll
    for (int i = 0; i < 4; i++) {
        float4 c = g_counts_v[tid + i * 256];
        float e0 = __expf(r[i].x - m), e1 = __expf(r[i].y - m);
        float e2 = __expf(r[i].z - m), e3 = __expf(r[i].w - m);
        z += e0 + e1 + e2 + e3;
        d += e0 * c.x + e1 * c.y + e2 * c.z + e3 * c.w;
    }
    z = warpReduceSumF(z);
    d = warpReduceSumF(d);
    if (lane == 0) { sredZ[wid] = z; sredD[wid] = d; }
    __syncthreads();
    if (tid == 0) {
        float zz = 0.f, dd = 0.f;
#pragma unroll
        for (int i = 0; i < 8; i++) { zz += sredZ[i]; dd += sredD[i]; }
        float contrib = (dd / zz) * ((float)NSLOT / ((float)TOK * (float)TOK));
        atomicAdd(&g_aux, contrib);
    }
}

// ---------------- K5 ----------------
__global__ void k_finish(float* __restrict__ out_aux)
{
    if (threadIdx.x == 0) out_aux[0] = g_aux;
}

// ---------------- launch ----------------
extern "C" void kernel_launch(void* const* d_in, const int* in_sizes, int n_in,
                              void* d_out, int out_size)
{
    const float* x  = (const float*)d_in[0];
    const float* Wc = (const float*)d_in[1];
    const float* bc = (const float*)d_in[2];
    const float* Wh = (const float*)d_in[3];
    const float* bh = (const float*)d_in[4];
    const float* Ws = (const float*)d_in[5];
    const float* bs = (const float*)d_in[6];

    float* out     = (float*)d_out;
    float* out_idx = out;
    float* out_w   = out + TOK * MAXK;
    float* out_b   = out + 2 * TOK * MAXK;
    float* out_aux = out + 2 * TOK * MAXK + TOK;

    cudaFuncSetAttribute(k_scores_mma, cudaFuncAttributeMaxDynamicSharedMemorySize, SM2_TOTAL);

    k_init<<<(NSLOT + 255) / 256, 256>>>();
    k_transpose<<<dim3(128, 4), 256>>>(Ws);
    k_hidden<<<TOK / 128, 256>>>(x, Wc, bc, Wh, bh, out_b);
    k_scores_mma<<<TOK / 128, 256, SM2_TOTAL>>>(Ws, bs);
    k_topk<<<TOK, 256>>>(out_idx, out_w, bs);
    k_aux<<<TOK, 256>>>();
    k_finish<<<1, 32>>>(out_aux);
}

// round 11
// speedup vs baseline: 1.3846x; 1.0105x over previous
#include <cuda_runtime.h>
#include <cstdint>

#define TOK   32768
#define DIN   1024
#define RDIM  128
#define NSLOT 4096
#define MAXK  32
#define KSEL  48

typedef unsigned long long u64;

// ---------------- scratch ----------------
__device__ float  g_hidden[TOK * RDIM];
__device__ float4 g_scores_v[TOK * NSLOT / 4];     // 512 MB (approx scores)
__device__ float  g_wsT[NSLOT * RDIM];             // 2 MB W_s transposed
__device__ int    g_budget[TOK];
__device__ float4 g_counts_v[NSLOT / 4];
__device__ float  g_aux;

#define g_scores ((float*)g_scores_v)
#define g_counts ((float*)g_counts_v)

// ---------------- tf32 ----------------
__device__ __forceinline__ float to_tf32(float v) {
    unsigned h;
    asm("cvt.rna.tf32.f32 %0, %1;" : "=r"(h) : "f"(v));
    return __uint_as_float(h);
}

#define MMA_TF32(c, a, b) \
    asm volatile("mma.sync.aligned.m16n8k8.row.col.f32.tf32.tf32.f32 " \
        "{%0,%1,%2,%3}, {%4,%5,%6,%7}, {%8,%9}, {%0,%1,%2,%3};" \
        : "+f"((c)[0]), "+f"((c)[1]), "+f"((c)[2]), "+f"((c)[3]) \
        : "r"(__float_as_uint((a).x)), "r"(__float_as_uint((a).y)), \
          "r"(__float_as_uint((a).z)), "r"(__float_as_uint((a).w)), \
          "r"(__float_as_uint((b).x)), "r"(__float_as_uint((b).y)))

// smem layout for k_scores_mma (bytes): A 64K + B 32K = 96K -> 2 CTAs/SM
#define SM2_A     0
#define SM2_B     65536
#define SM2_TOTAL 98304

// ---------------- reductions ----------------
__device__ __forceinline__ float warpReduceMaxF(float v) {
#pragma unroll
    for (int o = 16; o > 0; o >>= 1) v = fmaxf(v, __shfl_xor_sync(0xffffffffu, v, o));
    return v;
}
__device__ __forceinline__ float warpReduceSumF(float v) {
#pragma unroll
    for (int o = 16; o > 0; o >>= 1) v += __shfl_xor_sync(0xffffffffu, v, o);
    return v;
}
__device__ __forceinline__ int warpReduceSumI(int v) {
#pragma unroll
    for (int o = 16; o > 0; o >>= 1) v += __shfl_xor_sync(0xffffffffu, v, o);
    return v;
}
__device__ __forceinline__ int warpReduceMinI(int v) {
#pragma unroll
    for (int o = 16; o > 0; o >>= 1) {
        int t = __shfl_xor_sync(0xffffffffu, v, o);
        v = (t < v) ? t : v;
    }
    return v;
}
__device__ __forceinline__ u64 warpReduceMaxU64(u64 v) {
#pragma unroll
    for (int o = 16; o > 0; o >>= 1) {
        u64 t = __shfl_xor_sync(0xffffffffu, v, o);
        v = (t > v) ? t : v;
    }
    return v;
}

// ---------------- K0 ----------------
__global__ void k_init() {
    int i = blockIdx.x * blockDim.x + threadIdx.x;
    if (i < NSLOT) g_counts[i] = 0.f;
    if (i == 0)    g_aux = 0.f;
}

// ---------------- K0b: transpose W_s -> g_wsT[N][R] ----------------
__global__ __launch_bounds__(256) void k_transpose(const float* __restrict__ Wsg) {
    __shared__ float tile[32][33];
    const int bx = blockIdx.x;
    const int by = blockIdx.y;
    const int tx = threadIdx.x & 31, ty = threadIdx.x >> 5;
#pragma unroll
    for (int i = 0; i < 4; i++) {
        int r = by * 32 + ty + i * 8;
        tile[ty + i * 8][tx] = Wsg[(size_t)r * NSLOT + bx * 32 + tx];
    }
    __syncthreads();
#pragma unroll
    for (int i = 0; i < 4; i++) {
        int n = bx * 32 + ty + i * 8;
        g_wsT[(size_t)n * RDIM + by * 32 + tx] = tile[tx][ty + i * 8];
    }
}

// ---------------- K1: hidden GEMM + budget (unchanged) ----------------
__global__ __launch_bounds__(256) void k_hidden(
    const float* __restrict__ x,  const float* __restrict__ Wc, const float* __restrict__ bc,
    const float* __restrict__ Wh, const float* __restrict__ bh, float* __restrict__ out_b)
{
    __shared__ float Xs[32][132];
    __shared__ float Wsm[32][128];
    __shared__ float Wcs[32];

    const int tid = threadIdx.x;
    const int tx = tid & 15, ty = tid >> 4;
    const int t0 = blockIdx.x * 128;

    float acc[8][8];
#pragma unroll
    for (int j = 0; j < 8; j++) {
        int c = (j < 4) ? tx * 4 + j : 64 + tx * 4 + (j - 4);
        float b = bh[c];
#pragma unroll
        for (int i = 0; i < 8; i++) acc[i][j] = b;
    }
    float cacc = 0.f;

    for (int kt = 0; kt < 32; kt++) {
#pragma unroll
        for (int i = 0; i < 4; i++) {
            int id = tid + i * 256;
            int token = id >> 3, kg = id & 7;
            float4 f = *(const float4*)(x + (size_t)(t0 + token) * DIN + kt * 32 + kg * 4);
            Xs[kg * 4 + 0][token] = f.x; Xs[kg * 4 + 1][token] = f.y;
            Xs[kg * 4 + 2][token] = f.z; Xs[kg * 4 + 3][token] = f.w;
        }
#pragma unroll
        for (int i = 0; i < 4; i++) {
            int id = tid + i * 256;
            int rowk = id >> 5, ng = id & 31;
            *(float4*)&Wsm[rowk][ng * 4] =
                *(const float4*)(Wh + (size_t)(kt * 32 + rowk) * RDIM + ng * 4);
        }
        if (tid < 32) Wcs[tid] = Wc[kt * 32 + tid];
        __syncthreads();

#pragma unroll
        for (int k = 0; k < 32; k++) {
            float4 a0 = *(float4*)&Xs[k][ty * 4];
            float4 a1 = *(float4*)&Xs[k][64 + ty * 4];
            float4 b0 = *(float4*)&Wsm[k][tx * 4];
            float4 b1 = *(float4*)&Wsm[k][64 + tx * 4];
            float xf[8] = {a0.x, a0.y, a0.z, a0.w, a1.x, a1.y, a1.z, a1.w};
            float wf[8] = {b0.x, b0.y, b0.z, b0.w, b1.x, b1.y, b1.z, b1.w};
#pragma unroll
            for (int i = 0; i < 8; i++)
#pragma unroll
                for (int j = 0; j < 8; j++)
                    acc[i][j] += xf[i] * wf[j];
        }
        if (tid < 128) {
            float s = 0.f;
#pragma unroll
            for (int k = 0; k < 32; k++) s += Xs[k][tid] * Wcs[k];
            cacc += s;
        }
        __syncthreads();
    }

#pragma unroll
    for (int i = 0; i < 8; i++) {
        int r = (i < 4) ? ty * 4 + i : 64 + ty * 4 + (i - 4);
        float4 o0 = make_float4(fmaxf(acc[i][0], 0.f), fmaxf(acc[i][1], 0.f),
                                fmaxf(acc[i][2], 0.f), fmaxf(acc[i][3], 0.f));
        float4 o1 = make_float4(fmaxf(acc[i][4], 0.f), fmaxf(acc[i][5], 0.f),
                                fmaxf(acc[i][6], 0.f), fmaxf(acc[i][7], 0.f));
        *(float4*)(g_hidden + (size_t)(t0 + r) * RDIM + tx * 4) = o0;
        *(float4*)(g_hidden + (size_t)(t0 + r) * RDIM + 64 + tx * 4) = o1;
    }
    if (tid < 128) {
        float zc = cacc + bc[0];
        float c = 1.f / (1.f + expf(-zc));
        float bf = 4.f + 28.f * c * c;
        int b = (int)floorf(bf);
        g_budget[t0 + tid] = b;
        out_b[t0 + tid] = (float)b;
    }
}

// ---------------- K2: approx scores via tf32 mma.sync, 2 CTA/SM + B reg-prefetch ----------------
__device__ __forceinline__ void storeB_frag(float* sB, const float4* pre, int tid) {
#pragma unroll
    for (int i = 0; i < 8; i++) {
        int id = tid + i * 256;
        int k = id >> 4, ng = id & 15;
        float hv[4] = {to_tf32(pre[i].x), to_tf32(pre[i].y),
                       to_tf32(pre[i].z), to_tf32(pre[i].w)};
        int kc = k >> 3, k8 = k & 7;
        int r = (k8 >> 2) & 1, tg = k8 & 3;
#pragma unroll
        for (int j = 0; j < 4; j++) {
            int n = ng * 4 + j;
            sB[(((kc * 8 + (n >> 3)) * 32 + ((n & 7) * 4 + tg)) * 2) + r] = hv[j];
        }
    }
}

__global__ __launch_bounds__(256, 2) void k_scores_mma(const float* __restrict__ Wsg,
                                                       const float* __restrict__ bs)
{
    extern __shared__ char smem[];
    float* sA = (float*)(smem + SM2_A);
    float* sB = (float*)(smem + SM2_B);
    const float4* sA4 = (const float4*)sA;
    const float2* sB2 = (const float2*)sB;

    const int tid = threadIdx.x;
    const int lane = tid & 31, wid = tid >> 5;
    const int warpM = wid & 3, warpN = wid >> 2;
    const int gid = lane >> 2, tig = lane & 3;
    const int t0 = blockIdx.x * 128;

    // stage A: hidden[128][128] tf32 in fragment order
#pragma unroll
    for (int i = 0; i < 16; i++) {
        int id = tid + i * 256;
        int m = id >> 5, fg = id & 31;
        float4 v = *(const float4*)(g_hidden + (size_t)(t0 + m) * RDIM + fg * 4);
        float hv[4] = {to_tf32(v.x), to_tf32(v.y), to_tf32(v.z), to_tf32(v.w)};
        int mt = m >> 4, rr = m & 15;
#pragma unroll
        for (int j = 0; j < 4; j++) {
            int k = fg * 4 + j;
            int kc = k >> 3, c4 = k & 7;
            int reg = ((rr >> 3) & 1) | (((c4 >> 2) & 1) << 1);
            int ln = (rr & 7) * 4 + (c4 & 3);
            sA[((mt * 16 + kc) * 32 + ln) * 4 + reg] = hv[j];
        }
    }

    // prologue: stage B tile 0
    {
        float4 pre[8];
#pragma unroll
        for (int i = 0; i < 8; i++) {
            int id = tid + i * 256;
            int k = id >> 4, ng = id & 15;
            pre[i] = *(const float4*)(Wsg + (size_t)k * NSLOT + ng * 4);
        }
        storeB_frag(sB, pre, tid);
    }
    __syncthreads();

    for (int nt = 0; nt < 64; nt++) {
        const int nbase = nt * 64;

        // prefetch next B tile into registers (overlaps with MMA below)
        float4 pre[8];
        if (nt < 63) {
#pragma unroll
            for (int i = 0; i < 8; i++) {
                int id = tid + i * 256;
                int k = id >> 4, ng = id & 15;
                pre[i] = *(const float4*)(Wsg + (size_t)k * NSLOT + nbase + 64 + ng * 4);
            }
        }

        float c[2][4][4];
#pragma unroll
        for (int mi = 0; mi < 2; mi++)
#pragma unroll
            for (int ni = 0; ni < 4; ni++)
#pragma unroll
                for (int q = 0; q < 4; q++) c[mi][ni][q] = 0.f;

#pragma unroll 4
        for (int kc = 0; kc < 16; kc++) {
            float4 ah[2];
            float2 bh[4];
#pragma unroll
            for (int mi = 0; mi < 2; mi++) {
                int mt = warpM * 2 + mi;
                ah[mi] = sA4[(mt * 16 + kc) * 32 + lane];
            }
#pragma unroll
            for (int ni = 0; ni < 4; ni++) {
                int nt8 = warpN * 4 + ni;
                bh[ni] = sB2[(kc * 8 + nt8) * 32 + lane];
            }
#pragma unroll
            for (int mi = 0; mi < 2; mi++)
#pragma unroll
                for (int ni = 0; ni < 4; ni++)
                    MMA_TF32(c[mi][ni], ah[mi], bh[ni]);
        }

        // epilogue: bias (L2) + store approx scores
#pragma unroll
        for (int mi = 0; mi < 2; mi++) {
            int row = t0 + warpM * 32 + mi * 16 + gid;
#pragma unroll
            for (int ni = 0; ni < 4; ni++) {
                int col = nbase + warpN * 32 + ni * 8 + tig * 2;
                float b0 = __ldg(bs + col), b1 = __ldg(bs + col + 1);
                *(float2*)(g_scores + (size_t)row * NSLOT + col) =
                    make_float2(c[mi][ni][0] + b0, c[mi][ni][1] + b1);
                *(float2*)(g_scores + (size_t)(row + 8) * NSLOT + col) =
                    make_float2(c[mi][ni][2] + b0, c[mi][ni][3] + b1);
            }
        }

        __syncthreads();                 // everyone done reading sB(nt)
        if (nt < 63) storeB_frag(sB, pre, tid);
        __syncthreads();                 // sB(nt+1) visible
    }
}

// ---------------- K3: candidates from approx scores + R1-arithmetic exact refine ----------------
__global__ __launch_bounds__(256) void k_topk(float* __restrict__ out_idx,
                                              float* __restrict__ out_w,
                                              const float* __restrict__ bsg)
{
    __shared__ unsigned skey[4096];
    __shared__ u64      cand[256];
    __shared__ float    hrow[128];
    __shared__ float    fred[8], f2red[8];
    __shared__ int      ired[8];
    __shared__ unsigned s_cnt;
    __shared__ int      s_best;

    const int t = blockIdx.x;
    const int tid = threadIdx.x, lane = tid & 31, wid = tid >> 5;
    const float4* rowv = (const float4*)(g_scores + (size_t)t * NSLOT);

    if (tid < 32)
        *(float4*)&hrow[tid * 4] = *(const float4*)(g_hidden + (size_t)t * RDIM + tid * 4);

    float s = 0.f, s2 = 0.f;
#pragma unroll
    for (int i = 0; i < 4; i++) {
        int e4 = tid + i * 256;
        float4 f = rowv[e4];
        float vv[4] = {f.x, f.y, f.z, f.w};
        unsigned kk[4];
#pragma unroll
        for (int j = 0; j < 4; j++) {
            s += vv[j]; s2 += vv[j] * vv[j];
            unsigned b = __float_as_uint(vv[j]);
            kk[j] = b ^ ((unsigned)((int)b >> 31) | 0x80000000u);
        }
        *(uint4*)&skey[e4 * 4] = make_uint4(kk[0], kk[1], kk[2], kk[3]);
    }
    s = warpReduceSumF(s);
    s2 = warpReduceSumF(s2);
    if (lane == 0) { fred[wid] = s; f2red[wid] = s2; }
    __syncthreads();
    float ss = 0.f, ss2 = 0.f;
#pragma unroll
    for (int i = 0; i < 8; i++) { ss += fred[i]; ss2 += f2red[i]; }
    const float mean = ss * (1.f / NSLOT);
    const float sigma = sqrtf(fmaxf(ss2 * (1.f / NSLOT) - mean * mean, 0.f)) + 1e-20f;

    auto countGreater = [&](unsigned thrKey) -> int {
        int c = 0;
#pragma unroll
        for (int i = 0; i < 4; i++) {
            uint4 k4 = *(uint4*)&skey[(tid + i * 256) * 4];
            c += (k4.x > thrKey) + (k4.y > thrKey) + (k4.z > thrKey) + (k4.w > thrKey);
        }
        c = warpReduceSumI(c);
        __syncthreads();
        if (lane == 0) ired[wid] = c;
        __syncthreads();
        int tot = 0;
#pragma unroll
        for (int i = 0; i < 8; i++) tot += ired[i];
        return tot;
    };

    unsigned thrKey = 0;
    int cnt = 0;
    bool ok = false;
    float zf = 2.2f;
    for (int a = 0; a < 4; a++) {
        float thr = mean + zf * sigma;
        unsigned tb = __float_as_uint(thr);
        unsigned tk = tb ^ ((unsigned)((int)tb >> 31) | 0x80000000u);
        int c = countGreater(tk);
        if (c >= KSEL && c <= 256) { thrKey = tk; cnt = c; ok = true; break; }
        zf += (c < KSEL) ? -0.6f : 0.45f;
    }

    bool tiePath = false;
    unsigned Tkey = 0;
    if (!ok) {
        unsigned K = 0;
        for (int bit = 31; bit >= 0; bit--) {
            unsigned trial = K | (1u << bit);
            if (countGreater(trial) >= KSEL) K = trial;
        }
        int c = countGreater(K);
        if (c <= 256) {
            thrKey = K; cnt = c; ok = true;
        } else {
            tiePath = true;
            Tkey = K + 1u;
            thrKey = Tkey;
            cnt = countGreater(Tkey);
        }
    }

    if (tid == 0) s_cnt = 0;
    __syncthreads();
    {
        unsigned kk[16];
        unsigned my = 0;
#pragma unroll
        for (int i = 0; i < 4; i++) {
            uint4 k4 = *(uint4*)&skey[(tid + i * 256) * 4];
            kk[i * 4 + 0] = k4.x; kk[i * 4 + 1] = k4.y;
            kk[i * 4 + 2] = k4.z; kk[i * 4 + 3] = k4.w;
        }
#pragma unroll
        for (int i = 0; i < 16; i++) my += (kk[i] > thrKey) ? 1u : 0u;
        unsigned pre = my;
#pragma unroll
        for (int o = 1; o < 32; o <<= 1) {
            unsigned tt = __shfl_up_sync(0xffffffffu, pre, o);
            if (lane >= o) pre += tt;
        }
        unsigned wtot = __shfl_sync(0xffffffffu, pre, 31);
        unsigned wbase = 0;
        if (lane == 31 && wtot > 0) wbase = atomicAdd(&s_cnt, wtot);
        wbase = __shfl_sync(0xffffffffu, wbase, 31);
        unsigned pos = wbase + pre - my;
        if (my > 0) {
#pragma unroll
            for (int i = 0; i < 16; i++) {
                if (kk[i] > thrKey) {
                    if (pos < 256) {
                        unsigned idx = (unsigned)((tid + (i >> 2) * 256) * 4 + (i & 3));
                        cand[pos] = ((u64)kk[i] << 12) | (u64)(4095u - idx);
                    }
                    pos++;
                }
            }
        }
    }
    __syncthreads();

    if (tiePath) {
        int lastIdx = -1;
        for (int e = cnt; e < KSEL; e++) {
            int best = 0x7FFFFFFF;
#pragma unroll
            for (int i = 0; i < 4; i++) {
                uint4 k4 = *(uint4*)&skey[(tid + i * 256) * 4];
                unsigned ka[4] = {k4.x, k4.y, k4.z, k4.w};
#pragma unroll
                for (int j = 0; j < 4; j++) {
                    int idx = (tid + i * 256) * 4 + j;
                    if (ka[j] == Tkey && idx > lastIdx && idx < best) best = idx;
                }
            }
            best = warpReduceMinI(best);
            __syncthreads();
            if (lane == 0) ired[wid] = best;
            __syncthreads();
            if (tid == 0) {
                int bb = ired[0];
#pragma unroll
                for (int i = 1; i < 8; i++) bb = (ired[i] < bb) ? ired[i] : bb;
                s_best = bb;
                cand[e] = ((u64)Tkey << 12) | (u64)(4095u - (unsigned)bb);
            }
            __syncthreads();
            lastIdx = s_best;
        }
        cnt = KSEL;
        __syncthreads();
    }

    // ---- exact refine: one THREAD per candidate, bias-first, k-serial fmaf
    //      (bit-matches the R1 arithmetic that passed at rel_err 4e-6) ----
    const int ncand = (cnt < 256) ? cnt : 256;
    if (tid < ncand) {
        unsigned idxv = 4095u - (unsigned)(cand[tid] & 0xFFFull);
        const float4* wv = (const float4*)(g_wsT + (size_t)idxv * RDIM);
        float acc = __ldg(bsg + idxv);
#pragma unroll
        for (int q = 0; q < 32; q++) {
            float4 w4 = __ldg(wv + q);
            float4 h4 = *(const float4*)&hrow[q * 4];
            acc = fmaf(h4.x, w4.x, acc);
            acc = fmaf(h4.y, w4.y, acc);
            acc = fmaf(h4.z, w4.z, acc);
            acc = fmaf(h4.w, w4.w, acc);
        }
        unsigned b = __float_as_uint(acc);
        unsigned k = b ^ ((unsigned)((int)b >> 31) | 0x80000000u);
        cand[tid] = ((u64)k << 12) | (u64)(4095u - idxv);
    }
    __syncthreads();

    // warp 0: exact top-32 extraction + outputs
    if (wid == 0) {
        u64 cl[8];
#pragma unroll
        for (int q = 0; q < 8; q++) {
            int p = lane + 32 * q;
            cl[q] = (p < ncand) ? cand[p] : 0ull;
        }
#pragma unroll
        for (int a = 1; a < 8; a++)
#pragma unroll
            for (int b2 = a; b2 > 0; b2--) {
                u64 lo = cl[b2 - 1] < cl[b2] ? cl[b2 - 1] : cl[b2];
                u64 hi = cl[b2 - 1] < cl[b2] ? cl[b2] : cl[b2 - 1];
                cl[b2 - 1] = hi; cl[b2] = lo;
            }
        u64 mysel = 0;
#pragma unroll
        for (int r2 = 0; r2 < MAXK; r2++) {
            u64 wb = warpReduceMaxU64(cl[0]);
            if (cl[0] == wb) {
#pragma unroll
                for (int q = 0; q < 7; q++) cl[q] = cl[q + 1];
                cl[7] = 0ull;
            }
            if (lane == r2) mysel = wb;
        }

        unsigned keyv = (unsigned)(mysel >> 12);
        unsigned idxv = 4095u - (unsigned)(mysel & 0xFFFull);
        unsigned fb = (keyv & 0x80000000u) ? (keyv ^ 0x80000000u) : ~keyv;
        float val = __uint_as_float(fb);

        int b = g_budget[t];
        float v0 = __shfl_sync(0xffffffffu, val, 0);
        bool msk = lane < b;
        float ev = msk ? __expf(val - v0) : 0.f;
        float zz = warpReduceSumF(ev);
        float w = msk ? ev / zz : 0.f;

        out_idx[(size_t)t * MAXK + lane] = (float)idxv;
        out_w[(size_t)t * MAXK + lane] = w;
        if (msk) atomicAdd(&g_counts[idxv], 1.0f);
    }
}

// ---------------- K4: aux (approx scores) ----------------
__global__ __launch_bounds__(256) void k_aux()
{
    __shared__ float sredZ[8], sredD[8], s_m;
    const int t = blockIdx.x;
    const int tid = threadIdx.x, lane = tid & 31, wid = tid >> 5;
    const float* row = g_scores + (size_t)t * NSLOT;

    float4 r[4];
#pragma unroll
    for (int i = 0; i < 4; i++) r[i] = *(const float4*)(row + (size_t)(tid + i * 256) * 4);

    float m = r[0].x;
#pragma unroll
    for (int i = 0; i < 4; i++) {
        m = fmaxf(m, r[i].x); m = fmaxf(m, r[i].y);
        m = fmaxf(m, r[i].z); m = fmaxf(m, r[i].w);
    }
    m = warpReduceMaxF(m);
    if (lane == 0) sredZ[wid] = m;
    __syncthreads();
    if (tid == 0) {
        float mm = sredZ[0];
#pragma unroll
        for (int i = 1; i < 8; i++) mm = fmaxf(mm, sredZ[i]);
        s_m = mm;
    }
    __syncthreads();
    m = s_m;

    float z = 0.f, d = 0.f;
#pragma unroll
    for (int i = 0; i < 4; i++) {
        float4 c = g_counts_v[tid + i * 256];
        float e0 = __expf(r[i].x - m), e1 = __expf(r[i].y - m);
        float e2 = __expf(r[i].z - m), e3 = __expf(r[i].w - m);
        z += e0 + e1 + e2 + e3;
        d += e0 * c.x + e1 * c.y + e2 * c.z + e3 * c.w;
    }
    z = warpReduceSumF(z);
    d = warpReduceSumF(d);
    if (lane == 0) { sredZ[wid] = z; sredD[wid] = d; }
    __syncthreads();
    if (tid == 0) {
        float zz = 0.f, dd = 0.f;
#pragma unroll
        for (int i = 0; i < 8; i++) { zz += sredZ[i]; dd += sredD[i]; }
        float contrib = (dd / zz) * ((float)NSLOT / ((float)TOK * (float)TOK));
        atomicAdd(&g_aux, contrib);
    }
}

// ---------------- K5 ----------------
__global__ void k_finish(float* __restrict__ out_aux)
{
    if (threadIdx.x == 0) out_aux[0] = g_aux;
}

// ---------------- launch ----------------
extern "C" void kernel_launch(void* const* d_in, const int* in_sizes, int n_in,
                              void* d_out, int out_size)
{
    const float* x  = (const float*)d_in[0];
    const float* Wc = (const float*)d_in[1];
    const float* bc = (const float*)d_in[2];
    const float* Wh = (const float*)d_in[3];
    const float* bh = (const float*)d_in[4];
    const float* Ws = (const float*)d_in[5];
    const float* bs = (const float*)d_in[6];

    float* out     = (float*)d_out;
    float* out_idx = out;
    float* out_w   = out + TOK * MAXK;
    float* out_b   = out + 2 * TOK * MAXK;
    float* out_aux = out + 2 * TOK * MAXK + TOK;

    cudaFuncSetAttribute(k_scores_mma, cudaFuncAttributeMaxDynamicSharedMemorySize, SM2_TOTAL);

    k_init<<<(NSLOT + 255) / 256, 256>>>();
    k_transpose<<<dim3(128, 4), 256>>>(Ws);
    k_hidden<<<TOK / 128, 256>>>(x, Wc, bc, Wh, bh, out_b);
    k_scores_mma<<<TOK / 128, 256, SM2_TOTAL>>>(Ws, bs);
    k_topk<<<TOK, 256>>>(out_idx, out_w, bs);
    k_aux<<<TOK, 256>>>();
    k_finish<<<1, 32>>>(out_aux);
}

// round 12
// speedup vs baseline: 1.6636x; 1.2015x over previous
#include <cuda_runtime.h>
#include <cstdint>

#define TOK   32768
#define DIN   1024
#define RDIM  128
#define NSLOT 4096
#define MAXK  32
#define KSEL  48

typedef unsigned long long u64;

// ---------------- scratch ----------------
__device__ float  g_hidden[TOK * RDIM];
__device__ float4 g_scores_v[TOK * NSLOT / 4];     // 512 MB (approx scores)
__device__ float  g_wsT[NSLOT * RDIM];             // 2 MB W_s transposed
__device__ int    g_budget[TOK];
__device__ float4 g_counts_v[NSLOT / 4];
__device__ float  g_aux;

#define g_scores ((float*)g_scores_v)
#define g_counts ((float*)g_counts_v)

// ---------------- tf32 ----------------
__device__ __forceinline__ float to_tf32(float v) {
    unsigned h;
    asm("cvt.rna.tf32.f32 %0, %1;" : "=r"(h) : "f"(v));
    return __uint_as_float(h);
}

#define MMA_TF32(c, a, b) \
    asm volatile("mma.sync.aligned.m16n8k8.row.col.f32.tf32.tf32.f32 " \
        "{%0,%1,%2,%3}, {%4,%5,%6,%7}, {%8,%9}, {%0,%1,%2,%3};" \
        : "+f"((c)[0]), "+f"((c)[1]), "+f"((c)[2]), "+f"((c)[3]) \
        : "r"(__float_as_uint((a).x)), "r"(__float_as_uint((a).y)), \
          "r"(__float_as_uint((a).z)), "r"(__float_as_uint((a).w)), \
          "r"(__float_as_uint((b).x)), "r"(__float_as_uint((b).y)))

// smem layout for k_scores_mma (bytes):
//   sA frag-order 64K, sB row-major [128][72] = 36864  -> 100K, 2 CTAs/SM
#define BSTRIDE   72
#define SM2_A     0
#define SM2_B     65536
#define SM2_TOTAL (65536 + 128 * BSTRIDE * 4)

// ---------------- reductions ----------------
__device__ __forceinline__ float warpReduceMaxF(float v) {
#pragma unroll
    for (int o = 16; o > 0; o >>= 1) v = fmaxf(v, __shfl_xor_sync(0xffffffffu, v, o));
    return v;
}
__device__ __forceinline__ float warpReduceSumF(float v) {
#pragma unroll
    for (int o = 16; o > 0; o >>= 1) v += __shfl_xor_sync(0xffffffffu, v, o);
    return v;
}
__device__ __forceinline__ int warpReduceSumI(int v) {
#pragma unroll
    for (int o = 16; o > 0; o >>= 1) v += __shfl_xor_sync(0xffffffffu, v, o);
    return v;
}
__device__ __forceinline__ int warpReduceMinI(int v) {
#pragma unroll
    for (int o = 16; o > 0; o >>= 1) {
        int t = __shfl_xor_sync(0xffffffffu, v, o);
        v = (t < v) ? t : v;
    }
    return v;
}
__device__ __forceinline__ u64 warpReduceMaxU64(u64 v) {
#pragma unroll
    for (int o = 16; o > 0; o >>= 1) {
        u64 t = __shfl_xor_sync(0xffffffffu, v, o);
        v = (t > v) ? t : v;
    }
    return v;
}

// ---------------- K0 ----------------
__global__ void k_init() {
    int i = blockIdx.x * blockDim.x + threadIdx.x;
    if (i < NSLOT) g_counts[i] = 0.f;
    if (i == 0)    g_aux = 0.f;
}

// ---------------- K0b: transpose W_s -> g_wsT[N][R] ----------------
__global__ __launch_bounds__(256) void k_transpose(const float* __restrict__ Wsg) {
    __shared__ float tile[32][33];
    const int bx = blockIdx.x;
    const int by = blockIdx.y;
    const int tx = threadIdx.x & 31, ty = threadIdx.x >> 5;
#pragma unroll
    for (int i = 0; i < 4; i++) {
        int r = by * 32 + ty + i * 8;
        tile[ty + i * 8][tx] = Wsg[(size_t)r * NSLOT + bx * 32 + tx];
    }
    __syncthreads();
#pragma unroll
    for (int i = 0; i < 4; i++) {
        int n = bx * 32 + ty + i * 8;
        g_wsT[(size_t)n * RDIM + by * 32 + tx] = tile[tx][ty + i * 8];
    }
}

// ---------------- K1: hidden GEMM + budget (unchanged) ----------------
__global__ __launch_bounds__(256) void k_hidden(
    const float* __restrict__ x,  const float* __restrict__ Wc, const float* __restrict__ bc,
    const float* __restrict__ Wh, const float* __restrict__ bh, float* __restrict__ out_b)
{
    __shared__ float Xs[32][132];
    __shared__ float Wsm[32][128];
    __shared__ float Wcs[32];

    const int tid = threadIdx.x;
    const int tx = tid & 15, ty = tid >> 4;
    const int t0 = blockIdx.x * 128;

    float acc[8][8];
#pragma unroll
    for (int j = 0; j < 8; j++) {
        int c = (j < 4) ? tx * 4 + j : 64 + tx * 4 + (j - 4);
        float b = bh[c];
#pragma unroll
        for (int i = 0; i < 8; i++) acc[i][j] = b;
    }
    float cacc = 0.f;

    for (int kt = 0; kt < 32; kt++) {
#pragma unroll
        for (int i = 0; i < 4; i++) {
            int id = tid + i * 256;
            int token = id >> 3, kg = id & 7;
            float4 f = *(const float4*)(x + (size_t)(t0 + token) * DIN + kt * 32 + kg * 4);
            Xs[kg * 4 + 0][token] = f.x; Xs[kg * 4 + 1][token] = f.y;
            Xs[kg * 4 + 2][token] = f.z; Xs[kg * 4 + 3][token] = f.w;
        }
#pragma unroll
        for (int i = 0; i < 4; i++) {
            int id = tid + i * 256;
            int rowk = id >> 5, ng = id & 31;
            *(float4*)&Wsm[rowk][ng * 4] =
                *(const float4*)(Wh + (size_t)(kt * 32 + rowk) * RDIM + ng * 4);
        }
        if (tid < 32) Wcs[tid] = Wc[kt * 32 + tid];
        __syncthreads();

#pragma unroll
        for (int k = 0; k < 32; k++) {
            float4 a0 = *(float4*)&Xs[k][ty * 4];
            float4 a1 = *(float4*)&Xs[k][64 + ty * 4];
            float4 b0 = *(float4*)&Wsm[k][tx * 4];
            float4 b1 = *(float4*)&Wsm[k][64 + tx * 4];
            float xf[8] = {a0.x, a0.y, a0.z, a0.w, a1.x, a1.y, a1.z, a1.w};
            float wf[8] = {b0.x, b0.y, b0.z, b0.w, b1.x, b1.y, b1.z, b1.w};
#pragma unroll
            for (int i = 0; i < 8; i++)
#pragma unroll
                for (int j = 0; j < 8; j++)
                    acc[i][j] += xf[i] * wf[j];
        }
        if (tid < 128) {
            float s = 0.f;
#pragma unroll
            for (int k = 0; k < 32; k++) s += Xs[k][tid] * Wcs[k];
            cacc += s;
        }
        __syncthreads();
    }

#pragma unroll
    for (int i = 0; i < 8; i++) {
        int r = (i < 4) ? ty * 4 + i : 64 + ty * 4 + (i - 4);
        float4 o0 = make_float4(fmaxf(acc[i][0], 0.f), fmaxf(acc[i][1], 0.f),
                                fmaxf(acc[i][2], 0.f), fmaxf(acc[i][3], 0.f));
        float4 o1 = make_float4(fmaxf(acc[i][4], 0.f), fmaxf(acc[i][5], 0.f),
                                fmaxf(acc[i][6], 0.f), fmaxf(acc[i][7], 0.f));
        *(float4*)(g_hidden + (size_t)(t0 + r) * RDIM + tx * 4) = o0;
        *(float4*)(g_hidden + (size_t)(t0 + r) * RDIM + 64 + tx * 4) = o1;
    }
    if (tid < 128) {
        float zc = cacc + bc[0];
        float c = 1.f / (1.f + expf(-zc));
        float bf = 4.f + 28.f * c * c;
        int b = (int)floorf(bf);
        g_budget[t0 + tid] = b;
        out_b[t0 + tid] = (float)b;
    }
}

// ---------------- K2: approx scores via tf32 mma.sync ----------------
// sA: frag-order (conflict-free LDS.128). sB: row-major stride-72
// (coalesced staging stores; conflict-free LDS.32 fragment reads).
__device__ __forceinline__ void storeB_rowmajor(float* sB, const float4* pre, int tid) {
#pragma unroll
    for (int i = 0; i < 8; i++) {
        int id = tid + i * 256;
        int k = id >> 4, ng = id & 15;
        float4 hv = make_float4(to_tf32(pre[i].x), to_tf32(pre[i].y),
                                to_tf32(pre[i].z), to_tf32(pre[i].w));
        *(float4*)&sB[k * BSTRIDE + ng * 4] = hv;
    }
}

__global__ __launch_bounds__(256, 2) void k_scores_mma(const float* __restrict__ Wsg,
                                                       const float* __restrict__ bs)
{
    extern __shared__ char smem[];
    float* sA = (float*)(smem + SM2_A);
    float* sB = (float*)(smem + SM2_B);
    const float4* sA4 = (const float4*)sA;

    const int tid = threadIdx.x;
    const int lane = tid & 31, wid = tid >> 5;
    const int warpM = wid & 3, warpN = wid >> 2;
    const int gid = lane >> 2, tig = lane & 3;
    const int t0 = blockIdx.x * 128;

    // stage A: hidden[128][128] tf32 in fragment order (one-time)
#pragma unroll
    for (int i = 0; i < 16; i++) {
        int id = tid + i * 256;
        int m = id >> 5, fg = id & 31;
        float4 v = *(const float4*)(g_hidden + (size_t)(t0 + m) * RDIM + fg * 4);
        float hv[4] = {to_tf32(v.x), to_tf32(v.y), to_tf32(v.z), to_tf32(v.w)};
        int mt = m >> 4, rr = m & 15;
#pragma unroll
        for (int j = 0; j < 4; j++) {
            int k = fg * 4 + j;
            int kc = k >> 3, c4 = k & 7;
            int reg = ((rr >> 3) & 1) | (((c4 >> 2) & 1) << 1);
            int ln = (rr & 7) * 4 + (c4 & 3);
            sA[((mt * 16 + kc) * 32 + ln) * 4 + reg] = hv[j];
        }
    }

    // prologue: stage B tile 0 (row-major, coalesced)
    {
        float4 pre[8];
#pragma unroll
        for (int i = 0; i < 8; i++) {
            int id = tid + i * 256;
            int k = id >> 4, ng = id & 15;
            pre[i] = *(const float4*)(Wsg + (size_t)k * NSLOT + ng * 4);
        }
        storeB_rowmajor(sB, pre, tid);
    }
    __syncthreads();

    for (int nt = 0; nt < 64; nt++) {
        const int nbase = nt * 64;

        // prefetch next B tile into registers (overlaps MMA below)
        float4 pre[8];
        if (nt < 63) {
#pragma unroll
            for (int i = 0; i < 8; i++) {
                int id = tid + i * 256;
                int k = id >> 4, ng = id & 15;
                pre[i] = *(const float4*)(Wsg + (size_t)k * NSLOT + nbase + 64 + ng * 4);
            }
        }

        float c[2][4][4];
#pragma unroll
        for (int mi = 0; mi < 2; mi++)
#pragma unroll
            for (int ni = 0; ni < 4; ni++)
#pragma unroll
                for (int q = 0; q < 4; q++) c[mi][ni][q] = 0.f;

        const int colB = warpN * 32 + gid;

#pragma unroll 4
        for (int kc = 0; kc < 16; kc++) {
            float4 ah[2];
            float2 bh[4];
#pragma unroll
            for (int mi = 0; mi < 2; mi++) {
                int mt = warpM * 2 + mi;
                ah[mi] = sA4[(mt * 16 + kc) * 32 + lane];
            }
            const float* bR0 = sB + (kc * 8 + tig) * BSTRIDE + colB;
            const float* bR1 = bR0 + 4 * BSTRIDE;
#pragma unroll
            for (int ni = 0; ni < 4; ni++) {
                bh[ni].x = bR0[ni * 8];
                bh[ni].y = bR1[ni * 8];
            }
#pragma unroll
            for (int mi = 0; mi < 2; mi++)
#pragma unroll
                for (int ni = 0; ni < 4; ni++)
                    MMA_TF32(c[mi][ni], ah[mi], bh[ni]);
        }

        // epilogue: bias (L2) + store approx scores
#pragma unroll
        for (int mi = 0; mi < 2; mi++) {
            int row = t0 + warpM * 32 + mi * 16 + gid;
#pragma unroll
            for (int ni = 0; ni < 4; ni++) {
                int col = nbase + warpN * 32 + ni * 8 + tig * 2;
                float b0 = __ldg(bs + col), b1 = __ldg(bs + col + 1);
                *(float2*)(g_scores + (size_t)row * NSLOT + col) =
                    make_float2(c[mi][ni][0] + b0, c[mi][ni][1] + b1);
                *(float2*)(g_scores + (size_t)(row + 8) * NSLOT + col) =
                    make_float2(c[mi][ni][2] + b0, c[mi][ni][3] + b1);
            }
        }

        __syncthreads();                 // everyone done reading sB(nt)
        if (nt < 63) storeB_rowmajor(sB, pre, tid);
        __syncthreads();                 // sB(nt+1) visible
    }
}

// ---------------- K3: candidates from approx scores + R1-arithmetic exact refine ----------------
__global__ __launch_bounds__(256) void k_topk(float* __restrict__ out_idx,
                                              float* __restrict__ out_w,
                                              const float* __restrict__ bsg)
{
    __shared__ unsigned skey[4096];
    __shared__ u64      cand[256];
    __shared__ float    hrow[128];
    __shared__ float    fred[8], f2red[8];
    __shared__ int      ired[8];
    __shared__ unsigned s_cnt;
    __shared__ int      s_best;

    const int t = blockIdx.x;
    const int tid = threadIdx.x, lane = tid & 31, wid = tid >> 5;
    const float4* rowv = (const float4*)(g_scores + (size_t)t * NSLOT);

    if (tid < 32)
        *(float4*)&hrow[tid * 4] = *(const float4*)(g_hidden + (size_t)t * RDIM + tid * 4);

    float s = 0.f, s2 = 0.f;
#pragma unroll
    for (int i = 0; i < 4; i++) {
        int e4 = tid + i * 256;
        float4 f = rowv[e4];
        float vv[4] = {f.x, f.y, f.z, f.w};
        unsigned kk[4];
#pragma unroll
        for (int j = 0; j < 4; j++) {
            s += vv[j]; s2 += vv[j] * vv[j];
            unsigned b = __float_as_uint(vv[j]);
            kk[j] = b ^ ((unsigned)((int)b >> 31) | 0x80000000u);
        }
        *(uint4*)&skey[e4 * 4] = make_uint4(kk[0], kk[1], kk[2], kk[3]);
    }
    s = warpReduceSumF(s);
    s2 = warpReduceSumF(s2);
    if (lane == 0) { fred[wid] = s; f2red[wid] = s2; }
    __syncthreads();
    float ss = 0.f, ss2 = 0.f;
#pragma unroll
    for (int i = 0; i < 8; i++) { ss += fred[i]; ss2 += f2red[i]; }
    const float mean = ss * (1.f / NSLOT);
    const float sigma = sqrtf(fmaxf(ss2 * (1.f / NSLOT) - mean * mean, 0.f)) + 1e-20f;

    auto countGreater = [&](unsigned thrKey) -> int {
        int c = 0;
#pragma unroll
        for (int i = 0; i < 4; i++) {
            uint4 k4 = *(uint4*)&skey[(tid + i * 256) * 4];
            c += (k4.x > thrKey) + (k4.y > thrKey) + (k4.z > thrKey) + (k4.w > thrKey);
        }
        c = warpReduceSumI(c);
        __syncthreads();
        if (lane == 0) ired[wid] = c;
        __syncthreads();
        int tot = 0;
#pragma unroll
        for (int i = 0; i < 8; i++) tot += ired[i];
        return tot;
    };

    unsigned thrKey = 0;
    int cnt = 0;
    bool ok = false;
    float zf = 2.2f;
    for (int a = 0; a < 4; a++) {
        float thr = mean + zf * sigma;
        unsigned tb = __float_as_uint(thr);
        unsigned tk = tb ^ ((unsigned)((int)tb >> 31) | 0x80000000u);
        int c = countGreater(tk);
        if (c >= KSEL && c <= 256) { thrKey = tk; cnt = c; ok = true; break; }
        zf += (c < KSEL) ? -0.6f : 0.45f;
    }

    bool tiePath = false;
    unsigned Tkey = 0;
    if (!ok) {
        unsigned K = 0;
        for (int bit = 31; bit >= 0; bit--) {
            unsigned trial = K | (1u << bit);
            if (countGreater(trial) >= KSEL) K = trial;
        }
        int c = countGreater(K);
        if (c <= 256) {
            thrKey = K; cnt = c; ok = true;
        } else {
            tiePath = true;
            Tkey = K + 1u;
            thrKey = Tkey;
            cnt = countGreater(Tkey);
        }
    }

    if (tid == 0) s_cnt = 0;
    __syncthreads();
    {
        unsigned kk[16];
        unsigned my = 0;
#pragma unroll
        for (int i = 0; i < 4; i++) {
            uint4 k4 = *(uint4*)&skey[(tid + i * 256) * 4];
            kk[i * 4 + 0] = k4.x; kk[i * 4 + 1] = k4.y;
            kk[i * 4 + 2] = k4.z; kk[i * 4 + 3] = k4.w;
        }
#pragma unroll
        for (int i = 0; i < 16; i++) my += (kk[i] > thrKey) ? 1u : 0u;
        unsigned pre = my;
#pragma unroll
        for (int o = 1; o < 32; o <<= 1) {
            unsigned tt = __shfl_up_sync(0xffffffffu, pre, o);
            if (lane >= o) pre += tt;
        }
        unsigned wtot = __shfl_sync(0xffffffffu, pre, 31);
        unsigned wbase = 0;
        if (lane == 31 && wtot > 0) wbase = atomicAdd(&s_cnt, wtot);
        wbase = __shfl_sync(0xffffffffu, wbase, 31);
        unsigned pos = wbase + pre - my;
        if (my > 0) {
#pragma unroll
            for (int i = 0; i < 16; i++) {
                if (kk[i] > thrKey) {
                    if (pos < 256) {
                        unsigned idx = (unsigned)((tid + (i >> 2) * 256) * 4 + (i & 3));
                        cand[pos] = ((u64)kk[i] << 12) | (u64)(4095u - idx);
                    }
                    pos++;
                }
            }
        }
    }
    __syncthreads();

    if (tiePath) {
        int lastIdx = -1;
        for (int e = cnt; e < KSEL; e++) {
            int best = 0x7FFFFFFF;
#pragma unroll
            for (int i = 0; i < 4; i++) {
                uint4 k4 = *(uint4*)&skey[(tid + i * 256) * 4];
                unsigned ka[4] = {k4.x, k4.y, k4.z, k4.w};
#pragma unroll
                for (int j = 0; j < 4; j++) {
                    int idx = (tid + i * 256) * 4 + j;
                    if (ka[j] == Tkey && idx > lastIdx && idx < best) best = idx;
                }
            }
            best = warpReduceMinI(best);
            __syncthreads();
            if (lane == 0) ired[wid] = best;
            __syncthreads();
            if (tid == 0) {
                int bb = ired[0];
#pragma unroll
                for (int i = 1; i < 8; i++) bb = (ired[i] < bb) ? ired[i] : bb;
                s_best = bb;
                cand[e] = ((u64)Tkey << 12) | (u64)(4095u - (unsigned)bb);
            }
            __syncthreads();
            lastIdx = s_best;
        }
        cnt = KSEL;
        __syncthreads();
    }

    // ---- exact refine: one THREAD per candidate, bias-first, k-serial fmaf ----
    const int ncand = (cnt < 256) ? cnt : 256;
    if (tid < ncand) {
        unsigned idxv = 4095u - (unsigned)(cand[tid] & 0xFFFull);
        const float4* wv = (const float4*)(g_wsT + (size_t)idxv * RDIM);
        float acc = __ldg(bsg + idxv);
#pragma unroll
        for (int q = 0; q < 32; q++) {
            float4 w4 = __ldg(wv + q);
            float4 h4 = *(const float4*)&hrow[q * 4];
            acc = fmaf(h4.x, w4.x, acc);
            acc = fmaf(h4.y, w4.y, acc);
            acc = fmaf(h4.z, w4.z, acc);
            acc = fmaf(h4.w, w4.w, acc);
        }
        unsigned b = __float_as_uint(acc);
        unsigned k = b ^ ((unsigned)((int)b >> 31) | 0x80000000u);
        cand[tid] = ((u64)k << 12) | (u64)(4095u - idxv);
    }
    __syncthreads();

    // warp 0: exact top-32 extraction + outputs
    if (wid == 0) {
        u64 cl[8];
#pragma unroll
        for (int q = 0; q < 8; q++) {
            int p = lane + 32 * q;
            cl[q] = (p < ncand) ? cand[p] : 0ull;
        }
#pragma unroll
        for (int a = 1; a < 8; a++)
#pragma unroll
            for (int b2 = a; b2 > 0; b2--) {
                u64 lo = cl[b2 - 1] < cl[b2] ? cl[b2 - 1] : cl[b2];
                u64 hi = cl[b2 - 1] < cl[b2] ? cl[b2] : cl[b2 - 1];
                cl[b2 - 1] = hi; cl[b2] = lo;
            }
        u64 mysel = 0;
#pragma unroll
        for (int r2 = 0; r2 < MAXK; r2++) {
            u64 wb = warpReduceMaxU64(cl[0]);
            if (cl[0] == wb) {
#pragma unroll
                for (int q = 0; q < 7; q++) cl[q] = cl[q + 1];
                cl[7] = 0ull;
            }
            if (lane == r2) mysel = wb;
        }

        unsigned keyv = (unsigned)(mysel >> 12);
        unsigned idxv = 4095u - (unsigned)(mysel & 0xFFFull);
        unsigned fb = (keyv & 0x80000000u) ? (keyv ^ 0x80000000u) : ~keyv;
        float val = __uint_as_float(fb);

        int b = g_budget[t];
        float v0 = __shfl_sync(0xffffffffu, val, 0);
        bool msk = lane < b;
        float ev = msk ? __expf(val - v0) : 0.f;
        float zz = warpReduceSumF(ev);
        float w = msk ? ev / zz : 0.f;

        out_idx[(size_t)t * MAXK + lane] = (float)idxv;
        out_w[(size_t)t * MAXK + lane] = w;
        if (msk) atomicAdd(&g_counts[idxv], 1.0f);
    }
}

// ---------------- K4: aux (approx scores) ----------------
__global__ __launch_bounds__(256) void k_aux()
{
    __shared__ float sredZ[8], sredD[8], s_m;
    const int t = blockIdx.x;
    const int tid = threadIdx.x, lane = tid & 31, wid = tid >> 5;
    const float* row = g_scores + (size_t)t * NSLOT;

    float4 r[4];
#pragma unroll
    for (int i = 0; i < 4; i++) r[i] = *(const float4*)(row + (size_t)(tid + i * 256) * 4);

    float m = r[0].x;
#pragma unroll
    for (int i = 0; i < 4; i++) {
        m = fmaxf(m, r[i].x); m = fmaxf(m, r[i].y);
        m = fmaxf(m, r[i].z); m = fmaxf(m, r[i].w);
    }
    m = warpReduceMaxF(m);
    if (lane == 0) sredZ[wid] = m;
    __syncthreads();
    if (tid == 0) {
        float mm = sredZ[0];
#pragma unroll
        for (int i = 1; i < 8; i++) mm = fmaxf(mm, sredZ[i]);
        s_m = mm;
    }
    __syncthreads();
    m = s_m;

    float z = 0.f, d = 0.f;
#pragma unroll
    for (int i = 0; i < 4; i++) {
        float4 c = g_counts_v[tid + i * 256];
        float e0 = __expf(r[i].x - m), e1 = __expf(r[i].y - m);
        float e2 = __expf(r[i].z - m), e3 = __expf(r[i].w - m);
        z += e0 + e1 + e2 + e3;
        d += e0 * c.x + e1 * c.y + e2 * c.z + e3 * c.w;
    }
    z = warpReduceSumF(z);
    d = warpReduceSumF(d);
    if (lane == 0) { sredZ[wid] = z; sredD[wid] = d; }
    __syncthreads();
    if (tid == 0) {
        float zz = 0.f, dd = 0.f;
#pragma unroll
        for (int i = 0; i < 8; i++) { zz += sredZ[i]; dd += sredD[i]; }
        float contrib = (dd / zz) * ((float)NSLOT / ((float)TOK * (float)TOK));
        atomicAdd(&g_aux, contrib);
    }
}

// ---------------- K5 ----------------
__global__ void k_finish(float* __restrict__ out_aux)
{
    if (threadIdx.x == 0) out_aux[0] = g_aux;
}

// ---------------- launch ----------------
extern "C" void kernel_launch(void* const* d_in, const int* in_sizes, int n_in,
                              void* d_out, int out_size)
{
    const float* x  = (const float*)d_in[0];
    const float* Wc = (const float*)d_in[1];
    const float* bc = (const float*)d_in[2];
    const float* Wh = (const float*)d_in[3];
    const float* bh = (const float*)d_in[4];
    const float* Ws = (const float*)d_in[5];
    const float* bs = (const float*)d_in[6];

    float* out     = (float*)d_out;
    float* out_idx = out;
    float* out_w   = out + TOK * MAXK;
    float* out_b   = out + 2 * TOK * MAXK;
    float* out_aux = out + 2 * TOK * MAXK + TOK;

    cudaFuncSetAttribute(k_scores_mma, cudaFuncAttributeMaxDynamicSharedMemorySize, SM2_TOTAL);

    k_init<<<(NSLOT + 255) / 256, 256>>>();
    k_transpose<<<dim3(128, 4), 256>>>(Ws);
    k_hidden<<<TOK / 128, 256>>>(x, Wc, bc, Wh, bh, out_b);
    k_scores_mma<<<TOK / 128, 256, SM2_TOTAL>>>(Ws, bs);
    k_topk<<<TOK, 256>>>(out_idx, out_w, bs);
    k_aux<<<TOK, 256>>>();
    k_finish<<<1, 32>>>(out_aux);
}

// round 13
// speedup vs baseline: 1.7183x; 1.0329x over previous
#include <cuda_runtime.h>
#include <cuda_fp16.h>
#include <cstdint>

#define TOK   32768
#define DIN   1024
#define RDIM  128
#define NSLOT 4096
#define MAXK  32
#define KSEL  48

typedef unsigned long long u64;

// ---------------- scratch ----------------
__device__ float   g_hidden[TOK * RDIM];
__device__ __half2 g_scores_h2[TOK * NSLOT / 2];   // 256 MB approx scores (fp16)
__device__ float   g_wsT[NSLOT * RDIM];            // 2 MB W_s transposed
__device__ int     g_budget[TOK];
__device__ float4  g_counts_v[NSLOT / 4];
__device__ float   g_aux;

#define g_scores_h ((__half*)g_scores_h2)
#define g_counts   ((float*)g_counts_v)

// ---------------- tf32 ----------------
__device__ __forceinline__ float to_tf32(float v) {
    unsigned h;
    asm("cvt.rna.tf32.f32 %0, %1;" : "=r"(h) : "f"(v));
    return __uint_as_float(h);
}

#define MMA_TF32(c, a, b) \
    asm volatile("mma.sync.aligned.m16n8k8.row.col.f32.tf32.tf32.f32 " \
        "{%0,%1,%2,%3}, {%4,%5,%6,%7}, {%8,%9}, {%0,%1,%2,%3};" \
        : "+f"((c)[0]), "+f"((c)[1]), "+f"((c)[2]), "+f"((c)[3]) \
        : "r"(__float_as_uint((a).x)), "r"(__float_as_uint((a).y)), \
          "r"(__float_as_uint((a).z)), "r"(__float_as_uint((a).w)), \
          "r"(__float_as_uint((b).x)), "r"(__float_as_uint((b).y)))

// smem layout for k_scores_mma
#define BSTRIDE   72
#define SM2_A     0
#define SM2_B     65536
#define SM2_TOTAL (65536 + 128 * BSTRIDE * 4)

// 16-bit sortable key for fp16 bits
__device__ __forceinline__ unsigned key16(unsigned h) {
    unsigned m = ((h >> 15) & 1u) ? 0xFFFFu : 0x8000u;
    return (h ^ m) & 0xFFFFu;
}

// ---------------- reductions ----------------
__device__ __forceinline__ float warpReduceMaxF(float v) {
#pragma unroll
    for (int o = 16; o > 0; o >>= 1) v = fmaxf(v, __shfl_xor_sync(0xffffffffu, v, o));
    return v;
}
__device__ __forceinline__ float warpReduceSumF(float v) {
#pragma unroll
    for (int o = 16; o > 0; o >>= 1) v += __shfl_xor_sync(0xffffffffu, v, o);
    return v;
}
__device__ __forceinline__ int warpReduceSumI(int v) {
#pragma unroll
    for (int o = 16; o > 0; o >>= 1) v += __shfl_xor_sync(0xffffffffu, v, o);
    return v;
}
__device__ __forceinline__ int warpReduceMinI(int v) {
#pragma unroll
    for (int o = 16; o > 0; o >>= 1) {
        int t = __shfl_xor_sync(0xffffffffu, v, o);
        v = (t < v) ? t : v;
    }
    return v;
}
__device__ __forceinline__ u64 warpReduceMaxU64(u64 v) {
#pragma unroll
    for (int o = 16; o > 0; o >>= 1) {
        u64 t = __shfl_xor_sync(0xffffffffu, v, o);
        v = (t > v) ? t : v;
    }
    return v;
}

// ---------------- K0 ----------------
__global__ void k_init() {
    int i = blockIdx.x * blockDim.x + threadIdx.x;
    if (i < NSLOT) g_counts[i] = 0.f;
    if (i == 0)    g_aux = 0.f;
}

// ---------------- K0b: transpose W_s -> g_wsT[N][R] ----------------
__global__ __launch_bounds__(256) void k_transpose(const float* __restrict__ Wsg) {
    __shared__ float tile[32][33];
    const int bx = blockIdx.x;
    const int by = blockIdx.y;
    const int tx = threadIdx.x & 31, ty = threadIdx.x >> 5;
#pragma unroll
    for (int i = 0; i < 4; i++) {
        int r = by * 32 + ty + i * 8;
        tile[ty + i * 8][tx] = Wsg[(size_t)r * NSLOT + bx * 32 + tx];
    }
    __syncthreads();
#pragma unroll
    for (int i = 0; i < 4; i++) {
        int n = bx * 32 + ty + i * 8;
        g_wsT[(size_t)n * RDIM + by * 32 + tx] = tile[tx][ty + i * 8];
    }
}

// ---------------- K1: hidden GEMM + budget (unchanged) ----------------
__global__ __launch_bounds__(256) void k_hidden(
    const float* __restrict__ x,  const float* __restrict__ Wc, const float* __restrict__ bc,
    const float* __restrict__ Wh, const float* __restrict__ bh, float* __restrict__ out_b)
{
    __shared__ float Xs[32][132];
    __shared__ float Wsm[32][128];
    __shared__ float Wcs[32];

    const int tid = threadIdx.x;
    const int tx = tid & 15, ty = tid >> 4;
    const int t0 = blockIdx.x * 128;

    float acc[8][8];
#pragma unroll
    for (int j = 0; j < 8; j++) {
        int c = (j < 4) ? tx * 4 + j : 64 + tx * 4 + (j - 4);
        float b = bh[c];
#pragma unroll
        for (int i = 0; i < 8; i++) acc[i][j] = b;
    }
    float cacc = 0.f;

    for (int kt = 0; kt < 32; kt++) {
#pragma unroll
        for (int i = 0; i < 4; i++) {
            int id = tid + i * 256;
            int token = id >> 3, kg = id & 7;
            float4 f = *(const float4*)(x + (size_t)(t0 + token) * DIN + kt * 32 + kg * 4);
            Xs[kg * 4 + 0][token] = f.x; Xs[kg * 4 + 1][token] = f.y;
            Xs[kg * 4 + 2][token] = f.z; Xs[kg * 4 + 3][token] = f.w;
        }
#pragma unroll
        for (int i = 0; i < 4; i++) {
            int id = tid + i * 256;
            int rowk = id >> 5, ng = id & 31;
            *(float4*)&Wsm[rowk][ng * 4] =
                *(const float4*)(Wh + (size_t)(kt * 32 + rowk) * RDIM + ng * 4);
        }
        if (tid < 32) Wcs[tid] = Wc[kt * 32 + tid];
        __syncthreads();

#pragma unroll
        for (int k = 0; k < 32; k++) {
            float4 a0 = *(float4*)&Xs[k][ty * 4];
            float4 a1 = *(float4*)&Xs[k][64 + ty * 4];
            float4 b0 = *(float4*)&Wsm[k][tx * 4];
            float4 b1 = *(float4*)&Wsm[k][64 + tx * 4];
            float xf[8] = {a0.x, a0.y, a0.z, a0.w, a1.x, a1.y, a1.z, a1.w};
            float wf[8] = {b0.x, b0.y, b0.z, b0.w, b1.x, b1.y, b1.z, b1.w};
#pragma unroll
            for (int i = 0; i < 8; i++)
#pragma unroll
                for (int j = 0; j < 8; j++)
                    acc[i][j] += xf[i] * wf[j];
        }
        if (tid < 128) {
            float s = 0.f;
#pragma unroll
            for (int k = 0; k < 32; k++) s += Xs[k][tid] * Wcs[k];
            cacc += s;
        }
        __syncthreads();
    }

#pragma unroll
    for (int i = 0; i < 8; i++) {
        int r = (i < 4) ? ty * 4 + i : 64 + ty * 4 + (i - 4);
        float4 o0 = make_float4(fmaxf(acc[i][0], 0.f), fmaxf(acc[i][1], 0.f),
                                fmaxf(acc[i][2], 0.f), fmaxf(acc[i][3], 0.f));
        float4 o1 = make_float4(fmaxf(acc[i][4], 0.f), fmaxf(acc[i][5], 0.f),
                                fmaxf(acc[i][6], 0.f), fmaxf(acc[i][7], 0.f));
        *(float4*)(g_hidden + (size_t)(t0 + r) * RDIM + tx * 4) = o0;
        *(float4*)(g_hidden + (size_t)(t0 + r) * RDIM + 64 + tx * 4) = o1;
    }
    if (tid < 128) {
        float zc = cacc + bc[0];
        float c = 1.f / (1.f + expf(-zc));
        float bf = 4.f + 28.f * c * c;
        int b = (int)floorf(bf);
        g_budget[t0 + tid] = b;
        out_b[t0 + tid] = (float)b;
    }
}

// ---------------- K2: approx scores via tf32 mma.sync (fp16 output) ----------------
__device__ __forceinline__ void storeB_rowmajor(float* sB, const float4* pre, int tid) {
#pragma unroll
    for (int i = 0; i < 8; i++) {
        int id = tid + i * 256;
        int k = id >> 4, ng = id & 15;
        float4 hv = make_float4(to_tf32(pre[i].x), to_tf32(pre[i].y),
                                to_tf32(pre[i].z), to_tf32(pre[i].w));
        *(float4*)&sB[k * BSTRIDE + ng * 4] = hv;
    }
}

__global__ __launch_bounds__(256, 2) void k_scores_mma(const float* __restrict__ Wsg,
                                                       const float* __restrict__ bs)
{
    extern __shared__ char smem[];
    float* sA = (float*)(smem + SM2_A);
    float* sB = (float*)(smem + SM2_B);
    const float4* sA4 = (const float4*)sA;

    const int tid = threadIdx.x;
    const int lane = tid & 31, wid = tid >> 5;
    const int warpM = wid & 3, warpN = wid >> 2;
    const int gid = lane >> 2, tig = lane & 3;
    const int t0 = blockIdx.x * 128;

    // stage A: hidden[128][128] tf32 in fragment order (one-time)
#pragma unroll
    for (int i = 0; i < 16; i++) {
        int id = tid + i * 256;
        int m = id >> 5, fg = id & 31;
        float4 v = *(const float4*)(g_hidden + (size_t)(t0 + m) * RDIM + fg * 4);
        float hv[4] = {to_tf32(v.x), to_tf32(v.y), to_tf32(v.z), to_tf32(v.w)};
        int mt = m >> 4, rr = m & 15;
#pragma unroll
        for (int j = 0; j < 4; j++) {
            int k = fg * 4 + j;
            int kc = k >> 3, c4 = k & 7;
            int reg = ((rr >> 3) & 1) | (((c4 >> 2) & 1) << 1);
            int ln = (rr & 7) * 4 + (c4 & 3);
            sA[((mt * 16 + kc) * 32 + ln) * 4 + reg] = hv[j];
        }
    }

    // prologue: stage B tile 0
    {
        float4 pre[8];
#pragma unroll
        for (int i = 0; i < 8; i++) {
            int id = tid + i * 256;
            int k = id >> 4, ng = id & 15;
            pre[i] = *(const float4*)(Wsg + (size_t)k * NSLOT + ng * 4);
        }
        storeB_rowmajor(sB, pre, tid);
    }
    __syncthreads();

    for (int nt = 0; nt < 64; nt++) {
        const int nbase = nt * 64;

        float4 pre[8];
        if (nt < 63) {
#pragma unroll
            for (int i = 0; i < 8; i++) {
                int id = tid + i * 256;
                int k = id >> 4, ng = id & 15;
                pre[i] = *(const float4*)(Wsg + (size_t)k * NSLOT + nbase + 64 + ng * 4);
            }
        }

        float c[2][4][4];
#pragma unroll
        for (int mi = 0; mi < 2; mi++)
#pragma unroll
            for (int ni = 0; ni < 4; ni++)
#pragma unroll
                for (int q = 0; q < 4; q++) c[mi][ni][q] = 0.f;

        const int colB = warpN * 32 + gid;

#pragma unroll 4
        for (int kc = 0; kc < 16; kc++) {
            float4 ah[2];
            float2 bh[4];
#pragma unroll
            for (int mi = 0; mi < 2; mi++) {
                int mt = warpM * 2 + mi;
                ah[mi] = sA4[(mt * 16 + kc) * 32 + lane];
            }
            const float* bR0 = sB + (kc * 8 + tig) * BSTRIDE + colB;
            const float* bR1 = bR0 + 4 * BSTRIDE;
#pragma unroll
            for (int ni = 0; ni < 4; ni++) {
                bh[ni].x = bR0[ni * 8];
                bh[ni].y = bR1[ni * 8];
            }
#pragma unroll
            for (int mi = 0; mi < 2; mi++)
#pragma unroll
                for (int ni = 0; ni < 4; ni++)
                    MMA_TF32(c[mi][ni], ah[mi], bh[ni]);
        }

        // epilogue: bias (L2) + store approx scores (fp16)
#pragma unroll
        for (int mi = 0; mi < 2; mi++) {
            int row = t0 + warpM * 32 + mi * 16 + gid;
#pragma unroll
            for (int ni = 0; ni < 4; ni++) {
                int col = nbase + warpN * 32 + ni * 8 + tig * 2;
                float b0 = __ldg(bs + col), b1 = __ldg(bs + col + 1);
                g_scores_h2[((size_t)row * NSLOT + col) >> 1] =
                    __floats2half2_rn(c[mi][ni][0] + b0, c[mi][ni][1] + b1);
                g_scores_h2[((size_t)(row + 8) * NSLOT + col) >> 1] =
                    __floats2half2_rn(c[mi][ni][2] + b0, c[mi][ni][3] + b1);
            }
        }

        __syncthreads();
        if (nt < 63) storeB_rowmajor(sB, pre, tid);
        __syncthreads();
    }
}

// ---------------- K3: fp16 candidates + R1-arithmetic exact refine ----------------
__global__ __launch_bounds__(256) void k_topk(float* __restrict__ out_idx,
                                              float* __restrict__ out_w,
                                              const float* __restrict__ bsg)
{
    __shared__ unsigned skey[2048];     // 2x16-bit keys per word (8 KB)
    __shared__ u64      cand[256];
    __shared__ float    hrow[128];
    __shared__ float    fred[8], f2red[8];
    __shared__ int      ired[8];
    __shared__ unsigned s_cnt;
    __shared__ int      s_best;

    const int t = blockIdx.x;
    const int tid = threadIdx.x, lane = tid & 31, wid = tid >> 5;
    const uint4* rowv = (const uint4*)(g_scores_h + (size_t)t * NSLOT);

    if (tid < 32)
        *(float4*)&hrow[tid * 4] = *(const float4*)(g_hidden + (size_t)t * RDIM + tid * 4);

    // load row (fp16), build packed 16-bit keys in smem + stats
    float s = 0.f, s2 = 0.f;
#pragma unroll
    for (int i = 0; i < 2; i++) {
        uint4 v = rowv[tid + i * 256];
        unsigned w[4] = {v.x, v.y, v.z, v.w};
        unsigned pk[4];
#pragma unroll
        for (int j = 0; j < 4; j++) {
            float2 f2 = __half22float2(*(__half2*)&w[j]);
            s += f2.x + f2.y;
            s2 += f2.x * f2.x + f2.y * f2.y;
            pk[j] = key16(w[j] & 0xFFFFu) | (key16(w[j] >> 16) << 16);
        }
        *(uint4*)&skey[(tid + i * 256) * 4] = make_uint4(pk[0], pk[1], pk[2], pk[3]);
    }
    s = warpReduceSumF(s);
    s2 = warpReduceSumF(s2);
    if (lane == 0) { fred[wid] = s; f2red[wid] = s2; }
    __syncthreads();
    float ss = 0.f, ss2 = 0.f;
#pragma unroll
    for (int i = 0; i < 8; i++) { ss += fred[i]; ss2 += f2red[i]; }
    const float mean = ss * (1.f / NSLOT);
    const float sigma = sqrtf(fmaxf(ss2 * (1.f / NSLOT) - mean * mean, 0.f)) + 1e-20f;

    auto countGreater = [&](unsigned thrKey) -> int {
        int c = 0;
#pragma unroll
        for (int i = 0; i < 2; i++) {
            uint4 k4 = *(uint4*)&skey[(tid + i * 256) * 4];
            unsigned w[4] = {k4.x, k4.y, k4.z, k4.w};
#pragma unroll
            for (int j = 0; j < 4; j++)
                c += ((w[j] & 0xFFFFu) > thrKey) + ((w[j] >> 16) > thrKey);
        }
        c = warpReduceSumI(c);
        __syncthreads();
        if (lane == 0) ired[wid] = c;
        __syncthreads();
        int tot = 0;
#pragma unroll
        for (int i = 0; i < 8; i++) tot += ired[i];
        return tot;
    };

    unsigned thrKey = 0;
    int cnt = 0;
    bool ok = false;
    float zf = 2.2f;
    for (int a = 0; a < 4; a++) {
        __half th = __float2half_rn(mean + zf * sigma);
        unsigned tk = key16((unsigned)__half_as_ushort(th));
        int c = countGreater(tk);
        if (c >= KSEL && c <= 256) { thrKey = tk; cnt = c; ok = true; break; }
        zf += (c < KSEL) ? -0.6f : 0.45f;
    }

    bool tiePath = false;
    unsigned Tkey = 0;
    if (!ok) {
        unsigned K = 0;
        for (int bit = 15; bit >= 0; bit--) {
            unsigned trial = K | (1u << bit);
            if (countGreater(trial) >= KSEL) K = trial;
        }
        int c = countGreater(K);
        if (c <= 256) {
            thrKey = K; cnt = c; ok = true;
        } else {
            tiePath = true;
            Tkey = K + 1u;
            thrKey = Tkey;
            cnt = countGreater(Tkey);
        }
    }

    // compaction pass
    if (tid == 0) s_cnt = 0;
    __syncthreads();
    {
        unsigned kk[16];
#pragma unroll
        for (int i = 0; i < 2; i++) {
            uint4 k4 = *(uint4*)&skey[(tid + i * 256) * 4];
            unsigned w[4] = {k4.x, k4.y, k4.z, k4.w};
#pragma unroll
            for (int j = 0; j < 4; j++) {
                kk[i * 8 + j * 2 + 0] = w[j] & 0xFFFFu;
                kk[i * 8 + j * 2 + 1] = w[j] >> 16;
            }
        }
        unsigned my = 0;
#pragma unroll
        for (int q = 0; q < 16; q++) my += (kk[q] > thrKey) ? 1u : 0u;
        unsigned pre = my;
#pragma unroll
        for (int o = 1; o < 32; o <<= 1) {
            unsigned tt = __shfl_up_sync(0xffffffffu, pre, o);
            if (lane >= o) pre += tt;
        }
        unsigned wtot = __shfl_sync(0xffffffffu, pre, 31);
        unsigned wbase = 0;
        if (lane == 31 && wtot > 0) wbase = atomicAdd(&s_cnt, wtot);
        wbase = __shfl_sync(0xffffffffu, wbase, 31);
        unsigned pos = wbase + pre - my;
        if (my > 0) {
#pragma unroll
            for (int q = 0; q < 16; q++) {
                if (kk[q] > thrKey) {
                    if (pos < 256) {
                        unsigned idx = (unsigned)((tid + (q >> 3) * 256) * 8 + (q & 7));
                        cand[pos] = ((u64)kk[q] << 12) | (u64)(4095u - idx);
                    }
                    pos++;
                }
            }
        }
    }
    __syncthreads();

    if (tiePath) {
        int lastIdx = -1;
        for (int e = cnt; e < KSEL; e++) {
            int best = 0x7FFFFFFF;
#pragma unroll
            for (int i = 0; i < 2; i++) {
                uint4 k4 = *(uint4*)&skey[(tid + i * 256) * 4];
                unsigned w[4] = {k4.x, k4.y, k4.z, k4.w};
#pragma unroll
                for (int j = 0; j < 4; j++) {
                    int idx0 = (tid + i * 256) * 8 + j * 2;
                    unsigned lo = w[j] & 0xFFFFu, hi = w[j] >> 16;
                    if (lo == Tkey && idx0 > lastIdx && idx0 < best) best = idx0;
                    if (hi == Tkey && idx0 + 1 > lastIdx && idx0 + 1 < best) best = idx0 + 1;
                }
            }
            best = warpReduceMinI(best);
            __syncthreads();
            if (lane == 0) ired[wid] = best;
            __syncthreads();
            if (tid == 0) {
                int bb = ired[0];
#pragma unroll
                for (int i = 1; i < 8; i++) bb = (ired[i] < bb) ? ired[i] : bb;
                s_best = bb;
                cand[e] = ((u64)Tkey << 12) | (u64)(4095u - (unsigned)bb);
            }
            __syncthreads();
            lastIdx = s_best;
        }
        cnt = KSEL;
        __syncthreads();
    }

    // ---- exact refine: one THREAD per candidate, bias-first, k-serial fmaf ----
    const int ncand = (cnt < 256) ? cnt : 256;
    if (tid < ncand) {
        unsigned idxv = 4095u - (unsigned)(cand[tid] & 0xFFFull);
        const float4* wv = (const float4*)(g_wsT + (size_t)idxv * RDIM);
        float acc = __ldg(bsg + idxv);
#pragma unroll
        for (int q = 0; q < 32; q++) {
            float4 w4 = __ldg(wv + q);
            float4 h4 = *(const float4*)&hrow[q * 4];
            acc = fmaf(h4.x, w4.x, acc);
            acc = fmaf(h4.y, w4.y, acc);
            acc = fmaf(h4.z, w4.z, acc);
            acc = fmaf(h4.w, w4.w, acc);
        }
        unsigned b = __float_as_uint(acc);
        unsigned k = b ^ ((unsigned)((int)b >> 31) | 0x80000000u);
        cand[tid] = ((u64)k << 12) | (u64)(4095u - idxv);
    }
    __syncthreads();

    // warp 0: exact top-32 extraction + outputs
    if (wid == 0) {
        u64 cl[8];
#pragma unroll
        for (int q = 0; q < 8; q++) {
            int p = lane + 32 * q;
            cl[q] = (p < ncand) ? cand[p] : 0ull;
        }
#pragma unroll
        for (int a = 1; a < 8; a++)
#pragma unroll
            for (int b2 = a; b2 > 0; b2--) {
                u64 lo = cl[b2 - 1] < cl[b2] ? cl[b2 - 1] : cl[b2];
                u64 hi = cl[b2 - 1] < cl[b2] ? cl[b2] : cl[b2 - 1];
                cl[b2 - 1] = hi; cl[b2] = lo;
            }
        u64 mysel = 0;
#pragma unroll
        for (int r2 = 0; r2 < MAXK; r2++) {
            u64 wb = warpReduceMaxU64(cl[0]);
            if (cl[0] == wb) {
#pragma unroll
                for (int q = 0; q < 7; q++) cl[q] = cl[q + 1];
                cl[7] = 0ull;
            }
            if (lane == r2) mysel = wb;
        }

        unsigned keyv = (unsigned)(mysel >> 12);
        unsigned idxv = 4095u - (unsigned)(mysel & 0xFFFull);
        unsigned fb = (keyv & 0x80000000u) ? (keyv ^ 0x80000000u) : ~keyv;
        float val = __uint_as_float(fb);

        int b = g_budget[t];
        float v0 = __shfl_sync(0xffffffffu, val, 0);
        bool msk = lane < b;
        float ev = msk ? __expf(val - v0) : 0.f;
        float zz = warpReduceSumF(ev);
        float w = msk ? ev / zz : 0.f;

        out_idx[(size_t)t * MAXK + lane] = (float)idxv;
        out_w[(size_t)t * MAXK + lane] = w;
        if (msk) atomicAdd(&g_counts[idxv], 1.0f);
    }
}

// ---------------- K4: aux (fp16 approx scores) ----------------
__global__ __launch_bounds__(256) void k_aux()
{
    __shared__ float sredZ[8], sredD[8], s_m;
    const int t = blockIdx.x;
    const int tid = threadIdx.x, lane = tid & 31, wid = tid >> 5;
    const uint4* rowv = (const uint4*)(g_scores_h + (size_t)t * NSLOT);

    float fv[16];
    float m = -1e30f;
#pragma unroll
    for (int i = 0; i < 2; i++) {
        uint4 v = rowv[tid + i * 256];
        unsigned w[4] = {v.x, v.y, v.z, v.w};
#pragma unroll
        for (int j = 0; j < 4; j++) {
            float2 f2 = __half22float2(*(__half2*)&w[j]);
            fv[i * 8 + j * 2 + 0] = f2.x;
            fv[i * 8 + j * 2 + 1] = f2.y;
            m = fmaxf(m, fmaxf(f2.x, f2.y));
        }
    }
    m = warpReduceMaxF(m);
    if (lane == 0) sredZ[wid] = m;
    __syncthreads();
    if (tid == 0) {
        float mm = sredZ[0];
#pragma unroll
        for (int i = 1; i < 8; i++) mm = fmaxf(mm, sredZ[i]);
        s_m = mm;
    }
    __syncthreads();
    m = s_m;

    float z = 0.f, d = 0.f;
#pragma unroll
    for (int i = 0; i < 2; i++) {
#pragma unroll
        for (int j = 0; j < 2; j++) {
            float4 c = g_counts_v[(tid + i * 256) * 2 + j];
            float e0 = __expf(fv[i * 8 + j * 4 + 0] - m);
            float e1 = __expf(fv[i * 8 + j * 4 + 1] - m);
            float e2 = __expf(fv[i * 8 + j * 4 + 2] - m);
            float e3 = __expf(fv[i * 8 + j * 4 + 3] - m);
            z += e0 + e1 + e2 + e3;
            d += e0 * c.x + e1 * c.y + e2 * c.z + e3 * c.w;
        }
    }
    z = warpReduceSumF(z);
    d = warpReduceSumF(d);
    if (lane == 0) { sredZ[wid] = z; sredD[wid] = d; }
    __syncthreads();
    if (tid == 0) {
        float zz = 0.f, dd = 0.f;
#pragma unroll
        for (int i = 0; i < 8; i++) { zz += sredZ[i]; dd += sredD[i]; }
        float contrib = (dd / zz) * ((float)NSLOT / ((float)TOK * (float)TOK));
        atomicAdd(&g_aux, contrib);
    }
}

// ---------------- K5 ----------------
__global__ void k_finish(float* __restrict__ out_aux)
{
    if (threadIdx.x == 0) out_aux[0] = g_aux;
}

// ---------------- launch ----------------
extern "C" void kernel_launch(void* const* d_in, const int* in_sizes, int n_in,
                              void* d_out, int out_size)
{
    const float* x  = (const float*)d_in[0];
    const float* Wc = (const float*)d_in[1];
    const float* bc = (const float*)d_in[2];
    const float* Wh = (const float*)d_in[3];
    const float* bh = (const float*)d_in[4];
    const float* Ws = (const float*)d_in[5];
    const float* bs = (const float*)d_in[6];

    float* out     = (float*)d_out;
    float* out_idx = out;
    float* out_w   = out + TOK * MAXK;
    float* out_b   = out + 2 * TOK * MAXK;
    float* out_aux = out + 2 * TOK * MAXK + TOK;

    cudaFuncSetAttribute(k_scores_mma, cudaFuncAttributeMaxDynamicSharedMemorySize, SM2_TOTAL);

    k_init<<<(NSLOT + 255) / 256, 256>>>();
    k_transpose<<<dim3(128, 4), 256>>>(Ws);
    k_hidden<<<TOK / 128, 256>>>(x, Wc, bc, Wh, bh, out_b);
    k_scores_mma<<<TOK / 128, 256, SM2_TOTAL>>>(Ws, bs);
    k_topk<<<TOK, 256>>>(out_idx, out_w, bs);
    k_aux<<<TOK, 256>>>();
    k_finish<<<1, 32>>>(out_aux);
}

// round 14
// speedup vs baseline: 1.8634x; 1.0845x over previous
#include <cuda_runtime.h>
#include <cuda_fp16.h>
#include <cstdint>

#define TOK   32768
#define DIN   1024
#define RDIM  128
#define NSLOT 4096
#define MAXK  32
#define KSEL  48

typedef unsigned long long u64;

// ---------------- scratch ----------------
__device__ float   g_hidden[TOK * RDIM];
__device__ __half2 g_scores_h2[TOK * NSLOT / 2];   // 256 MB approx scores (fp16)
__device__ float   g_wsT[NSLOT * RDIM];            // 2 MB W_s transposed
__device__ int     g_budget[TOK];
__device__ float4  g_counts_v[NSLOT / 4];
__device__ float   g_aux;

#define g_scores_h ((__half*)g_scores_h2)
#define g_counts   ((float*)g_counts_v)

// ---------------- fp16 MMA ----------------
#define MMA_F16(c, a, b) \
    asm volatile("mma.sync.aligned.m16n8k16.row.col.f32.f16.f16.f32 " \
        "{%0,%1,%2,%3}, {%4,%5,%6,%7}, {%8,%9}, {%0,%1,%2,%3};" \
        : "+f"((c)[0]), "+f"((c)[1]), "+f"((c)[2]), "+f"((c)[3]) \
        : "r"((a)[0]), "r"((a)[1]), "r"((a)[2]), "r"((a)[3]), \
          "r"((b)[0]), "r"((b)[1]))

// smem: sA frag-order 32 KB (8mt x 8kc x 32lane x uint4), sB half2[64][72] 18 KB
#define BSTR2     72
#define SM2_A     0
#define SM2_B     32768
#define SM2_TOTAL (32768 + 64 * BSTR2 * 4)   // 51200

// 16-bit sortable key for fp16 bits
__device__ __forceinline__ unsigned key16(unsigned h) {
    unsigned m = ((h >> 15) & 1u) ? 0xFFFFu : 0x8000u;
    return (h ^ m) & 0xFFFFu;
}

// ---------------- reductions ----------------
__device__ __forceinline__ float warpReduceMaxF(float v) {
#pragma unroll
    for (int o = 16; o > 0; o >>= 1) v = fmaxf(v, __shfl_xor_sync(0xffffffffu, v, o));
    return v;
}
__device__ __forceinline__ float warpReduceSumF(float v) {
#pragma unroll
    for (int o = 16; o > 0; o >>= 1) v += __shfl_xor_sync(0xffffffffu, v, o);
    return v;
}
__device__ __forceinline__ int warpReduceSumI(int v) {
#pragma unroll
    for (int o = 16; o > 0; o >>= 1) v += __shfl_xor_sync(0xffffffffu, v, o);
    return v;
}
__device__ __forceinline__ int warpReduceMinI(int v) {
#pragma unroll
    for (int o = 16; o > 0; o >>= 1) {
        int t = __shfl_xor_sync(0xffffffffu, v, o);
        v = (t < v) ? t : v;
    }
    return v;
}
__device__ __forceinline__ u64 warpReduceMaxU64(u64 v) {
#pragma unroll
    for (int o = 16; o > 0; o >>= 1) {
        u64 t = __shfl_xor_sync(0xffffffffu, v, o);
        v = (t > v) ? t : v;
    }
    return v;
}

// ---------------- K0 ----------------
__global__ void k_init() {
    int i = blockIdx.x * blockDim.x + threadIdx.x;
    if (i < NSLOT) g_counts[i] = 0.f;
    if (i == 0)    g_aux = 0.f;
}

// ---------------- K0b: transpose W_s -> g_wsT[N][R] ----------------
__global__ __launch_bounds__(256) void k_transpose(const float* __restrict__ Wsg) {
    __shared__ float tile[32][33];
    const int bx = blockIdx.x;
    const int by = blockIdx.y;
    const int tx = threadIdx.x & 31, ty = threadIdx.x >> 5;
#pragma unroll
    for (int i = 0; i < 4; i++) {
        int r = by * 32 + ty + i * 8;
        tile[ty + i * 8][tx] = Wsg[(size_t)r * NSLOT + bx * 32 + tx];
    }
    __syncthreads();
#pragma unroll
    for (int i = 0; i < 4; i++) {
        int n = bx * 32 + ty + i * 8;
        g_wsT[(size_t)n * RDIM + by * 32 + tx] = tile[tx][ty + i * 8];
    }
}

// ---------------- K1: hidden GEMM + budget (unchanged) ----------------
__global__ __launch_bounds__(256) void k_hidden(
    const float* __restrict__ x,  const float* __restrict__ Wc, const float* __restrict__ bc,
    const float* __restrict__ Wh, const float* __restrict__ bh, float* __restrict__ out_b)
{
    __shared__ float Xs[32][132];
    __shared__ float Wsm[32][128];
    __shared__ float Wcs[32];

    const int tid = threadIdx.x;
    const int tx = tid & 15, ty = tid >> 4;
    const int t0 = blockIdx.x * 128;

    float acc[8][8];
#pragma unroll
    for (int j = 0; j < 8; j++) {
        int c = (j < 4) ? tx * 4 + j : 64 + tx * 4 + (j - 4);
        float b = bh[c];
#pragma unroll
        for (int i = 0; i < 8; i++) acc[i][j] = b;
    }
    float cacc = 0.f;

    for (int kt = 0; kt < 32; kt++) {
#pragma unroll
        for (int i = 0; i < 4; i++) {
            int id = tid + i * 256;
            int token = id >> 3, kg = id & 7;
            float4 f = *(const float4*)(x + (size_t)(t0 + token) * DIN + kt * 32 + kg * 4);
            Xs[kg * 4 + 0][token] = f.x; Xs[kg * 4 + 1][token] = f.y;
            Xs[kg * 4 + 2][token] = f.z; Xs[kg * 4 + 3][token] = f.w;
        }
#pragma unroll
        for (int i = 0; i < 4; i++) {
            int id = tid + i * 256;
            int rowk = id >> 5, ng = id & 31;
            *(float4*)&Wsm[rowk][ng * 4] =
                *(const float4*)(Wh + (size_t)(kt * 32 + rowk) * RDIM + ng * 4);
        }
        if (tid < 32) Wcs[tid] = Wc[kt * 32 + tid];
        __syncthreads();

#pragma unroll
        for (int k = 0; k < 32; k++) {
            float4 a0 = *(float4*)&Xs[k][ty * 4];
            float4 a1 = *(float4*)&Xs[k][64 + ty * 4];
            float4 b0 = *(float4*)&Wsm[k][tx * 4];
            float4 b1 = *(float4*)&Wsm[k][64 + tx * 4];
            float xf[8] = {a0.x, a0.y, a0.z, a0.w, a1.x, a1.y, a1.z, a1.w};
            float wf[8] = {b0.x, b0.y, b0.z, b0.w, b1.x, b1.y, b1.z, b1.w};
#pragma unroll
            for (int i = 0; i < 8; i++)
#pragma unroll
                for (int j = 0; j < 8; j++)
                    acc[i][j] += xf[i] * wf[j];
        }
        if (tid < 128) {
            float s = 0.f;
#pragma unroll
            for (int k = 0; k < 32; k++) s += Xs[k][tid] * Wcs[k];
            cacc += s;
        }
        __syncthreads();
    }

#pragma unroll
    for (int i = 0; i < 8; i++) {
        int r = (i < 4) ? ty * 4 + i : 64 + ty * 4 + (i - 4);
        float4 o0 = make_float4(fmaxf(acc[i][0], 0.f), fmaxf(acc[i][1], 0.f),
                                fmaxf(acc[i][2], 0.f), fmaxf(acc[i][3], 0.f));
        float4 o1 = make_float4(fmaxf(acc[i][4], 0.f), fmaxf(acc[i][5], 0.f),
                                fmaxf(acc[i][6], 0.f), fmaxf(acc[i][7], 0.f));
        *(float4*)(g_hidden + (size_t)(t0 + r) * RDIM + tx * 4) = o0;
        *(float4*)(g_hidden + (size_t)(t0 + r) * RDIM + 64 + tx * 4) = o1;
    }
    if (tid < 128) {
        float zc = cacc + bc[0];
        float c = 1.f / (1.f + expf(-zc));
        float bf = 4.f + 28.f * c * c;
        int b = (int)floorf(bf);
        g_budget[t0 + tid] = b;
        out_b[t0 + tid] = (float)b;
    }
}

// ---------------- K2: approx scores via fp16 mma.sync m16n8k16 ----------------
// B staged as half2 k-pairs, rows = k/2, stride BSTR2 (72) half2 -> conflict-free
__device__ __forceinline__ void storeB_h(char* sBb, const float4* pre, int tid) {
#pragma unroll
    for (int i = 0; i < 8; i++) {
        int id = tid + i * 256;
        int k = id >> 4, ng = id & 15;
        __half hv[4] = {__float2half_rn(pre[i].x), __float2half_rn(pre[i].y),
                        __float2half_rn(pre[i].z), __float2half_rn(pre[i].w)};
        int rowp = k >> 1, klo = k & 1;
        char* base = sBb + (size_t)(rowp * BSTR2) * 4 + klo * 2;
#pragma unroll
        for (int j = 0; j < 4; j++)
            *(__half*)(base + (ng * 4 + j) * 4) = hv[j];
    }
}

__global__ __launch_bounds__(256, 2) void k_scores_mma(const float* __restrict__ Wsg,
                                                       const float* __restrict__ bs)
{
    extern __shared__ char smem[];
    unsigned* sA = (unsigned*)(smem + SM2_A);        // half2 words, frag order
    unsigned* sB = (unsigned*)(smem + SM2_B);        // half2 words, [k/2][BSTR2]
    const uint4* sA4 = (const uint4*)sA;

    const int tid = threadIdx.x;
    const int lane = tid & 31, wid = tid >> 5;
    const int warpM = wid & 3, warpN = wid >> 2;
    const int gid = lane >> 2, tig = lane & 3;
    const int t0 = blockIdx.x * 128;

    // stage A: hidden[128][128] -> fp16 m16n8k16 fragment order (one-time)
    // frag uint4 index: (mt*8 + kc)*32 + lane ; regs a0..a3
#pragma unroll
    for (int i = 0; i < 16; i++) {
        int id = tid + i * 256;
        int m = id >> 5, fg = id & 31;                 // k = fg*4 .. fg*4+3
        float4 v = *(const float4*)(g_hidden + (size_t)(t0 + m) * RDIM + fg * 4);
        __half2 h01 = __floats2half2_rn(v.x, v.y);
        __half2 h23 = __floats2half2_rn(v.z, v.w);
        int mt = m >> 4, rr = m & 15;
        int kc = fg >> 2;
        int j0 = (fg & 3) * 2;                         // half2 pair index within kc
        int khi = j0 >> 2;                             // same for j0 and j0+1
        int base = ((mt * 8 + kc) * 32 + (rr & 7) * 4);
        int regbase = (rr >> 3) | (khi << 1);
        sA[(base + (j0 & 3)) * 4 + regbase]       = *(unsigned*)&h01;
        sA[(base + ((j0 + 1) & 3)) * 4 + regbase] = *(unsigned*)&h23;
    }

    // prologue: stage B tile 0
    {
        float4 pre[8];
#pragma unroll
        for (int i = 0; i < 8; i++) {
            int id = tid + i * 256;
            int k = id >> 4, ng = id & 15;
            pre[i] = *(const float4*)(Wsg + (size_t)k * NSLOT + ng * 4);
        }
        storeB_h((char*)sB, pre, tid);
    }
    __syncthreads();

    for (int nt = 0; nt < 64; nt++) {
        const int nbase = nt * 64;

        float4 pre[8];
        if (nt < 63) {
#pragma unroll
            for (int i = 0; i < 8; i++) {
                int id = tid + i * 256;
                int k = id >> 4, ng = id & 15;
                pre[i] = *(const float4*)(Wsg + (size_t)k * NSLOT + nbase + 64 + ng * 4);
            }
        }

        float c[2][4][4];
#pragma unroll
        for (int mi = 0; mi < 2; mi++)
#pragma unroll
            for (int ni = 0; ni < 4; ni++)
#pragma unroll
                for (int q = 0; q < 4; q++) c[mi][ni][q] = 0.f;

        const int colB = warpN * 32 + gid;

#pragma unroll
        for (int kc = 0; kc < 8; kc++) {
            uint4 af[2];
#pragma unroll
            for (int mi = 0; mi < 2; mi++)
                af[mi] = sA4[((warpM * 2 + mi) * 8 + kc) * 32 + lane];

            unsigned bf[4][2];
            const unsigned* bR0 = sB + (kc * 8 + tig) * BSTR2 + colB;
            const unsigned* bR1 = bR0 + 4 * BSTR2;
#pragma unroll
            for (int ni = 0; ni < 4; ni++) {
                bf[ni][0] = bR0[ni * 8];
                bf[ni][1] = bR1[ni * 8];
            }
#pragma unroll
            for (int mi = 0; mi < 2; mi++)
#pragma unroll
                for (int ni = 0; ni < 4; ni++)
                    MMA_F16(c[mi][ni], (const unsigned*)&af[mi], bf[ni]);
        }

        // epilogue: bias (L2) + store approx scores (fp16)
#pragma unroll
        for (int mi = 0; mi < 2; mi++) {
            int row = t0 + warpM * 32 + mi * 16 + gid;
#pragma unroll
            for (int ni = 0; ni < 4; ni++) {
                int col = nbase + warpN * 32 + ni * 8 + tig * 2;
                float b0 = __ldg(bs + col), b1 = __ldg(bs + col + 1);
                g_scores_h2[((size_t)row * NSLOT + col) >> 1] =
                    __floats2half2_rn(c[mi][ni][0] + b0, c[mi][ni][1] + b1);
                g_scores_h2[((size_t)(row + 8) * NSLOT + col) >> 1] =
                    __floats2half2_rn(c[mi][ni][2] + b0, c[mi][ni][3] + b1);
            }
        }

        __syncthreads();
        if (nt < 63) storeB_h((char*)sB, pre, tid);
        __syncthreads();
    }
}

// ---------------- K3: fp16 candidates + R1-arithmetic exact refine (unchanged) ----------------
__global__ __launch_bounds__(256) void k_topk(float* __restrict__ out_idx,
                                              float* __restrict__ out_w,
                                              const float* __restrict__ bsg)
{
    __shared__ unsigned skey[2048];
    __shared__ u64      cand[256];
    __shared__ float    hrow[128];
    __shared__ float    fred[8], f2red[8];
    __shared__ int      ired[8];
    __shared__ unsigned s_cnt;
    __shared__ int      s_best;

    const int t = blockIdx.x;
    const int tid = threadIdx.x, lane = tid & 31, wid = tid >> 5;
    const uint4* rowv = (const uint4*)(g_scores_h + (size_t)t * NSLOT);

    if (tid < 32)
        *(float4*)&hrow[tid * 4] = *(const float4*)(g_hidden + (size_t)t * RDIM + tid * 4);

    float s = 0.f, s2 = 0.f;
#pragma unroll
    for (int i = 0; i < 2; i++) {
        uint4 v = rowv[tid + i * 256];
        unsigned w[4] = {v.x, v.y, v.z, v.w};
        unsigned pk[4];
#pragma unroll
        for (int j = 0; j < 4; j++) {
            float2 f2 = __half22float2(*(__half2*)&w[j]);
            s += f2.x + f2.y;
            s2 += f2.x * f2.x + f2.y * f2.y;
            pk[j] = key16(w[j] & 0xFFFFu) | (key16(w[j] >> 16) << 16);
        }
        *(uint4*)&skey[(tid + i * 256) * 4] = make_uint4(pk[0], pk[1], pk[2], pk[3]);
    }
    s = warpReduceSumF(s);
    s2 = warpReduceSumF(s2);
    if (lane == 0) { fred[wid] = s; f2red[wid] = s2; }
    __syncthreads();
    float ss = 0.f, ss2 = 0.f;
#pragma unroll
    for (int i = 0; i < 8; i++) { ss += fred[i]; ss2 += f2red[i]; }
    const float mean = ss * (1.f / NSLOT);
    const float sigma = sqrtf(fmaxf(ss2 * (1.f / NSLOT) - mean * mean, 0.f)) + 1e-20f;

    auto countGreater = [&](unsigned thrKey) -> int {
        int c = 0;
#pragma unroll
        for (int i = 0; i < 2; i++) {
            uint4 k4 = *(uint4*)&skey[(tid + i * 256) * 4];
            unsigned w[4] = {k4.x, k4.y, k4.z, k4.w};
#pragma unroll
            for (int j = 0; j < 4; j++)
                c += ((w[j] & 0xFFFFu) > thrKey) + ((w[j] >> 16) > thrKey);
        }
        c = warpReduceSumI(c);
        __syncthreads();
        if (lane == 0) ired[wid] = c;
        __syncthreads();
        int tot = 0;
#pragma unroll
        for (int i = 0; i < 8; i++) tot += ired[i];
        return tot;
    };

    unsigned thrKey = 0;
    int cnt = 0;
    bool ok = false;
    float zf = 2.2f;
    for (int a = 0; a < 4; a++) {
        __half th = __float2half_rn(mean + zf * sigma);
        unsigned tk = key16((unsigned)__half_as_ushort(th));
        int c = countGreater(tk);
        if (c >= KSEL && c <= 256) { thrKey = tk; cnt = c; ok = true; break; }
        zf += (c < KSEL) ? -0.6f : 0.45f;
    }

    bool tiePath = false;
    unsigned Tkey = 0;
    if (!ok) {
        unsigned K = 0;
        for (int bit = 15; bit >= 0; bit--) {
            unsigned trial = K | (1u << bit);
            if (countGreater(trial) >= KSEL) K = trial;
        }
        int c = countGreater(K);
        if (c <= 256) {
            thrKey = K; cnt = c; ok = true;
        } else {
            tiePath = true;
            Tkey = K + 1u;
            thrKey = Tkey;
            cnt = countGreater(Tkey);
        }
    }

    if (tid == 0) s_cnt = 0;
    __syncthreads();
    {
        unsigned kk[16];
#pragma unroll
        for (int i = 0; i < 2; i++) {
            uint4 k4 = *(uint4*)&skey[(tid + i * 256) * 4];
            unsigned w[4] = {k4.x, k4.y, k4.z, k4.w};
#pragma unroll
            for (int j = 0; j < 4; j++) {
                kk[i * 8 + j * 2 + 0] = w[j] & 0xFFFFu;
                kk[i * 8 + j * 2 + 1] = w[j] >> 16;
            }
        }
        unsigned my = 0;
#pragma unroll
        for (int q = 0; q < 16; q++) my += (kk[q] > thrKey) ? 1u : 0u;
        unsigned pre = my;
#pragma unroll
        for (int o = 1; o < 32; o <<= 1) {
            unsigned tt = __shfl_up_sync(0xffffffffu, pre, o);
            if (lane >= o) pre += tt;
        }
        unsigned wtot = __shfl_sync(0xffffffffu, pre, 31);
        unsigned wbase = 0;
        if (lane == 31 && wtot > 0) wbase = atomicAdd(&s_cnt, wtot);
        wbase = __shfl_sync(0xffffffffu, wbase, 31);
        unsigned pos = wbase + pre - my;
        if (my > 0) {
#pragma unroll
            for (int q = 0; q < 16; q++) {
                if (kk[q] > thrKey) {
                    if (pos < 256) {
                        unsigned idx = (unsigned)((tid + (q >> 3) * 256) * 8 + (q & 7));
                        cand[pos] = ((u64)kk[q] << 12) | (u64)(4095u - idx);
                    }
                    pos++;
                }
            }
        }
    }
    __syncthreads();

    if (tiePath) {
        int lastIdx = -1;
        for (int e = cnt; e < KSEL; e++) {
            int best = 0x7FFFFFFF;
#pragma unroll
            for (int i = 0; i < 2; i++) {
                uint4 k4 = *(uint4*)&skey[(tid + i * 256) * 4];
                unsigned w[4] = {k4.x, k4.y, k4.z, k4.w};
#pragma unroll
                for (int j = 0; j < 4; j++) {
                    int idx0 = (tid + i * 256) * 8 + j * 2;
                    unsigned lo = w[j] & 0xFFFFu, hi = w[j] >> 16;
                    if (lo == Tkey && idx0 > lastIdx && idx0 < best) best = idx0;
                    if (hi == Tkey && idx0 + 1 > lastIdx && idx0 + 1 < best) best = idx0 + 1;
                }
            }
            best = warpReduceMinI(best);
            __syncthreads();
            if (lane == 0) ired[wid] = best;
            __syncthreads();
            if (tid == 0) {
                int bb = ired[0];
#pragma unroll
                for (int i = 1; i < 8; i++) bb = (ired[i] < bb) ? ired[i] : bb;
                s_best = bb;
                cand[e] = ((u64)Tkey << 12) | (u64)(4095u - (unsigned)bb);
            }
            __syncthreads();
            lastIdx = s_best;
        }
        cnt = KSEL;
        __syncthreads();
    }

    // exact refine: one THREAD per candidate, bias-first, k-serial fmaf
    const int ncand = (cnt < 256) ? cnt : 256;
    if (tid < ncand) {
        unsigned idxv = 4095u - (unsigned)(cand[tid] & 0xFFFull);
        const float4* wv = (const float4*)(g_wsT + (size_t)idxv * RDIM);
        float acc = __ldg(bsg + idxv);
#pragma unroll
        for (int q = 0; q < 32; q++) {
            float4 w4 = __ldg(wv + q);
            float4 h4 = *(const float4*)&hrow[q * 4];
            acc = fmaf(h4.x, w4.x, acc);
            acc = fmaf(h4.y, w4.y, acc);
            acc = fmaf(h4.z, w4.z, acc);
            acc = fmaf(h4.w, w4.w, acc);
        }
        unsigned b = __float_as_uint(acc);
        unsigned k = b ^ ((unsigned)((int)b >> 31) | 0x80000000u);
        cand[tid] = ((u64)k << 12) | (u64)(4095u - idxv);
    }
    __syncthreads();

    // warp 0: exact top-32 extraction + outputs
    if (wid == 0) {
        u64 cl[8];
#pragma unroll
        for (int q = 0; q < 8; q++) {
            int p = lane + 32 * q;
            cl[q] = (p < ncand) ? cand[p] : 0ull;
        }
#pragma unroll
        for (int a = 1; a < 8; a++)
#pragma unroll
            for (int b2 = a; b2 > 0; b2--) {
                u64 lo = cl[b2 - 1] < cl[b2] ? cl[b2 - 1] : cl[b2];
                u64 hi = cl[b2 - 1] < cl[b2] ? cl[b2] : cl[b2 - 1];
                cl[b2 - 1] = hi; cl[b2] = lo;
            }
        u64 mysel = 0;
#pragma unroll
        for (int r2 = 0; r2 < MAXK; r2++) {
            u64 wb = warpReduceMaxU64(cl[0]);
            if (cl[0] == wb) {
#pragma unroll
                for (int q = 0; q < 7; q++) cl[q] = cl[q + 1];
                cl[7] = 0ull;
            }
            if (lane == r2) mysel = wb;
        }

        unsigned keyv = (unsigned)(mysel >> 12);
        unsigned idxv = 4095u - (unsigned)(mysel & 0xFFFull);
        unsigned fb = (keyv & 0x80000000u) ? (keyv ^ 0x80000000u) : ~keyv;
        float val = __uint_as_float(fb);

        int b = g_budget[t];
        float v0 = __shfl_sync(0xffffffffu, val, 0);
        bool msk = lane < b;
        float ev = msk ? __expf(val - v0) : 0.f;
        float zz = warpReduceSumF(ev);
        float w = msk ? ev / zz : 0.f;

        out_idx[(size_t)t * MAXK + lane] = (float)idxv;
        out_w[(size_t)t * MAXK + lane] = w;
        if (msk) atomicAdd(&g_counts[idxv], 1.0f);
    }
}

// ---------------- K4: aux (fp16 approx scores, unchanged) ----------------
__global__ __launch_bounds__(256) void k_aux()
{
    __shared__ float sredZ[8], sredD[8], s_m;
    const int t = blockIdx.x;
    const int tid = threadIdx.x, lane = tid & 31, wid = tid >> 5;
    const uint4* rowv = (const uint4*)(g_scores_h + (size_t)t * NSLOT);

    float fv[16];
    float m = -1e30f;
#pragma unroll
    for (int i = 0; i < 2; i++) {
        uint4 v = rowv[tid + i * 256];
        unsigned w[4] = {v.x, v.y, v.z, v.w};
#pragma unroll
        for (int j = 0; j < 4; j++) {
            float2 f2 = __half22float2(*(__half2*)&w[j]);
            fv[i * 8 + j * 2 + 0] = f2.x;
            fv[i * 8 + j * 2 + 1] = f2.y;
            m = fmaxf(m, fmaxf(f2.x, f2.y));
        }
    }
    m = warpReduceMaxF(m);
    if (lane == 0) sredZ[wid] = m;
    __syncthreads();
    if (tid == 0) {
        float mm = sredZ[0];
#pragma unroll
        for (int i = 1; i < 8; i++) mm = fmaxf(mm, sredZ[i]);
        s_m = mm;
    }
    __syncthreads();
    m = s_m;

    float z = 0.f, d = 0.f;
#pragma unroll
    for (int i = 0; i < 2; i++) {
#pragma unroll
        for (int j = 0; j < 2; j++) {
            float4 c = g_counts_v[(tid + i * 256) * 2 + j];
            float e0 = __expf(fv[i * 8 + j * 4 + 0] - m);
            float e1 = __expf(fv[i * 8 + j * 4 + 1] - m);
            float e2 = __expf(fv[i * 8 + j * 4 + 2] - m);
            float e3 = __expf(fv[i * 8 + j * 4 + 3] - m);
            z += e0 + e1 + e2 + e3;
            d += e0 * c.x + e1 * c.y + e2 * c.z + e3 * c.w;
        }
    }
    z = warpReduceSumF(z);
    d = warpReduceSumF(d);
    if (lane == 0) { sredZ[wid] = z; sredD[wid] = d; }
    __syncthreads();
    if (tid == 0) {
        float zz = 0.f, dd = 0.f;
#pragma unroll
        for (int i = 0; i < 8; i++) { zz += sredZ[i]; dd += sredD[i]; }
        float contrib = (dd / zz) * ((float)NSLOT / ((float)TOK * (float)TOK));
        atomicAdd(&g_aux, contrib);
    }
}

// ---------------- K5 ----------------
__global__ void k_finish(float* __restrict__ out_aux)
{
    if (threadIdx.x == 0) out_aux[0] = g_aux;
}

// ---------------- launch ----------------
extern "C" void kernel_launch(void* const* d_in, const int* in_sizes, int n_in,
                              void* d_out, int out_size)
{
    const float* x  = (const float*)d_in[0];
    const float* Wc = (const float*)d_in[1];
    const float* bc = (const float*)d_in[2];
    const float* Wh = (const float*)d_in[3];
    const float* bh = (const float*)d_in[4];
    const float* Ws = (const float*)d_in[5];
    const float* bs = (const float*)d_in[6];

    float* out     = (float*)d_out;
    float* out_idx = out;
    float* out_w   = out + TOK * MAXK;
    float* out_b   = out + 2 * TOK * MAXK;
    float* out_aux = out + 2 * TOK * MAXK + TOK;

    cudaFuncSetAttribute(k_scores_mma, cudaFuncAttributeMaxDynamicSharedMemorySize, SM2_TOTAL);

    k_init<<<(NSLOT + 255) / 256, 256>>>();
    k_transpose<<<dim3(128, 4), 256>>>(Ws);
    k_hidden<<<TOK / 128, 256>>>(x, Wc, bc, Wh, bh, out_b);
    k_scores_mma<<<TOK / 128, 256, SM2_TOTAL>>>(Ws, bs);
    k_topk<<<TOK, 256>>>(out_idx, out_w, bs);
    k_aux<<<TOK, 256>>>();
    k_finish<<<1, 32>>>(out_aux);
}

// round 15
// speedup vs baseline: 2.0341x; 1.0916x over previous
#include <cuda_runtime.h>
#include <cuda_fp16.h>
#include <cstdint>

#define TOK   32768
#define DIN   1024
#define RDIM  128
#define NSLOT 4096
#define MAXK  32
#define KSEL  48

typedef unsigned long long u64;

// ---------------- scratch ----------------
__device__ float   g_hidden[TOK * RDIM];
__device__ __half2 g_scores_h2[TOK * NSLOT / 2];   // 256 MB approx scores (fp16)
__device__ float   g_wsT[NSLOT * RDIM];            // 2 MB W_s transposed
__device__ int     g_budget[TOK];
__device__ float4  g_counts_v[NSLOT / 4];
__device__ float   g_aux;

#define g_scores_h ((__half*)g_scores_h2)
#define g_counts   ((float*)g_counts_v)

// ---------------- fp16 MMA ----------------
#define MMA_F16(c, a, b) \
    asm volatile("mma.sync.aligned.m16n8k16.row.col.f32.f16.f16.f32 " \
        "{%0,%1,%2,%3}, {%4,%5,%6,%7}, {%8,%9}, {%0,%1,%2,%3};" \
        : "+f"((c)[0]), "+f"((c)[1]), "+f"((c)[2]), "+f"((c)[3]) \
        : "r"((a)[0]), "r"((a)[1]), "r"((a)[2]), "r"((a)[3]), \
          "r"((b)[0]), "r"((b)[1]))

// smem: sA frag-order 32 KB, sB half2[64][72] = 18 KB
#define BSTR2     72
#define SM2_A     0
#define SM2_B     32768
#define SM2_TOTAL (32768 + 64 * BSTR2 * 4)   // 51200

// 16-bit sortable key for fp16 bits
__device__ __forceinline__ unsigned key16(unsigned h) {
    unsigned m = ((h >> 15) & 1u) ? 0xFFFFu : 0x8000u;
    return (h ^ m) & 0xFFFFu;
}

// ---------------- reductions ----------------
__device__ __forceinline__ float warpReduceMaxF(float v) {
#pragma unroll
    for (int o = 16; o > 0; o >>= 1) v = fmaxf(v, __shfl_xor_sync(0xffffffffu, v, o));
    return v;
}
__device__ __forceinline__ float warpReduceSumF(float v) {
#pragma unroll
    for (int o = 16; o > 0; o >>= 1) v += __shfl_xor_sync(0xffffffffu, v, o);
    return v;
}
__device__ __forceinline__ int warpReduceSumI(int v) {
#pragma unroll
    for (int o = 16; o > 0; o >>= 1) v += __shfl_xor_sync(0xffffffffu, v, o);
    return v;
}
__device__ __forceinline__ int warpReduceMinI(int v) {
#pragma unroll
    for (int o = 16; o > 0; o >>= 1) {
        int t = __shfl_xor_sync(0xffffffffu, v, o);
        v = (t < v) ? t : v;
    }
    return v;
}
__device__ __forceinline__ u64 warpReduceMaxU64(u64 v) {
#pragma unroll
    for (int o = 16; o > 0; o >>= 1) {
        u64 t = __shfl_xor_sync(0xffffffffu, v, o);
        v = (t > v) ? t : v;
    }
    return v;
}

// ---------------- K0 ----------------
__global__ void k_init() {
    int i = blockIdx.x * blockDim.x + threadIdx.x;
    if (i < NSLOT) g_counts[i] = 0.f;
    if (i == 0)    g_aux = 0.f;
}

// ---------------- K0b: transpose W_s -> g_wsT[N][R] ----------------
__global__ __launch_bounds__(256) void k_transpose(const float* __restrict__ Wsg) {
    __shared__ float tile[32][33];
    const int bx = blockIdx.x;
    const int by = blockIdx.y;
    const int tx = threadIdx.x & 31, ty = threadIdx.x >> 5;
#pragma unroll
    for (int i = 0; i < 4; i++) {
        int r = by * 32 + ty + i * 8;
        tile[ty + i * 8][tx] = Wsg[(size_t)r * NSLOT + bx * 32 + tx];
    }
    __syncthreads();
#pragma unroll
    for (int i = 0; i < 4; i++) {
        int n = bx * 32 + ty + i * 8;
        g_wsT[(size_t)n * RDIM + by * 32 + tx] = tile[tx][ty + i * 8];
    }
}

// ---------------- K1: hidden GEMM + budget (unchanged) ----------------
__global__ __launch_bounds__(256) void k_hidden(
    const float* __restrict__ x,  const float* __restrict__ Wc, const float* __restrict__ bc,
    const float* __restrict__ Wh, const float* __restrict__ bh, float* __restrict__ out_b)
{
    __shared__ float Xs[32][132];
    __shared__ float Wsm[32][128];
    __shared__ float Wcs[32];

    const int tid = threadIdx.x;
    const int tx = tid & 15, ty = tid >> 4;
    const int t0 = blockIdx.x * 128;

    float acc[8][8];
#pragma unroll
    for (int j = 0; j < 8; j++) {
        int c = (j < 4) ? tx * 4 + j : 64 + tx * 4 + (j - 4);
        float b = bh[c];
#pragma unroll
        for (int i = 0; i < 8; i++) acc[i][j] = b;
    }
    float cacc = 0.f;

    for (int kt = 0; kt < 32; kt++) {
#pragma unroll
        for (int i = 0; i < 4; i++) {
            int id = tid + i * 256;
            int token = id >> 3, kg = id & 7;
            float4 f = *(const float4*)(x + (size_t)(t0 + token) * DIN + kt * 32 + kg * 4);
            Xs[kg * 4 + 0][token] = f.x; Xs[kg * 4 + 1][token] = f.y;
            Xs[kg * 4 + 2][token] = f.z; Xs[kg * 4 + 3][token] = f.w;
        }
#pragma unroll
        for (int i = 0; i < 4; i++) {
            int id = tid + i * 256;
            int rowk = id >> 5, ng = id & 31;
            *(float4*)&Wsm[rowk][ng * 4] =
                *(const float4*)(Wh + (size_t)(kt * 32 + rowk) * RDIM + ng * 4);
        }
        if (tid < 32) Wcs[tid] = Wc[kt * 32 + tid];
        __syncthreads();

#pragma unroll
        for (int k = 0; k < 32; k++) {
            float4 a0 = *(float4*)&Xs[k][ty * 4];
            float4 a1 = *(float4*)&Xs[k][64 + ty * 4];
            float4 b0 = *(float4*)&Wsm[k][tx * 4];
            float4 b1 = *(float4*)&Wsm[k][64 + tx * 4];
            float xf[8] = {a0.x, a0.y, a0.z, a0.w, a1.x, a1.y, a1.z, a1.w};
            float wf[8] = {b0.x, b0.y, b0.z, b0.w, b1.x, b1.y, b1.z, b1.w};
#pragma unroll
            for (int i = 0; i < 8; i++)
#pragma unroll
                for (int j = 0; j < 8; j++)
                    acc[i][j] += xf[i] * wf[j];
        }
        if (tid < 128) {
            float s = 0.f;
#pragma unroll
            for (int k = 0; k < 32; k++) s += Xs[k][tid] * Wcs[k];
            cacc += s;
        }
        __syncthreads();
    }

#pragma unroll
    for (int i = 0; i < 8; i++) {
        int r = (i < 4) ? ty * 4 + i : 64 + ty * 4 + (i - 4);
        float4 o0 = make_float4(fmaxf(acc[i][0], 0.f), fmaxf(acc[i][1], 0.f),
                                fmaxf(acc[i][2], 0.f), fmaxf(acc[i][3], 0.f));
        float4 o1 = make_float4(fmaxf(acc[i][4], 0.f), fmaxf(acc[i][5], 0.f),
                                fmaxf(acc[i][6], 0.f), fmaxf(acc[i][7], 0.f));
        *(float4*)(g_hidden + (size_t)(t0 + r) * RDIM + tx * 4) = o0;
        *(float4*)(g_hidden + (size_t)(t0 + r) * RDIM + 64 + tx * 4) = o1;
    }
    if (tid < 128) {
        float zc = cacc + bc[0];
        float c = 1.f / (1.f + expf(-zc));
        float bf = 4.f + 28.f * c * c;
        int b = (int)floorf(bf);
        g_budget[t0 + tid] = b;
        out_b[t0 + tid] = (float)b;
    }
}

// ---------------- K2: approx scores via fp16 mma.sync m16n8k16 ----------------
// B staged as half2 k-pairs: thread loads 2 adjacent k-rows, packs 4 half2,
// stores one uint4 -> coalesced, conflict-free.
__device__ __forceinline__ void loadB_pair(float4* pre, const float* __restrict__ Wsg,
                                           int nbase, int tid) {
#pragma unroll
    for (int i = 0; i < 4; i++) {
        int id = tid + i * 256;            // 1024 (row-pair, col-group) items
        int rp = id >> 4, ng = id & 15;
        pre[i * 2 + 0] = *(const float4*)(Wsg + (size_t)(rp * 2) * NSLOT + nbase + ng * 4);
        pre[i * 2 + 1] = *(const float4*)(Wsg + (size_t)(rp * 2 + 1) * NSLOT + nbase + ng * 4);
    }
}
__device__ __forceinline__ void storeB_pair(unsigned* sB, const float4* pre, int tid) {
#pragma unroll
    for (int i = 0; i < 4; i++) {
        int id = tid + i * 256;
        int rp = id >> 4, ng = id & 15;
        const float4& lo = pre[i * 2 + 0];
        const float4& hi = pre[i * 2 + 1];
        __half2 p0 = __halves2half2(__float2half_rn(lo.x), __float2half_rn(hi.x));
        __half2 p1 = __halves2half2(__float2half_rn(lo.y), __float2half_rn(hi.y));
        __half2 p2 = __halves2half2(__float2half_rn(lo.z), __float2half_rn(hi.z));
        __half2 p3 = __halves2half2(__float2half_rn(lo.w), __float2half_rn(hi.w));
        *(uint4*)&sB[rp * BSTR2 + ng * 4] =
            make_uint4(*(unsigned*)&p0, *(unsigned*)&p1, *(unsigned*)&p2, *(unsigned*)&p3);
    }
}

__global__ __launch_bounds__(256, 2) void k_scores_mma(const float* __restrict__ Wsg,
                                                       const float* __restrict__ bs)
{
    extern __shared__ char smem[];
    unsigned* sA = (unsigned*)(smem + SM2_A);        // half2 words, frag order
    unsigned* sB = (unsigned*)(smem + SM2_B);        // half2 words, [k/2][BSTR2]
    const uint4* sA4 = (const uint4*)sA;

    const int tid = threadIdx.x;
    const int lane = tid & 31, wid = tid >> 5;
    const int warpM = wid & 3, warpN = wid >> 2;
    const int gid = lane >> 2, tig = lane & 3;
    const int t0 = blockIdx.x * 128;

    // stage A: hidden[128][128] -> fp16 m16n8k16 fragment order (one-time)
#pragma unroll
    for (int i = 0; i < 16; i++) {
        int id = tid + i * 256;
        int m = id >> 5, fg = id & 31;
        float4 v = *(const float4*)(g_hidden + (size_t)(t0 + m) * RDIM + fg * 4);
        __half2 h01 = __floats2half2_rn(v.x, v.y);
        __half2 h23 = __floats2half2_rn(v.z, v.w);
        int mt = m >> 4, rr = m & 15;
        int kc = fg >> 2;
        int j0 = (fg & 3) * 2;
        int khi = j0 >> 2;
        int base = ((mt * 8 + kc) * 32 + (rr & 7) * 4);
        int regbase = (rr >> 3) | (khi << 1);
        sA[(base + (j0 & 3)) * 4 + regbase]       = *(unsigned*)&h01;
        sA[(base + ((j0 + 1) & 3)) * 4 + regbase] = *(unsigned*)&h23;
    }

    // prologue: stage B tile 0
    {
        float4 pre[8];
        loadB_pair(pre, Wsg, 0, tid);
        storeB_pair(sB, pre, tid);
    }
    __syncthreads();

    for (int nt = 0; nt < 64; nt++) {
        const int nbase = nt * 64;

        float4 pre[8];
        if (nt < 63) loadB_pair(pre, Wsg, nbase + 64, tid);

        float c[2][4][4];
#pragma unroll
        for (int mi = 0; mi < 2; mi++)
#pragma unroll
            for (int ni = 0; ni < 4; ni++)
#pragma unroll
                for (int q = 0; q < 4; q++) c[mi][ni][q] = 0.f;

        const int colB = warpN * 32 + gid;

#pragma unroll
        for (int kc = 0; kc < 8; kc++) {
            uint4 af[2];
#pragma unroll
            for (int mi = 0; mi < 2; mi++)
                af[mi] = sA4[((warpM * 2 + mi) * 8 + kc) * 32 + lane];

            unsigned bf[4][2];
            const unsigned* bR0 = sB + (kc * 8 + tig) * BSTR2 + colB;
            const unsigned* bR1 = bR0 + 4 * BSTR2;
#pragma unroll
            for (int ni = 0; ni < 4; ni++) {
                bf[ni][0] = bR0[ni * 8];
                bf[ni][1] = bR1[ni * 8];
            }
#pragma unroll
            for (int mi = 0; mi < 2; mi++)
#pragma unroll
                for (int ni = 0; ni < 4; ni++)
                    MMA_F16(c[mi][ni], (const unsigned*)&af[mi], bf[ni]);
        }

        // epilogue: bias (L2) + store approx scores (fp16)
#pragma unroll
        for (int mi = 0; mi < 2; mi++) {
            int row = t0 + warpM * 32 + mi * 16 + gid;
#pragma unroll
            for (int ni = 0; ni < 4; ni++) {
                int col = nbase + warpN * 32 + ni * 8 + tig * 2;
                float b0 = __ldg(bs + col), b1 = __ldg(bs + col + 1);
                g_scores_h2[((size_t)row * NSLOT + col) >> 1] =
                    __floats2half2_rn(c[mi][ni][0] + b0, c[mi][ni][1] + b1);
                g_scores_h2[((size_t)(row + 8) * NSLOT + col) >> 1] =
                    __floats2half2_rn(c[mi][ni][2] + b0, c[mi][ni][3] + b1);
            }
        }

        __syncthreads();
        if (nt < 63) storeB_pair(sB, pre, tid);
        __syncthreads();
    }
}

// ---------------- K3: fp16 candidates + exact refine (128-thread blocks) ----------------
__global__ __launch_bounds__(128) void k_topk(float* __restrict__ out_idx,
                                              float* __restrict__ out_w,
                                              const float* __restrict__ bsg)
{
    __shared__ unsigned skey[2048];     // 2x16-bit keys per word (8 KB)
    __shared__ u64      cand[256];
    __shared__ float    hrow[128];
    __shared__ float    fred[4], f2red[4];
    __shared__ int      ired[4];
    __shared__ unsigned s_cnt;
    __shared__ int      s_best;

    const int t = blockIdx.x;
    const int tid = threadIdx.x, lane = tid & 31, wid = tid >> 5;
    const uint4* rowv = (const uint4*)(g_scores_h + (size_t)t * NSLOT);

    if (tid < 32)
        *(float4*)&hrow[tid * 4] = *(const float4*)(g_hidden + (size_t)t * RDIM + tid * 4);

    // load row (fp16, 32 vals/thread), build packed keys + stats
    float s = 0.f, s2 = 0.f;
#pragma unroll
    for (int i = 0; i < 4; i++) {
        uint4 v = rowv[tid + i * 128];
        unsigned w[4] = {v.x, v.y, v.z, v.w};
        unsigned pk[4];
#pragma unroll
        for (int j = 0; j < 4; j++) {
            float2 f2 = __half22float2(*(__half2*)&w[j]);
            s += f2.x + f2.y;
            s2 += f2.x * f2.x + f2.y * f2.y;
            pk[j] = key16(w[j] & 0xFFFFu) | (key16(w[j] >> 16) << 16);
        }
        *(uint4*)&skey[(tid + i * 128) * 4] = make_uint4(pk[0], pk[1], pk[2], pk[3]);
    }
    s = warpReduceSumF(s);
    s2 = warpReduceSumF(s2);
    if (lane == 0) { fred[wid] = s; f2red[wid] = s2; }
    __syncthreads();
    float ss = 0.f, ss2 = 0.f;
#pragma unroll
    for (int i = 0; i < 4; i++) { ss += fred[i]; ss2 += f2red[i]; }
    const float mean = ss * (1.f / NSLOT);
    const float sigma = sqrtf(fmaxf(ss2 * (1.f / NSLOT) - mean * mean, 0.f)) + 1e-20f;

    auto countGreater = [&](unsigned thrKey) -> int {
        int c = 0;
#pragma unroll
        for (int i = 0; i < 4; i++) {
            uint4 k4 = *(uint4*)&skey[(tid + i * 128) * 4];
            unsigned w[4] = {k4.x, k4.y, k4.z, k4.w};
#pragma unroll
            for (int j = 0; j < 4; j++)
                c += ((w[j] & 0xFFFFu) > thrKey) + ((w[j] >> 16) > thrKey);
        }
        c = warpReduceSumI(c);
        __syncthreads();
        if (lane == 0) ired[wid] = c;
        __syncthreads();
        int tot = 0;
#pragma unroll
        for (int i = 0; i < 4; i++) tot += ired[i];
        return tot;
    };

    unsigned thrKey = 0;
    int cnt = 0;
    bool ok = false;
    float zf = 2.2f;
    for (int a = 0; a < 4; a++) {
        __half th = __float2half_rn(mean + zf * sigma);
        unsigned tk = key16((unsigned)__half_as_ushort(th));
        int c = countGreater(tk);
        if (c >= KSEL && c <= 256) { thrKey = tk; cnt = c; ok = true; break; }
        zf += (c < KSEL) ? -0.6f : 0.45f;
    }

    bool tiePath = false;
    unsigned Tkey = 0;
    if (!ok) {
        unsigned K = 0;
        for (int bit = 15; bit >= 0; bit--) {
            unsigned trial = K | (1u << bit);
            if (countGreater(trial) >= KSEL) K = trial;
        }
        int c = countGreater(K);
        if (c <= 256) {
            thrKey = K; cnt = c; ok = true;
        } else {
            tiePath = true;
            Tkey = K + 1u;
            thrKey = Tkey;
            cnt = countGreater(Tkey);
        }
    }

    // compaction pass
    if (tid == 0) s_cnt = 0;
    __syncthreads();
    {
        unsigned kk[32];
#pragma unroll
        for (int i = 0; i < 4; i++) {
            uint4 k4 = *(uint4*)&skey[(tid + i * 128) * 4];
            unsigned w[4] = {k4.x, k4.y, k4.z, k4.w};
#pragma unroll
            for (int j = 0; j < 4; j++) {
                kk[i * 8 + j * 2 + 0] = w[j] & 0xFFFFu;
                kk[i * 8 + j * 2 + 1] = w[j] >> 16;
            }
        }
        unsigned my = 0;
#pragma unroll
        for (int q = 0; q < 32; q++) my += (kk[q] > thrKey) ? 1u : 0u;
        unsigned pre = my;
#pragma unroll
        for (int o = 1; o < 32; o <<= 1) {
            unsigned tt = __shfl_up_sync(0xffffffffu, pre, o);
            if (lane >= o) pre += tt;
        }
        unsigned wtot = __shfl_sync(0xffffffffu, pre, 31);
        unsigned wbase = 0;
        if (lane == 31 && wtot > 0) wbase = atomicAdd(&s_cnt, wtot);
        wbase = __shfl_sync(0xffffffffu, wbase, 31);
        unsigned pos = wbase + pre - my;
        if (my > 0) {
#pragma unroll
            for (int q = 0; q < 32; q++) {
                if (kk[q] > thrKey) {
                    if (pos < 256) {
                        unsigned idx = (unsigned)((tid + (q >> 3) * 128) * 8 + (q & 7));
                        cand[pos] = ((u64)kk[q] << 12) | (u64)(4095u - idx);
                    }
                    pos++;
                }
            }
        }
    }
    __syncthreads();

    if (tiePath) {
        int lastIdx = -1;
        for (int e = cnt; e < KSEL; e++) {
            int best = 0x7FFFFFFF;
#pragma unroll
            for (int i = 0; i < 4; i++) {
                uint4 k4 = *(uint4*)&skey[(tid + i * 128) * 4];
                unsigned w[4] = {k4.x, k4.y, k4.z, k4.w};
#pragma unroll
                for (int j = 0; j < 4; j++) {
                    int idx0 = (tid + i * 128) * 8 + j * 2;
                    unsigned lo = w[j] & 0xFFFFu, hi = w[j] >> 16;
                    if (lo == Tkey && idx0 > lastIdx && idx0 < best) best = idx0;
                    if (hi == Tkey && idx0 + 1 > lastIdx && idx0 + 1 < best) best = idx0 + 1;
                }
            }
            best = warpReduceMinI(best);
            __syncthreads();
            if (lane == 0) ired[wid] = best;
            __syncthreads();
            if (tid == 0) {
                int bb = ired[0];
#pragma unroll
                for (int i = 1; i < 4; i++) bb = (ired[i] < bb) ? ired[i] : bb;
                s_best = bb;
                cand[e] = ((u64)Tkey << 12) | (u64)(4095u - (unsigned)bb);
            }
            __syncthreads();
            lastIdx = s_best;
        }
        cnt = KSEL;
        __syncthreads();
    }

    // exact refine: bias-first, k-serial fmaf (R1 arithmetic)
    const int ncand = (cnt < 256) ? cnt : 256;
    for (int j = tid; j < ncand; j += 128) {
        unsigned idxv = 4095u - (unsigned)(cand[j] & 0xFFFull);
        const float4* wv = (const float4*)(g_wsT + (size_t)idxv * RDIM);
        float acc = __ldg(bsg + idxv);
#pragma unroll
        for (int q = 0; q < 32; q++) {
            float4 w4 = __ldg(wv + q);
            float4 h4 = *(const float4*)&hrow[q * 4];
            acc = fmaf(h4.x, w4.x, acc);
            acc = fmaf(h4.y, w4.y, acc);
            acc = fmaf(h4.z, w4.z, acc);
            acc = fmaf(h4.w, w4.w, acc);
        }
        unsigned b = __float_as_uint(acc);
        unsigned k = b ^ ((unsigned)((int)b >> 31) | 0x80000000u);
        cand[j] = ((u64)k << 12) | (u64)(4095u - idxv);
    }
    __syncthreads();

    // warp 0: exact top-32 extraction + outputs
    if (wid == 0) {
        u64 cl[8];
#pragma unroll
        for (int q = 0; q < 8; q++) {
            int p = lane + 32 * q;
            cl[q] = (p < ncand) ? cand[p] : 0ull;
        }
#pragma unroll
        for (int a = 1; a < 8; a++)
#pragma unroll
            for (int b2 = a; b2 > 0; b2--) {
                u64 lo = cl[b2 - 1] < cl[b2] ? cl[b2 - 1] : cl[b2];
                u64 hi = cl[b2 - 1] < cl[b2] ? cl[b2] : cl[b2 - 1];
                cl[b2 - 1] = hi; cl[b2] = lo;
            }
        u64 mysel = 0;
#pragma unroll
        for (int r2 = 0; r2 < MAXK; r2++) {
            u64 wb = warpReduceMaxU64(cl[0]);
            if (cl[0] == wb) {
#pragma unroll
                for (int q = 0; q < 7; q++) cl[q] = cl[q + 1];
                cl[7] = 0ull;
            }
            if (lane == r2) mysel = wb;
        }

        unsigned keyv = (unsigned)(mysel >> 12);
        unsigned idxv = 4095u - (unsigned)(mysel & 0xFFFull);
        unsigned fb = (keyv & 0x80000000u) ? (keyv ^ 0x80000000u) : ~keyv;
        float val = __uint_as_float(fb);

        int b = g_budget[t];
        float v0 = __shfl_sync(0xffffffffu, val, 0);
        bool msk = lane < b;
        float ev = msk ? __expf(val - v0) : 0.f;
        float zz = warpReduceSumF(ev);
        float w = msk ? ev / zz : 0.f;

        out_idx[(size_t)t * MAXK + lane] = (float)idxv;
        out_w[(size_t)t * MAXK + lane] = w;
        if (msk) atomicAdd(&g_counts[idxv], 1.0f);
    }
}

// ---------------- K4: aux (fp16 approx scores, unchanged) ----------------
__global__ __launch_bounds__(256) void k_aux()
{
    __shared__ float sredZ[8], sredD[8], s_m;
    const int t = blockIdx.x;
    const int tid = threadIdx.x, lane = tid & 31, wid = tid >> 5;
    const uint4* rowv = (const uint4*)(g_scores_h + (size_t)t * NSLOT);

    float fv[16];
    float m = -1e30f;
#pragma unroll
    for (int i = 0; i < 2; i++) {
        uint4 v = rowv[tid + i * 256];
        unsigned w[4] = {v.x, v.y, v.z, v.w};
#pragma unroll
        for (int j = 0; j < 4; j++) {
            float2 f2 = __half22float2(*(__half2*)&w[j]);
            fv[i * 8 + j * 2 + 0] = f2.x;
            fv[i * 8 + j * 2 + 1] = f2.y;
            m = fmaxf(m, fmaxf(f2.x, f2.y));
        }
    }
    m = warpReduceMaxF(m);
    if (lane == 0) sredZ[wid] = m;
    __syncthreads();
    if (tid == 0) {
        float mm = sredZ[0];
#pragma unroll
        for (int i = 1; i < 8; i++) mm = fmaxf(mm, sredZ[i]);
        s_m = mm;
    }
    __syncthreads();
    m = s_m;

    float z = 0.f, d = 0.f;
#pragma unroll
    for (int i = 0; i < 2; i++) {
#pragma unroll
        for (int j = 0; j < 2; j++) {
            float4 c = g_counts_v[(tid + i * 256) * 2 + j];
            float e0 = __expf(fv[i * 8 + j * 4 + 0] - m);
            float e1 = __expf(fv[i * 8 + j * 4 + 1] - m);
            float e2 = __expf(fv[i * 8 + j * 4 + 2] - m);
            float e3 = __expf(fv[i * 8 + j * 4 + 3] - m);
            z += e0 + e1 + e2 + e3;
            d += e0 * c.x + e1 * c.y + e2 * c.z + e3 * c.w;
        }
    }
    z = warpReduceSumF(z);
    d = warpReduceSumF(d);
    if (lane == 0) { sredZ[wid] = z; sredD[wid] = d; }
    __syncthreads();
    if (tid == 0) {
        float zz = 0.f, dd = 0.f;
#pragma unroll
        for (int i = 0; i < 8; i++) { zz += sredZ[i]; dd += sredD[i]; }
        float contrib = (dd / zz) * ((float)NSLOT / ((float)TOK * (float)TOK));
        atomicAdd(&g_aux, contrib);
    }
}

// ---------------- K5 ----------------
__global__ void k_finish(float* __restrict__ out_aux)
{
    if (threadIdx.x == 0) out_aux[0] = g_aux;
}

// ---------------- launch ----------------
extern "C" void kernel_launch(void* const* d_in, const int* in_sizes, int n_in,
                              void* d_out, int out_size)
{
    const float* x  = (const float*)d_in[0];
    const float* Wc = (const float*)d_in[1];
    const float* bc = (const float*)d_in[2];
    const float* Wh = (const float*)d_in[3];
    const float* bh = (const float*)d_in[4];
    const float* Ws = (const float*)d_in[5];
    const float* bs = (const float*)d_in[6];

    float* out     = (float*)d_out;
    float* out_idx = out;
    float* out_w   = out + TOK * MAXK;
    float* out_b   = out + 2 * TOK * MAXK;
    float* out_aux = out + 2 * TOK * MAXK + TOK;

    cudaFuncSetAttribute(k_scores_mma, cudaFuncAttributeMaxDynamicSharedMemorySize, SM2_TOTAL);

    k_init<<<(NSLOT + 255) / 256, 256>>>();
    k_transpose<<<dim3(128, 4), 256>>>(Ws);
    k_hidden<<<TOK / 128, 256>>>(x, Wc, bc, Wh, bh, out_b);
    k_scores_mma<<<TOK / 128, 256, SM2_TOTAL>>>(Ws, bs);
    k_topk<<<TOK, 128>>>(out_idx, out_w, bs);
    k_aux<<<TOK, 256>>>();
    k_finish<<<1, 32>>>(out_aux);
}

// round 16
// speedup vs baseline: 2.1365x; 1.0503x over previous
#include <cuda_runtime.h>
#include <cuda_fp16.h>
#include <cstdint>

#define TOK   32768
#define DIN   1024
#define RDIM  128
#define NSLOT 4096
#define MAXK  32
#define KSEL  48

typedef unsigned long long u64;

// ---------------- scratch ----------------
__device__ float    g_hidden[TOK * RDIM];
__device__ __half2  g_scores_h2[TOK * NSLOT / 2];   // 256 MB approx scores (fp16)
__device__ float    g_wsT[NSLOT * RDIM];            // 2 MB W_s transposed (fp32, refine)
__device__ unsigned g_wsHp[64 * NSLOT];             // 1 MB W_s fp16 k-pair packed
__device__ int      g_budget[TOK];
__device__ float4   g_counts_v[NSLOT / 4];
__device__ float    g_aux;

#define g_scores_h ((__half*)g_scores_h2)
#define g_counts   ((float*)g_counts_v)

// ---------------- fp16 MMA ----------------
#define MMA_F16(c, a, b) \
    asm volatile("mma.sync.aligned.m16n8k16.row.col.f32.f16.f16.f32 " \
        "{%0,%1,%2,%3}, {%4,%5,%6,%7}, {%8,%9}, {%0,%1,%2,%3};" \
        : "+f"((c)[0]), "+f"((c)[1]), "+f"((c)[2]), "+f"((c)[3]) \
        : "r"((a)[0]), "r"((a)[1]), "r"((a)[2]), "r"((a)[3]), \
          "r"((b)[0]), "r"((b)[1]))

// smem: sA frag 32 KB | sB half2[64][72] 18 KB | sC half2[128][36] 18 KB
#define BSTR2     72
#define CSTR      36
#define SM2_A     0
#define SM2_B     32768
#define SM2_C     (32768 + 64 * BSTR2 * 4)
#define SM2_TOTAL (SM2_C + 128 * CSTR * 4)     // 69632

// 16-bit sortable key for fp16 bits
__device__ __forceinline__ unsigned key16(unsigned h) {
    unsigned m = ((h >> 15) & 1u) ? 0xFFFFu : 0x8000u;
    return (h ^ m) & 0xFFFFu;
}

// ---------------- reductions ----------------
__device__ __forceinline__ float warpReduceMaxF(float v) {
#pragma unroll
    for (int o = 16; o > 0; o >>= 1) v = fmaxf(v, __shfl_xor_sync(0xffffffffu, v, o));
    return v;
}
__device__ __forceinline__ float warpReduceSumF(float v) {
#pragma unroll
    for (int o = 16; o > 0; o >>= 1) v += __shfl_xor_sync(0xffffffffu, v, o);
    return v;
}
__device__ __forceinline__ int warpReduceSumI(int v) {
#pragma unroll
    for (int o = 16; o > 0; o >>= 1) v += __shfl_xor_sync(0xffffffffu, v, o);
    return v;
}
__device__ __forceinline__ int warpReduceMinI(int v) {
#pragma unroll
    for (int o = 16; o > 0; o >>= 1) {
        int t = __shfl_xor_sync(0xffffffffu, v, o);
        v = (t < v) ? t : v;
    }
    return v;
}
__device__ __forceinline__ u64 warpReduceMaxU64(u64 v) {
#pragma unroll
    for (int o = 16; o > 0; o >>= 1) {
        u64 t = __shfl_xor_sync(0xffffffffu, v, o);
        v = (t > v) ? t : v;
    }
    return v;
}

// ---------------- K0 ----------------
__global__ void k_init() {
    int i = blockIdx.x * blockDim.x + threadIdx.x;
    if (i < NSLOT) g_counts[i] = 0.f;
    if (i == 0)    g_aux = 0.f;
}

// ---------------- K0b: prep W_s -> g_wsT (fp32 [N][R]) + g_wsHp (fp16 k-pairs) ----------------
__global__ __launch_bounds__(256) void k_prep(const float* __restrict__ Wsg) {
    __shared__ float tile[32][33];
    const int bx = blockIdx.x;          // n tile (32 cols)
    const int by = blockIdx.y;          // r tile (32 rows)
    const int tx = threadIdx.x & 31, ty = threadIdx.x >> 5;
#pragma unroll
    for (int i = 0; i < 4; i++) {
        int r = by * 32 + ty + i * 8;
        tile[ty + i * 8][tx] = Wsg[(size_t)r * NSLOT + bx * 32 + tx];
    }
    __syncthreads();
    // transposed fp32 for exact refine
#pragma unroll
    for (int i = 0; i < 4; i++) {
        int n = bx * 32 + ty + i * 8;
        g_wsT[(size_t)n * RDIM + by * 32 + tx] = tile[tx][ty + i * 8];
    }
    // k-pair packed fp16: g_wsHp[rp][n] = half2(W[2rp][n], W[2rp+1][n])
#pragma unroll
    for (int i = 0; i < 2; i++) {
        int id = threadIdx.x + i * 256;     // 512 = 16 row-pairs x 32 cols
        int rr2 = id >> 5, c = id & 31;
        __half2 p = __halves2half2(__float2half_rn(tile[rr2 * 2][c]),
                                   __float2half_rn(tile[rr2 * 2 + 1][c]));
        g_wsHp[(size_t)(by * 16 + rr2) * NSLOT + bx * 32 + c] = *(unsigned*)&p;
    }
}

// ---------------- K1: hidden GEMM + budget (unchanged) ----------------
__global__ __launch_bounds__(256) void k_hidden(
    const float* __restrict__ x,  const float* __restrict__ Wc, const float* __restrict__ bc,
    const float* __restrict__ Wh, const float* __restrict__ bh, float* __restrict__ out_b)
{
    __shared__ float Xs[32][132];
    __shared__ float Wsm[32][128];
    __shared__ float Wcs[32];

    const int tid = threadIdx.x;
    const int tx = tid & 15, ty = tid >> 4;
    const int t0 = blockIdx.x * 128;

    float acc[8][8];
#pragma unroll
    for (int j = 0; j < 8; j++) {
        int c = (j < 4) ? tx * 4 + j : 64 + tx * 4 + (j - 4);
        float b = bh[c];
#pragma unroll
        for (int i = 0; i < 8; i++) acc[i][j] = b;
    }
    float cacc = 0.f;

    for (int kt = 0; kt < 32; kt++) {
#pragma unroll
        for (int i = 0; i < 4; i++) {
            int id = tid + i * 256;
            int token = id >> 3, kg = id & 7;
            float4 f = *(const float4*)(x + (size_t)(t0 + token) * DIN + kt * 32 + kg * 4);
            Xs[kg * 4 + 0][token] = f.x; Xs[kg * 4 + 1][token] = f.y;
            Xs[kg * 4 + 2][token] = f.z; Xs[kg * 4 + 3][token] = f.w;
        }
#pragma unroll
        for (int i = 0; i < 4; i++) {
            int id = tid + i * 256;
            int rowk = id >> 5, ng = id & 31;
            *(float4*)&Wsm[rowk][ng * 4] =
                *(const float4*)(Wh + (size_t)(kt * 32 + rowk) * RDIM + ng * 4);
        }
        if (tid < 32) Wcs[tid] = Wc[kt * 32 + tid];
        __syncthreads();

#pragma unroll
        for (int k = 0; k < 32; k++) {
            float4 a0 = *(float4*)&Xs[k][ty * 4];
            float4 a1 = *(float4*)&Xs[k][64 + ty * 4];
            float4 b0 = *(float4*)&Wsm[k][tx * 4];
            float4 b1 = *(float4*)&Wsm[k][64 + tx * 4];
            float xf[8] = {a0.x, a0.y, a0.z, a0.w, a1.x, a1.y, a1.z, a1.w};
            float wf[8] = {b0.x, b0.y, b0.z, b0.w, b1.x, b1.y, b1.z, b1.w};
#pragma unroll
            for (int i = 0; i < 8; i++)
#pragma unroll
                for (int j = 0; j < 8; j++)
                    acc[i][j] += xf[i] * wf[j];
        }
        if (tid < 128) {
            float s = 0.f;
#pragma unroll
            for (int k = 0; k < 32; k++) s += Xs[k][tid] * Wcs[k];
            cacc += s;
        }
        __syncthreads();
    }

#pragma unroll
    for (int i = 0; i < 8; i++) {
        int r = (i < 4) ? ty * 4 + i : 64 + ty * 4 + (i - 4);
        float4 o0 = make_float4(fmaxf(acc[i][0], 0.f), fmaxf(acc[i][1], 0.f),
                                fmaxf(acc[i][2], 0.f), fmaxf(acc[i][3], 0.f));
        float4 o1 = make_float4(fmaxf(acc[i][4], 0.f), fmaxf(acc[i][5], 0.f),
                                fmaxf(acc[i][6], 0.f), fmaxf(acc[i][7], 0.f));
        *(float4*)(g_hidden + (size_t)(t0 + r) * RDIM + tx * 4) = o0;
        *(float4*)(g_hidden + (size_t)(t0 + r) * RDIM + 64 + tx * 4) = o1;
    }
    if (tid < 128) {
        float zc = cacc + bc[0];
        float c = 1.f / (1.f + expf(-zc));
        float bf = 4.f + 28.f * c * c;
        int b = (int)floorf(bf);
        g_budget[t0 + tid] = b;
        out_b[t0 + tid] = (float)b;
    }
}

// ---------------- K2: approx scores via fp16 mma.sync m16n8k16 ----------------
__global__ __launch_bounds__(256, 2) void k_scores_mma(const float* __restrict__ bs)
{
    extern __shared__ char smem[];
    unsigned* sA = (unsigned*)(smem + SM2_A);
    unsigned* sB = (unsigned*)(smem + SM2_B);
    unsigned* sC = (unsigned*)(smem + SM2_C);
    const uint4* sA4 = (const uint4*)sA;

    const int tid = threadIdx.x;
    const int lane = tid & 31, wid = tid >> 5;
    const int warpM = wid & 3, warpN = wid >> 2;
    const int gid = lane >> 2, tig = lane & 3;
    const int t0 = blockIdx.x * 128;

    // stage A: hidden[128][128] -> fp16 frag order (one-time)
#pragma unroll
    for (int i = 0; i < 16; i++) {
        int id = tid + i * 256;
        int m = id >> 5, fg = id & 31;
        float4 v = *(const float4*)(g_hidden + (size_t)(t0 + m) * RDIM + fg * 4);
        __half2 h01 = __floats2half2_rn(v.x, v.y);
        __half2 h23 = __floats2half2_rn(v.z, v.w);
        int mt = m >> 4, rr = m & 15;
        int kc = fg >> 2;
        int j0 = (fg & 3) * 2;
        int khi = j0 >> 2;
        int base = ((mt * 8 + kc) * 32 + (rr & 7) * 4);
        int regbase = (rr >> 3) | (khi << 1);
        sA[(base + (j0 & 3)) * 4 + regbase]       = *(unsigned*)&h01;
        sA[(base + ((j0 + 1) & 3)) * 4 + regbase] = *(unsigned*)&h23;
    }

    // prologue: stage B tile 0 (pre-packed fp16)
    {
        uint4 pre[4];
#pragma unroll
        for (int i = 0; i < 4; i++) {
            int id = tid + i * 256;
            int rp = id >> 4, ng = id & 15;
            pre[i] = *(const uint4*)(g_wsHp + (size_t)rp * NSLOT + ng * 4);
        }
#pragma unroll
        for (int i = 0; i < 4; i++) {
            int id = tid + i * 256;
            int rp = id >> 4, ng = id & 15;
            *(uint4*)&sB[rp * BSTR2 + ng * 4] = pre[i];
        }
    }
    __syncthreads();

    for (int nt = 0; nt < 64; nt++) {
        const int nbase = nt * 64;

        uint4 pre[4];
        if (nt < 63) {
#pragma unroll
            for (int i = 0; i < 4; i++) {
                int id = tid + i * 256;
                int rp = id >> 4, ng = id & 15;
                pre[i] = *(const uint4*)(g_wsHp + (size_t)rp * NSLOT + nbase + 64 + ng * 4);
            }
        }

        float c[2][4][4];
#pragma unroll
        for (int mi = 0; mi < 2; mi++)
#pragma unroll
            for (int ni = 0; ni < 4; ni++)
#pragma unroll
                for (int q = 0; q < 4; q++) c[mi][ni][q] = 0.f;

        const int colB = warpN * 32 + gid;

#pragma unroll
        for (int kc = 0; kc < 8; kc++) {
            uint4 af[2];
#pragma unroll
            for (int mi = 0; mi < 2; mi++)
                af[mi] = sA4[((warpM * 2 + mi) * 8 + kc) * 32 + lane];

            unsigned bf[4][2];
            const unsigned* bR0 = sB + (kc * 8 + tig) * BSTR2 + colB;
            const unsigned* bR1 = bR0 + 4 * BSTR2;
#pragma unroll
            for (int ni = 0; ni < 4; ni++) {
                bf[ni][0] = bR0[ni * 8];
                bf[ni][1] = bR1[ni * 8];
            }
#pragma unroll
            for (int mi = 0; mi < 2; mi++)
#pragma unroll
                for (int ni = 0; ni < 4; ni++)
                    MMA_F16(c[mi][ni], (const unsigned*)&af[mi], bf[ni]);
        }

        // epilogue: bias (fp32) -> half2 -> conflict-free smem stage
#pragma unroll
        for (int mi = 0; mi < 2; mi++) {
            int row = warpM * 32 + mi * 16 + gid;   // local row
#pragma unroll
            for (int ni = 0; ni < 4; ni++) {
                int col = nbase + warpN * 32 + ni * 8 + tig * 2;
                float2 bb = *(const float2*)(bs + col);
                __half2 lo = __floats2half2_rn(c[mi][ni][0] + bb.x, c[mi][ni][1] + bb.y);
                __half2 hi = __floats2half2_rn(c[mi][ni][2] + bb.x, c[mi][ni][3] + bb.y);
                int cw = warpN * 16 + ni * 4 + tig;
                sC[row * CSTR + cw]       = *(unsigned*)&lo;
                sC[(row + 8) * CSTR + cw] = *(unsigned*)&hi;
            }
        }

        __syncthreads();   // C visible; all frag reads of sB(nt) done

        // coalesced readback + store (16B per thread x4)
#pragma unroll
        for (int q = 0; q < 4; q++) {
            int id = tid + q * 256;
            int row = id >> 3, c16 = id & 7;
            uint4 v = *(const uint4*)&sC[row * CSTR + c16 * 4];
            *(uint4*)(g_scores_h + (size_t)(t0 + row) * NSLOT + nbase + c16 * 8) = v;
        }
        if (nt < 63) {
#pragma unroll
            for (int i = 0; i < 4; i++) {
                int id = tid + i * 256;
                int rp = id >> 4, ng = id & 15;
                *(uint4*)&sB[rp * BSTR2 + ng * 4] = pre[i];
            }
        }
        __syncthreads();   // sB(nt+1) visible
    }
}

// ---------------- K3: fp16 candidates + exact refine (unchanged from R15) ----------------
__global__ __launch_bounds__(128) void k_topk(float* __restrict__ out_idx,
                                              float* __restrict__ out_w,
                                              const float* __restrict__ bsg)
{
    __shared__ unsigned skey[2048];
    __shared__ u64      cand[256];
    __shared__ float    hrow[128];
    __shared__ float    fred[4], f2red[4];
    __shared__ int      ired[4];
    __shared__ unsigned s_cnt;
    __shared__ int      s_best;

    const int t = blockIdx.x;
    const int tid = threadIdx.x, lane = tid & 31, wid = tid >> 5;
    const uint4* rowv = (const uint4*)(g_scores_h + (size_t)t * NSLOT);

    if (tid < 32)
        *(float4*)&hrow[tid * 4] = *(const float4*)(g_hidden + (size_t)t * RDIM + tid * 4);

    float s = 0.f, s2 = 0.f;
#pragma unroll
    for (int i = 0; i < 4; i++) {
        uint4 v = rowv[tid + i * 128];
        unsigned w[4] = {v.x, v.y, v.z, v.w};
        unsigned pk[4];
#pragma unroll
        for (int j = 0; j < 4; j++) {
            float2 f2 = __half22float2(*(__half2*)&w[j]);
            s += f2.x + f2.y;
            s2 += f2.x * f2.x + f2.y * f2.y;
            pk[j] = key16(w[j] & 0xFFFFu) | (key16(w[j] >> 16) << 16);
        }
        *(uint4*)&skey[(tid + i * 128) * 4] = make_uint4(pk[0], pk[1], pk[2], pk[3]);
    }
    s = warpReduceSumF(s);
    s2 = warpReduceSumF(s2);
    if (lane == 0) { fred[wid] = s; f2red[wid] = s2; }
    __syncthreads();
    float ss = 0.f, ss2 = 0.f;
#pragma unroll
    for (int i = 0; i < 4; i++) { ss += fred[i]; ss2 += f2red[i]; }
    const float mean = ss * (1.f / NSLOT);
    const float sigma = sqrtf(fmaxf(ss2 * (1.f / NSLOT) - mean * mean, 0.f)) + 1e-20f;

    auto countGreater = [&](unsigned thrKey) -> int {
        int c = 0;
#pragma unroll
        for (int i = 0; i < 4; i++) {
            uint4 k4 = *(uint4*)&skey[(tid + i * 128) * 4];
            unsigned w[4] = {k4.x, k4.y, k4.z, k4.w};
#pragma unroll
            for (int j = 0; j < 4; j++)
                c += ((w[j] & 0xFFFFu) > thrKey) + ((w[j] >> 16) > thrKey);
        }
        c = warpReduceSumI(c);
        __syncthreads();
        if (lane == 0) ired[wid] = c;
        __syncthreads();
        int tot = 0;
#pragma unroll
        for (int i = 0; i < 4; i++) tot += ired[i];
        return tot;
    };

    unsigned thrKey = 0;
    int cnt = 0;
    bool ok = false;
    float zf = 2.2f;
    for (int a = 0; a < 4; a++) {
        __half th = __float2half_rn(mean + zf * sigma);
        unsigned tk = key16((unsigned)__half_as_ushort(th));
        int c = countGreater(tk);
        if (c >= KSEL && c <= 256) { thrKey = tk; cnt = c; ok = true; break; }
        zf += (c < KSEL) ? -0.6f : 0.45f;
    }

    bool tiePath = false;
    unsigned Tkey = 0;
    if (!ok) {
        unsigned K = 0;
        for (int bit = 15; bit >= 0; bit--) {
            unsigned trial = K | (1u << bit);
            if (countGreater(trial) >= KSEL) K = trial;
        }
        int c = countGreater(K);
        if (c <= 256) {
            thrKey = K; cnt = c; ok = true;
        } else {
            tiePath = true;
            Tkey = K + 1u;
            thrKey = Tkey;
            cnt = countGreater(Tkey);
        }
    }

    if (tid == 0) s_cnt = 0;
    __syncthreads();
    {
        unsigned kk[32];
#pragma unroll
        for (int i = 0; i < 4; i++) {
            uint4 k4 = *(uint4*)&skey[(tid + i * 128) * 4];
            unsigned w[4] = {k4.x, k4.y, k4.z, k4.w};
#pragma unroll
            for (int j = 0; j < 4; j++) {
                kk[i * 8 + j * 2 + 0] = w[j] & 0xFFFFu;
                kk[i * 8 + j * 2 + 1] = w[j] >> 16;
            }
        }
        unsigned my = 0;
#pragma unroll
        for (int q = 0; q < 32; q++) my += (kk[q] > thrKey) ? 1u : 0u;
        unsigned pre = my;
#pragma unroll
        for (int o = 1; o < 32; o <<= 1) {
            unsigned tt = __shfl_up_sync(0xffffffffu, pre, o);
            if (lane >= o) pre += tt;
        }
        unsigned wtot = __shfl_sync(0xffffffffu, pre, 31);
        unsigned wbase = 0;
        if (lane == 31 && wtot > 0) wbase = atomicAdd(&s_cnt, wtot);
        wbase = __shfl_sync(0xffffffffu, wbase, 31);
        unsigned pos = wbase + pre - my;
        if (my > 0) {
#pragma unroll
            for (int q = 0; q < 32; q++) {
                if (kk[q] > thrKey) {
                    if (pos < 256) {
                        unsigned idx = (unsigned)((tid + (q >> 3) * 128) * 8 + (q & 7));
                        cand[pos] = ((u64)kk[q] << 12) | (u64)(4095u - idx);
                    }
                    pos++;
                }
            }
        }
    }
    __syncthreads();

    if (tiePath) {
        int lastIdx = -1;
        for (int e = cnt; e < KSEL; e++) {
            int best = 0x7FFFFFFF;
#pragma unroll
            for (int i = 0; i < 4; i++) {
                uint4 k4 = *(uint4*)&skey[(tid + i * 128) * 4];
                unsigned w[4] = {k4.x, k4.y, k4.z, k4.w};
#pragma unroll
                for (int j = 0; j < 4; j++) {
                    int idx0 = (tid + i * 128) * 8 + j * 2;
                    unsigned lo = w[j] & 0xFFFFu, hi = w[j] >> 16;
                    if (lo == Tkey && idx0 > lastIdx && idx0 < best) best = idx0;
                    if (hi == Tkey && idx0 + 1 > lastIdx && idx0 + 1 < best) best = idx0 + 1;
                }
            }
            best = warpReduceMinI(best);
            __syncthreads();
            if (lane == 0) ired[wid] = best;
            __syncthreads();
            if (tid == 0) {
                int bb = ired[0];
#pragma unroll
                for (int i = 1; i < 4; i++) bb = (ired[i] < bb) ? ired[i] : bb;
                s_best = bb;
                cand[e] = ((u64)Tkey << 12) | (u64)(4095u - (unsigned)bb);
            }
            __syncthreads();
            lastIdx = s_best;
        }
        cnt = KSEL;
        __syncthreads();
    }

    const int ncand = (cnt < 256) ? cnt : 256;
    for (int j = tid; j < ncand; j += 128) {
        unsigned idxv = 4095u - (unsigned)(cand[j] & 0xFFFull);
        const float4* wv = (const float4*)(g_wsT + (size_t)idxv * RDIM);
        float acc = __ldg(bsg + idxv);
#pragma unroll
        for (int q = 0; q < 32; q++) {
            float4 w4 = __ldg(wv + q);
            float4 h4 = *(const float4*)&hrow[q * 4];
            acc = fmaf(h4.x, w4.x, acc);
            acc = fmaf(h4.y, w4.y, acc);
            acc = fmaf(h4.z, w4.z, acc);
            acc = fmaf(h4.w, w4.w, acc);
        }
        unsigned b = __float_as_uint(acc);
        unsigned k = b ^ ((unsigned)((int)b >> 31) | 0x80000000u);
        cand[j] = ((u64)k << 12) | (u64)(4095u - idxv);
    }
    __syncthreads();

    if (wid == 0) {
        u64 cl[8];
#pragma unroll
        for (int q = 0; q < 8; q++) {
            int p = lane + 32 * q;
            cl[q] = (p < ncand) ? cand[p] : 0ull;
        }
#pragma unroll
        for (int a = 1; a < 8; a++)
#pragma unroll
            for (int b2 = a; b2 > 0; b2--) {
                u64 lo = cl[b2 - 1] < cl[b2] ? cl[b2 - 1] : cl[b2];
                u64 hi = cl[b2 - 1] < cl[b2] ? cl[b2] : cl[b2 - 1];
                cl[b2 - 1] = hi; cl[b2] = lo;
            }
        u64 mysel = 0;
#pragma unroll
        for (int r2 = 0; r2 < MAXK; r2++) {
            u64 wb = warpReduceMaxU64(cl[0]);
            if (cl[0] == wb) {
#pragma unroll
                for (int q = 0; q < 7; q++) cl[q] = cl[q + 1];
                cl[7] = 0ull;
            }
            if (lane == r2) mysel = wb;
        }

        unsigned keyv = (unsigned)(mysel >> 12);
        unsigned idxv = 4095u - (unsigned)(mysel & 0xFFFull);
        unsigned fb = (keyv & 0x80000000u) ? (keyv ^ 0x80000000u) : ~keyv;
        float val = __uint_as_float(fb);

        int b = g_budget[t];
        float v0 = __shfl_sync(0xffffffffu, val, 0);
        bool msk = lane < b;
        float ev = msk ? __expf(val - v0) : 0.f;
        float zz = warpReduceSumF(ev);
        float w = msk ? ev / zz : 0.f;

        out_idx[(size_t)t * MAXK + lane] = (float)idxv;
        out_w[(size_t)t * MAXK + lane] = w;
        if (msk) atomicAdd(&g_counts[idxv], 1.0f);
    }
}

// ---------------- K4: aux (fp16 approx scores, unchanged) ----------------
__global__ __launch_bounds__(256) void k_aux()
{
    __shared__ float sredZ[8], sredD[8], s_m;
    const int t = blockIdx.x;
    const int tid = threadIdx.x, lane = tid & 31, wid = tid >> 5;
    const uint4* rowv = (const uint4*)(g_scores_h + (size_t)t * NSLOT);

    float fv[16];
    float m = -1e30f;
#pragma unroll
    for (int i = 0; i < 2; i++) {
        uint4 v = rowv[tid + i * 256];
        unsigned w[4] = {v.x, v.y, v.z, v.w};
#pragma unroll
        for (int j = 0; j < 4; j++) {
            float2 f2 = __half22float2(*(__half2*)&w[j]);
            fv[i * 8 + j * 2 + 0] = f2.x;
            fv[i * 8 + j * 2 + 1] = f2.y;
            m = fmaxf(m, fmaxf(f2.x, f2.y));
        }
    }
    m = warpReduceMaxF(m);
    if (lane == 0) sredZ[wid] = m;
    __syncthreads();
    if (tid == 0) {
        float mm = sredZ[0];
#pragma unroll
        for (int i = 1; i < 8; i++) mm = fmaxf(mm, sredZ[i]);
        s_m = mm;
    }
    __syncthreads();
    m = s_m;

    float z = 0.f, d = 0.f;
#pragma unroll
    for (int i = 0; i < 2; i++) {
#pragma unroll
        for (int j = 0; j < 2; j++) {
            float4 c = g_counts_v[(tid + i * 256) * 2 + j];
            float e0 = __expf(fv[i * 8 + j * 4 + 0] - m);
            float e1 = __expf(fv[i * 8 + j * 4 + 1] - m);
            float e2 = __expf(fv[i * 8 + j * 4 + 2] - m);
            float e3 = __expf(fv[i * 8 + j * 4 + 3] - m);
            z += e0 + e1 + e2 + e3;
            d += e0 * c.x + e1 * c.y + e2 * c.z + e3 * c.w;
        }
    }
    z = warpReduceSumF(z);
    d = warpReduceSumF(d);
    if (lane == 0) { sredZ[wid] = z; sredD[wid] = d; }
    __syncthreads();
    if (tid == 0) {
        float zz = 0.f, dd = 0.f;
#pragma unroll
        for (int i = 0; i < 8; i++) { zz += sredZ[i]; dd += sredD[i]; }
        float contrib = (dd / zz) * ((float)NSLOT / ((float)TOK * (float)TOK));
        atomicAdd(&g_aux, contrib);
    }
}

// ---------------- K5 ----------------
__global__ void k_finish(float* __restrict__ out_aux)
{
    if (threadIdx.x == 0) out_aux[0] = g_aux;
}

// ---------------- launch ----------------
extern "C" void kernel_launch(void* const* d_in, const int* in_sizes, int n_in,
                              void* d_out, int out_size)
{
    const float* x  = (const float*)d_in[0];
    const float* Wc = (const float*)d_in[1];
    const float* bc = (const float*)d_in[2];
    const float* Wh = (const float*)d_in[3];
    const float* bh = (const float*)d_in[4];
    const float* Ws = (const float*)d_in[5];
    const float* bs = (const float*)d_in[6];

    float* out     = (float*)d_out;
    float* out_idx = out;
    float* out_w   = out + TOK * MAXK;
    float* out_b   = out + 2 * TOK * MAXK;
    float* out_aux = out + 2 * TOK * MAXK + TOK;

    cudaFuncSetAttribute(k_scores_mma, cudaFuncAttributeMaxDynamicSharedMemorySize, SM2_TOTAL);

    k_init<<<(NSLOT + 255) / 256, 256>>>();
    k_prep<<<dim3(128, 4), 256>>>(Ws);
    k_hidden<<<TOK / 128, 256>>>(x, Wc, bc, Wh, bh, out_b);
    k_scores_mma<<<TOK / 128, 256, SM2_TOTAL>>>(bs);
    k_topk<<<TOK, 128>>>(out_idx, out_w, bs);
    k_aux<<<TOK, 256>>>();
    k_finish<<<1, 32>>>(out_aux);
}